// round 1
// baseline (speedup 1.0000x reference)
#include <cuda_runtime.h>
#include <cuda_bf16.h>
#include <cstdint>
#include <cmath>

// ---------------------------------------------------------------------------
// GroupedQueryAttention: B=2, T=2048, DIM=2048, H=16, KH=4, DK=DV=128
// Outputs (concatenated in d_out): out [2,2048,2048] fp32, attn_weight
// [2,16,2048,2048] fp32.
//
// Strategy: split-bf16 (hi+lo) tensor-core MMA everywhere for ~16-bit mantissa
// accuracy (3 mma terms per k16: hh, hl, lh), fp32 accumulate.
// ---------------------------------------------------------------------------

#define BT 4096              // B*T
#define DIM 2048
#define KVDIM 512
#define T 2048
#define NH 16
#define NKV 4

// scratch (device globals: no allocation allowed)
__device__ float g_Q[BT * DIM];
__device__ float g_K[BT * KVDIM];
__device__ float g_V[BT * KVDIM];
__device__ float g_O[BT * DIM];

// ---------------------------------------------------------------------------
// helpers
// ---------------------------------------------------------------------------
__device__ __forceinline__ uint32_t smem_u32(const void* p) {
    return (uint32_t)__cvta_generic_to_shared(p);
}

__device__ __forceinline__ void ldsm_x4(uint32_t* r, uint32_t addr) {
    asm volatile("ldmatrix.sync.aligned.m8n8.x4.shared.b16 {%0,%1,%2,%3}, [%4];"
                 : "=r"(r[0]), "=r"(r[1]), "=r"(r[2]), "=r"(r[3])
                 : "r"(addr));
}
__device__ __forceinline__ void ldsm_x2(uint32_t* r, uint32_t addr) {
    asm volatile("ldmatrix.sync.aligned.m8n8.x2.shared.b16 {%0,%1}, [%2];"
                 : "=r"(r[0]), "=r"(r[1])
                 : "r"(addr));
}
__device__ __forceinline__ void ldsm_x2t(uint32_t* r, uint32_t addr) {
    asm volatile("ldmatrix.sync.aligned.m8n8.x2.trans.shared.b16 {%0,%1}, [%2];"
                 : "=r"(r[0]), "=r"(r[1])
                 : "r"(addr));
}

__device__ __forceinline__ void mma16816(float* c, const uint32_t* a, const uint32_t* b) {
    asm volatile(
        "mma.sync.aligned.m16n8k16.row.col.f32.bf16.bf16.f32 "
        "{%0,%1,%2,%3}, {%4,%5,%6,%7}, {%8,%9}, {%0,%1,%2,%3};\n"
        : "+f"(c[0]), "+f"(c[1]), "+f"(c[2]), "+f"(c[3])
        : "r"(a[0]), "r"(a[1]), "r"(a[2]), "r"(a[3]), "r"(b[0]), "r"(b[1]));
}

__device__ __forceinline__ void split_store(float x, __nv_bfloat16* ph, __nv_bfloat16* pl) {
    __nv_bfloat16 h = __float2bfloat16(x);
    *ph = h;
    *pl = __float2bfloat16(x - __bfloat162float(h));
}

// ---------------------------------------------------------------------------
// Generic GEMM: C[M,N] = A[M,K] @ W[K,N] + bias
// BM=128, BN=128, BK=32, 256 threads (8 warps, 2x4), warp tile 64x32.
// split-bf16: 3 mma terms per k16.
// M % 128 == 0, N % 128 == 0, K % 32 == 0 (all shapes here satisfy this)
// ---------------------------------------------------------------------------
#define GA_STRIDE 40    // halves per A smem row (32 + 8 pad), 80B = 16B aligned
#define GB_STRIDE 136   // halves per B smem row (128 + 8 pad), 272B

__global__ __launch_bounds__(256) void gemm_bias_kernel(
    const float* __restrict__ A, const float* __restrict__ W,
    const float* __restrict__ bias, float* __restrict__ C,
    int M, int N, int K)
{
    __shared__ __nv_bfloat16 Ah[128 * GA_STRIDE];
    __shared__ __nv_bfloat16 Al[128 * GA_STRIDE];
    __shared__ __nv_bfloat16 Bh[32 * GB_STRIDE];
    __shared__ __nv_bfloat16 Bl[32 * GB_STRIDE];

    const int tid = threadIdx.x;
    const int lane = tid & 31;
    const int wid = tid >> 5;
    const int wm = wid >> 2;   // 0..1
    const int wn = wid & 3;    // 0..3
    const int bm0 = blockIdx.y * 128;
    const int bn0 = blockIdx.x * 128;

    float acc[4][4][4] = {};

    for (int kt = 0; kt < K; kt += 32) {
        // load A tile 128x32
        #pragma unroll
        for (int i = 0; i < 4; i++) {
            int row = (tid >> 3) + i * 32;
            int col = (tid & 7) * 4;
            const float4 v = *reinterpret_cast<const float4*>(
                &A[(size_t)(bm0 + row) * K + kt + col]);
            float xs[4] = {v.x, v.y, v.z, v.w};
            #pragma unroll
            for (int j = 0; j < 4; j++)
                split_store(xs[j], &Ah[row * GA_STRIDE + col + j], &Al[row * GA_STRIDE + col + j]);
        }
        // load W tile 32x128
        #pragma unroll
        for (int i = 0; i < 4; i++) {
            int row = (tid >> 5) + i * 8;
            int col = (tid & 31) * 4;
            const float4 v = *reinterpret_cast<const float4*>(
                &W[(size_t)(kt + row) * N + bn0 + col]);
            float xs[4] = {v.x, v.y, v.z, v.w};
            #pragma unroll
            for (int j = 0; j < 4; j++)
                split_store(xs[j], &Bh[row * GB_STRIDE + col + j], &Bl[row * GB_STRIDE + col + j]);
        }
        __syncthreads();

        #pragma unroll
        for (int ks = 0; ks < 2; ks++) {
            uint32_t ah[4][4], al[4][4];
            #pragma unroll
            for (int mt = 0; mt < 4; mt++) {
                int r = wm * 64 + mt * 16 + (lane & 15);
                int c = ks * 16 + (lane >> 4) * 8;
                ldsm_x4(ah[mt], smem_u32(&Ah[r * GA_STRIDE + c]));
                ldsm_x4(al[mt], smem_u32(&Al[r * GA_STRIDE + c]));
            }
            uint32_t bh[4][2], bl[4][2];
            #pragma unroll
            for (int nt = 0; nt < 4; nt++) {
                int r = ks * 16 + (lane & 15);
                int c = wn * 32 + nt * 8;
                ldsm_x2t(bh[nt], smem_u32(&Bh[r * GB_STRIDE + c]));
                ldsm_x2t(bl[nt], smem_u32(&Bl[r * GB_STRIDE + c]));
            }
            #pragma unroll
            for (int mt = 0; mt < 4; mt++)
                #pragma unroll
                for (int nt = 0; nt < 4; nt++) {
                    mma16816(acc[mt][nt], ah[mt], bh[nt]);
                    mma16816(acc[mt][nt], ah[mt], bl[nt]);
                    mma16816(acc[mt][nt], al[mt], bh[nt]);
                }
        }
        __syncthreads();
    }

    // epilogue: + bias, write fp32
    #pragma unroll
    for (int mt = 0; mt < 4; mt++)
        #pragma unroll
        for (int nt = 0; nt < 4; nt++) {
            int row = bm0 + wm * 64 + mt * 16 + (lane >> 2);
            int col = bn0 + wn * 32 + nt * 8 + (lane & 3) * 2;
            float b0 = bias[col], b1 = bias[col + 1];
            *reinterpret_cast<float2*>(&C[(size_t)row * N + col]) =
                make_float2(acc[mt][nt][0] + b0, acc[mt][nt][1] + b1);
            *reinterpret_cast<float2*>(&C[(size_t)(row + 8) * N + col]) =
                make_float2(acc[mt][nt][2] + b0, acc[mt][nt][3] + b1);
        }
}

// ---------------------------------------------------------------------------
// Attention kernel: per block = one (b,h) x 64 query rows.
// Two passes over 32 key tiles of 64:
//   pass1: S = Q K^T * scale (split-bf16 mma), online row max/sum
//   pass2: recompute S, w = exp(s-m)/l, write w to global, P->smem(split),
//          O += P V (split-bf16 mma)
// 128 threads = 4 warps; each warp owns 16 query rows.
// ---------------------------------------------------------------------------
#define AS 136   // smem stride (halves) for 128-wide tiles
#define PS 72    // smem stride (halves) for 64-wide P tile

#define ATTN_SMEM_BYTES ((64 * AS * 6 + 64 * PS * 2) * 2)

__device__ __forceinline__ void load_tile64x128(
    const float* __restrict__ src, size_t row0, int col0, int ld,
    __nv_bfloat16* dh, __nv_bfloat16* dl, int tid, float mul)
{
    #pragma unroll
    for (int i = 0; i < 16; i++) {
        int r = i * 4 + (tid >> 5);
        int c = (tid & 31) * 4;
        const float4 v = *reinterpret_cast<const float4*>(&src[(row0 + r) * ld + col0 + c]);
        float xs[4] = {v.x * mul, v.y * mul, v.z * mul, v.w * mul};
        #pragma unroll
        for (int j = 0; j < 4; j++)
            split_store(xs[j], &dh[r * AS + c + j], &dl[r * AS + c + j]);
    }
}

// compute 16x64 S tile for this warp (accumulated fp32)
__device__ __forceinline__ void compute_S(
    const __nv_bfloat16* Qh, const __nv_bfloat16* Ql,
    const __nv_bfloat16* Kh, const __nv_bfloat16* Kl,
    int w, int lane, float s[8][4])
{
    #pragma unroll
    for (int nt = 0; nt < 8; nt++)
        #pragma unroll
        for (int j = 0; j < 4; j++) s[nt][j] = 0.f;

    #pragma unroll
    for (int kk = 0; kk < 8; kk++) {
        uint32_t ah[4], al[4];
        {
            int r = w * 16 + (lane & 15);
            int c = kk * 16 + (lane >> 4) * 8;
            ldsm_x4(ah, smem_u32(&Qh[r * AS + c]));
            ldsm_x4(al, smem_u32(&Ql[r * AS + c]));
        }
        #pragma unroll
        for (int nt = 0; nt < 8; nt++) {
            // B operand from K stored [key][d] (col-major B => non-trans ldmatrix)
            int n = nt * 8 + (lane & 7);
            int c = kk * 16 + ((lane >> 3) & 1) * 8;
            uint32_t bh[2], bl[2];
            ldsm_x2(bh, smem_u32(&Kh[n * AS + c]));
            ldsm_x2(bl, smem_u32(&Kl[n * AS + c]));
            mma16816(s[nt], ah, bh);
            mma16816(s[nt], ah, bl);
            mma16816(s[nt], al, bh);
        }
    }
}

__global__ __launch_bounds__(128) void attn_kernel(
    const float* __restrict__ Qp, const float* __restrict__ Kp,
    const float* __restrict__ Vp, float* __restrict__ AW,
    float* __restrict__ Op)
{
    extern __shared__ __nv_bfloat16 smem[];
    __nv_bfloat16* Qh = smem;
    __nv_bfloat16* Ql = Qh + 64 * AS;
    __nv_bfloat16* Kh = Ql + 64 * AS;
    __nv_bfloat16* Kl = Kh + 64 * AS;
    __nv_bfloat16* Vh = Kl + 64 * AS;
    __nv_bfloat16* Vl = Vh + 64 * AS;
    __nv_bfloat16* Ph = Vl + 64 * AS;
    __nv_bfloat16* Pl = Ph + 64 * PS;

    const int tid = threadIdx.x;
    const int lane = tid & 31;
    const int w = tid >> 5;
    const int qt = blockIdx.x;          // 0..31
    const int bh = blockIdx.y;          // 0..31
    const int b = bh >> 4;
    const int h = bh & 15;
    const int kv = h >> 2;
    const float scale = 0.08838834764831845f;  // 1/sqrt(128)

    // load Q (scaled) once
    load_tile64x128(Qp, (size_t)b * T + qt * 64, h * 128, DIM, Qh, Ql, tid, scale);
    __syncthreads();

    float m[2] = {-INFINITY, -INFINITY};
    float l[2] = {0.f, 0.f};

    // ------------------ pass 1: row max / sum ------------------
    for (int kt = 0; kt < 32; kt++) {
        load_tile64x128(Kp, (size_t)b * T + kt * 64, kv * 128, KVDIM, Kh, Kl, tid, 1.f);
        __syncthreads();

        float s[8][4];
        compute_S(Qh, Ql, Kh, Kl, w, lane, s);

        #pragma unroll
        for (int r = 0; r < 2; r++) {
            float vmax = -INFINITY;
            #pragma unroll
            for (int nt = 0; nt < 8; nt++)
                vmax = fmaxf(vmax, fmaxf(s[nt][2 * r], s[nt][2 * r + 1]));
            vmax = fmaxf(vmax, __shfl_xor_sync(0xffffffffu, vmax, 1));
            vmax = fmaxf(vmax, __shfl_xor_sync(0xffffffffu, vmax, 2));
            float mnew = fmaxf(m[r], vmax);
            float ps = 0.f;
            #pragma unroll
            for (int nt = 0; nt < 8; nt++)
                ps += __expf(s[nt][2 * r] - mnew) + __expf(s[nt][2 * r + 1] - mnew);
            ps += __shfl_xor_sync(0xffffffffu, ps, 1);
            ps += __shfl_xor_sync(0xffffffffu, ps, 2);
            l[r] = l[r] * __expf(m[r] - mnew) + ps;
            m[r] = mnew;
        }
        __syncthreads();
    }

    const float inv_l[2] = {1.f / l[0], 1.f / l[1]};
    float o[16][4] = {};

    // ------------------ pass 2: weights + O = P V ------------------
    for (int kt = 0; kt < 32; kt++) {
        load_tile64x128(Kp, (size_t)b * T + kt * 64, kv * 128, KVDIM, Kh, Kl, tid, 1.f);
        load_tile64x128(Vp, (size_t)b * T + kt * 64, kv * 128, KVDIM, Vh, Vl, tid, 1.f);
        __syncthreads();

        float s[8][4];
        compute_S(Qh, Ql, Kh, Kl, w, lane, s);

        // normalized weights -> global + P smem (split)
        const size_t gbase = (((size_t)bh * T) + (size_t)qt * 64) * T;
        const int r0 = w * 16 + (lane >> 2);
        const int c0 = (lane & 3) * 2;
        #pragma unroll
        for (int nt = 0; nt < 8; nt++) {
            float w00 = __expf(s[nt][0] - m[0]) * inv_l[0];
            float w01 = __expf(s[nt][1] - m[0]) * inv_l[0];
            float w10 = __expf(s[nt][2] - m[1]) * inv_l[1];
            float w11 = __expf(s[nt][3] - m[1]) * inv_l[1];
            int scol = kt * 64 + nt * 8 + c0;
            *reinterpret_cast<float2*>(&AW[gbase + (size_t)r0 * T + scol]) = make_float2(w00, w01);
            *reinterpret_cast<float2*>(&AW[gbase + (size_t)(r0 + 8) * T + scol]) = make_float2(w10, w11);
            int p0 = r0 * PS + nt * 8 + c0;
            int p1 = (r0 + 8) * PS + nt * 8 + c0;
            split_store(w00, &Ph[p0], &Pl[p0]);
            split_store(w01, &Ph[p0 + 1], &Pl[p0 + 1]);
            split_store(w10, &Ph[p1], &Pl[p1]);
            split_store(w11, &Ph[p1 + 1], &Pl[p1 + 1]);
        }
        __syncthreads();

        // O += P(64x64) @ V(64x128)
        #pragma unroll
        for (int kc = 0; kc < 4; kc++) {
            uint32_t ph[4], pl[4];
            {
                int r = w * 16 + (lane & 15);
                int c = kc * 16 + (lane >> 4) * 8;
                ldsm_x4(ph, smem_u32(&Ph[r * PS + c]));
                ldsm_x4(pl, smem_u32(&Pl[r * PS + c]));
            }
            #pragma unroll
            for (int nt = 0; nt < 16; nt++) {
                int r = kc * 16 + (lane & 15);
                int c = nt * 8;
                uint32_t vh[2], vl[2];
                ldsm_x2t(vh, smem_u32(&Vh[r * AS + c]));
                ldsm_x2t(vl, smem_u32(&Vl[r * AS + c]));
                mma16816(o[nt], ph, vh);
                mma16816(o[nt], ph, vl);
                mma16816(o[nt], pl, vh);
            }
        }
        __syncthreads();
    }

    // write O tile to g_O laid out [b, t, h, dv] = [BT, DIM]
    #pragma unroll
    for (int nt = 0; nt < 16; nt++) {
        int r = qt * 64 + w * 16 + (lane >> 2);
        int c = nt * 8 + (lane & 3) * 2;
        *reinterpret_cast<float2*>(&Op[(size_t)(b * T + r) * DIM + h * 128 + c]) =
            make_float2(o[nt][0], o[nt][1]);
        *reinterpret_cast<float2*>(&Op[(size_t)(b * T + r + 8) * DIM + h * 128 + c]) =
            make_float2(o[nt][2], o[nt][3]);
    }
}

// ---------------------------------------------------------------------------
// launch
// ---------------------------------------------------------------------------
extern "C" void kernel_launch(void* const* d_in, const int* in_sizes, int n_in,
                              void* d_out, int out_size)
{
    const float* q  = (const float*)d_in[0];
    const float* k  = (const float*)d_in[1];
    const float* v  = (const float*)d_in[2];
    const float* Wq = (const float*)d_in[3];
    const float* bq = (const float*)d_in[4];
    const float* Wk = (const float*)d_in[5];
    const float* bk = (const float*)d_in[6];
    const float* Wv = (const float*)d_in[7];
    const float* bv = (const float*)d_in[8];
    const float* Wo = (const float*)d_in[9];
    const float* bo = (const float*)d_in[10];

    float* out   = (float*)d_out;
    float* attnW = out + (size_t)BT * DIM;   // out is [2,2048,2048], then attn [2,16,2048,2048]

    float *gQ, *gK, *gV, *gO;
    cudaGetSymbolAddress((void**)&gQ, g_Q);
    cudaGetSymbolAddress((void**)&gK, g_K);
    cudaGetSymbolAddress((void**)&gV, g_V);
    cudaGetSymbolAddress((void**)&gO, g_O);

    cudaFuncSetAttribute(attn_kernel, cudaFuncAttributeMaxDynamicSharedMemorySize,
                         ATTN_SMEM_BYTES);

    // projections
    gemm_bias_kernel<<<dim3(DIM / 128, BT / 128), 256>>>(q, Wq, bq, gQ, BT, DIM, DIM);
    gemm_bias_kernel<<<dim3(KVDIM / 128, BT / 128), 256>>>(k, Wk, bk, gK, BT, KVDIM, DIM);
    gemm_bias_kernel<<<dim3(KVDIM / 128, BT / 128), 256>>>(v, Wv, bv, gV, BT, KVDIM, DIM);

    // attention (writes normalized weights + O)
    attn_kernel<<<dim3(T / 64, 2 * NH), 128, ATTN_SMEM_BYTES>>>(gQ, gK, gV, attnW, gO);

    // output projection
    gemm_bias_kernel<<<dim3(DIM / 128, BT / 128), 256>>>(gO, Wo, bo, out, BT, DIM, DIM);
}

// round 2
// speedup vs baseline: 1.1603x; 1.1603x over previous
#include <cuda_runtime.h>
#include <cuda_bf16.h>
#include <cstdint>
#include <cmath>

// ---------------------------------------------------------------------------
// GroupedQueryAttention: B=2, T=2048, DIM=2048, H=16, KH=4, DK=DV=128
// d_out = [ out (2,2048,2048) fp32 | attn_weight (2,16,2048,2048) fp32 ]
//
// Round 2: pre-split bf16 hi/lo Q/K/V, S staged in the AW output buffer
// (no recompute), 256-thread attention CTAs, cp.async double buffering,
// ldmatrix.x4 everywhere. Split-bf16 3-term MMA for precision.
// ---------------------------------------------------------------------------

#define BT 4096
#define DIM 2048
#define KVDIM 512
#define T 2048

__device__ __nv_bfloat16 g_Qh[BT * DIM];
__device__ __nv_bfloat16 g_Ql[BT * DIM];
__device__ __nv_bfloat16 g_Kh[BT * KVDIM];
__device__ __nv_bfloat16 g_Kl[BT * KVDIM];
__device__ __nv_bfloat16 g_Vh[BT * KVDIM];
__device__ __nv_bfloat16 g_Vl[BT * KVDIM];
__device__ float g_O[BT * DIM];

// ---------------------------------------------------------------------------
// helpers
// ---------------------------------------------------------------------------
__device__ __forceinline__ uint32_t smem_u32(const void* p) {
    return (uint32_t)__cvta_generic_to_shared(p);
}
__device__ __forceinline__ void ldsm_x4(uint32_t* r, uint32_t addr) {
    asm volatile("ldmatrix.sync.aligned.m8n8.x4.shared.b16 {%0,%1,%2,%3}, [%4];"
                 : "=r"(r[0]), "=r"(r[1]), "=r"(r[2]), "=r"(r[3]) : "r"(addr));
}
__device__ __forceinline__ void ldsm_x4t(uint32_t* r, uint32_t addr) {
    asm volatile("ldmatrix.sync.aligned.m8n8.x4.trans.shared.b16 {%0,%1,%2,%3}, [%4];"
                 : "=r"(r[0]), "=r"(r[1]), "=r"(r[2]), "=r"(r[3]) : "r"(addr));
}
__device__ __forceinline__ void mma16816(float* c, const uint32_t* a, const uint32_t* b) {
    asm volatile(
        "mma.sync.aligned.m16n8k16.row.col.f32.bf16.bf16.f32 "
        "{%0,%1,%2,%3}, {%4,%5,%6,%7}, {%8,%9}, {%0,%1,%2,%3};\n"
        : "+f"(c[0]), "+f"(c[1]), "+f"(c[2]), "+f"(c[3])
        : "r"(a[0]), "r"(a[1]), "r"(a[2]), "r"(a[3]), "r"(b[0]), "r"(b[1]));
}
__device__ __forceinline__ void cp16(uint32_t saddr, const void* g) {
    asm volatile("cp.async.cg.shared.global [%0], [%1], 16;" :: "r"(saddr), "l"(g));
}
#define CP_COMMIT() asm volatile("cp.async.commit_group;")
#define CP_WAIT1()  asm volatile("cp.async.wait_group 1;")

__device__ __forceinline__ void split_store(float x, __nv_bfloat16* ph, __nv_bfloat16* pl) {
    __nv_bfloat16 h = __float2bfloat16(x);
    *ph = h;
    *pl = __float2bfloat16(x - __bfloat162float(h));
}

// ---------------------------------------------------------------------------
// GEMM: C[M,N] = (A[M,K] @ W[K,N] + bias) * scale
// epilogue: fp32 (Cf) or split-bf16 (Ch/Cl). 256 threads, BM=128 BN=128 BK=32.
// ---------------------------------------------------------------------------
#define GA_STRIDE 40
#define GB_STRIDE 136

__global__ __launch_bounds__(256) void gemm_bias_kernel(
    const float* __restrict__ A, const float* __restrict__ W,
    const float* __restrict__ bias,
    float* __restrict__ Cf, __nv_bfloat16* __restrict__ Ch, __nv_bfloat16* __restrict__ Cl,
    float scale, int M, int N, int K)
{
    __shared__ __nv_bfloat16 Ah[128 * GA_STRIDE];
    __shared__ __nv_bfloat16 Al[128 * GA_STRIDE];
    __shared__ __nv_bfloat16 Bh[32 * GB_STRIDE];
    __shared__ __nv_bfloat16 Bl[32 * GB_STRIDE];

    const int tid = threadIdx.x;
    const int lane = tid & 31;
    const int wid = tid >> 5;
    const int wm = wid >> 2;
    const int wn = wid & 3;
    const int bm0 = blockIdx.y * 128;
    const int bn0 = blockIdx.x * 128;

    float acc[4][4][4] = {};

    for (int kt = 0; kt < K; kt += 32) {
        #pragma unroll
        for (int i = 0; i < 4; i++) {
            int row = (tid >> 3) + i * 32;
            int col = (tid & 7) * 4;
            const float4 v = *reinterpret_cast<const float4*>(
                &A[(size_t)(bm0 + row) * K + kt + col]);
            float xs[4] = {v.x, v.y, v.z, v.w};
            #pragma unroll
            for (int j = 0; j < 4; j++)
                split_store(xs[j], &Ah[row * GA_STRIDE + col + j], &Al[row * GA_STRIDE + col + j]);
        }
        #pragma unroll
        for (int i = 0; i < 4; i++) {
            int row = (tid >> 5) + i * 8;
            int col = (tid & 31) * 4;
            const float4 v = *reinterpret_cast<const float4*>(
                &W[(size_t)(kt + row) * N + bn0 + col]);
            float xs[4] = {v.x, v.y, v.z, v.w};
            #pragma unroll
            for (int j = 0; j < 4; j++)
                split_store(xs[j], &Bh[row * GB_STRIDE + col + j], &Bl[row * GB_STRIDE + col + j]);
        }
        __syncthreads();

        #pragma unroll
        for (int ks = 0; ks < 2; ks++) {
            uint32_t ah[4][4], al[4][4];
            #pragma unroll
            for (int mt = 0; mt < 4; mt++) {
                int r = wm * 64 + mt * 16 + (lane & 15);
                int c = ks * 16 + (lane >> 4) * 8;
                ldsm_x4(ah[mt], smem_u32(&Ah[r * GA_STRIDE + c]));
                ldsm_x4(al[mt], smem_u32(&Al[r * GA_STRIDE + c]));
            }
            uint32_t bh[4][2], bl[4][2];
            #pragma unroll
            for (int p = 0; p < 2; p++) {
                int r = ks * 16 + (lane & 15);
                int c = wn * 32 + p * 16 + (lane >> 4) * 8;
                uint32_t t4[4];
                ldsm_x4t(t4, smem_u32(&Bh[r * GB_STRIDE + c]));
                bh[2*p][0] = t4[0]; bh[2*p][1] = t4[1];
                bh[2*p+1][0] = t4[2]; bh[2*p+1][1] = t4[3];
                ldsm_x4t(t4, smem_u32(&Bl[r * GB_STRIDE + c]));
                bl[2*p][0] = t4[0]; bl[2*p][1] = t4[1];
                bl[2*p+1][0] = t4[2]; bl[2*p+1][1] = t4[3];
            }
            #pragma unroll
            for (int mt = 0; mt < 4; mt++)
                #pragma unroll
                for (int nt = 0; nt < 4; nt++) {
                    mma16816(acc[mt][nt], ah[mt], bh[nt]);
                    mma16816(acc[mt][nt], ah[mt], bl[nt]);
                    mma16816(acc[mt][nt], al[mt], bh[nt]);
                }
        }
        __syncthreads();
    }

    #pragma unroll
    for (int mt = 0; mt < 4; mt++)
        #pragma unroll
        for (int nt = 0; nt < 4; nt++) {
            int row = bm0 + wm * 64 + mt * 16 + (lane >> 2);
            int col = bn0 + wn * 32 + nt * 8 + (lane & 3) * 2;
            float b0 = bias[col], b1 = bias[col + 1];
            float v00 = (acc[mt][nt][0] + b0) * scale;
            float v01 = (acc[mt][nt][1] + b1) * scale;
            float v10 = (acc[mt][nt][2] + b0) * scale;
            float v11 = (acc[mt][nt][3] + b1) * scale;
            if (Cf) {
                *reinterpret_cast<float2*>(&Cf[(size_t)row * N + col]) = make_float2(v00, v01);
                *reinterpret_cast<float2*>(&Cf[(size_t)(row + 8) * N + col]) = make_float2(v10, v11);
            } else {
                __nv_bfloat162 hh, ll;
                hh.x = __float2bfloat16(v00); hh.y = __float2bfloat16(v01);
                ll.x = __float2bfloat16(v00 - __bfloat162float(hh.x));
                ll.y = __float2bfloat16(v01 - __bfloat162float(hh.y));
                *reinterpret_cast<__nv_bfloat162*>(&Ch[(size_t)row * N + col]) = hh;
                *reinterpret_cast<__nv_bfloat162*>(&Cl[(size_t)row * N + col]) = ll;
                hh.x = __float2bfloat16(v10); hh.y = __float2bfloat16(v11);
                ll.x = __float2bfloat16(v10 - __bfloat162float(hh.x));
                ll.y = __float2bfloat16(v11 - __bfloat162float(hh.y));
                *reinterpret_cast<__nv_bfloat162*>(&Ch[(size_t)(row + 8) * N + col]) = hh;
                *reinterpret_cast<__nv_bfloat162*>(&Cl[(size_t)(row + 8) * N + col]) = ll;
            }
        }
}

// ---------------------------------------------------------------------------
// Attention: grid (16 qtiles x 32 bh), 256 threads (8 warps x 16 q rows).
// pass1: S = Q K^T  -> staged raw into AW buffer; l = sum exp(S) per row.
// pass2: w = exp(S)/l -> AW (overwrite) + split to smem; O += P V.
// Double-buffered cp.async K/V tiles (64 keys).
// ---------------------------------------------------------------------------
#define AS 136
#define PS 72
#define ATTN_SMEM_BYTES ((2 * 128 * AS + 4 * 64 * AS + 2 * 128 * PS) * 2 + 128 * 4)

__device__ __forceinline__ void load_kv_async(
    const __nv_bfloat16* __restrict__ gh, const __nv_bfloat16* __restrict__ gl,
    __nv_bfloat16* sh, __nv_bfloat16* sl, size_t row0, int col0, int tid)
{
    #pragma unroll
    for (int i = 0; i < 4; i++) {
        int idx = i * 256 + tid;
        int r = idx >> 4, c = (idx & 15) * 8;
        cp16(smem_u32(&sh[r * AS + c]), &gh[(row0 + r) * KVDIM + col0 + c]);
        cp16(smem_u32(&sl[r * AS + c]), &gl[(row0 + r) * KVDIM + col0 + c]);
    }
}

__global__ __launch_bounds__(256) void attn_kernel(
    const __nv_bfloat16* __restrict__ Qhg, const __nv_bfloat16* __restrict__ Qlg,
    const __nv_bfloat16* __restrict__ Khg, const __nv_bfloat16* __restrict__ Klg,
    const __nv_bfloat16* __restrict__ Vhg, const __nv_bfloat16* __restrict__ Vlg,
    float* __restrict__ AW, float* __restrict__ Op)
{
    extern __shared__ __nv_bfloat16 smem[];
    __nv_bfloat16* Qh = smem;
    __nv_bfloat16* Ql = Qh + 128 * AS;
    __nv_bfloat16* KV = Ql + 128 * AS;        // 4 x (64*AS): buf0h, buf0l, buf1h, buf1l
    __nv_bfloat16* Ph = KV + 4 * 64 * AS;
    __nv_bfloat16* Pl = Ph + 128 * PS;
    float* invL = reinterpret_cast<float*>(Pl + 128 * PS);

    const int tid = threadIdx.x;
    const int lane = tid & 31;
    const int w = tid >> 5;
    const int qt = blockIdx.x;
    const int bh = blockIdx.y;
    const int b = bh >> 4, h = bh & 15, kv = h >> 2;

    const size_t qrow0 = (size_t)b * T + qt * 128;
    const size_t krow0 = (size_t)b * T;
    const int kcol = kv * 128;

    // prologue: K tile 0 async, Q plain
    load_kv_async(Khg, Klg, KV, KV + 64 * AS, krow0, kcol, tid);
    CP_COMMIT();
    #pragma unroll
    for (int i = 0; i < 8; i++) {
        int idx = i * 256 + tid;
        int r = idx >> 4, c = (idx & 15) * 8;
        *reinterpret_cast<uint4*>(&Qh[r * AS + c]) =
            *reinterpret_cast<const uint4*>(&Qhg[(qrow0 + r) * DIM + h * 128 + c]);
        *reinterpret_cast<uint4*>(&Ql[r * AS + c]) =
            *reinterpret_cast<const uint4*>(&Qlg[(qrow0 + r) * DIM + h * 128 + c]);
    }

    float l0 = 0.f, l1 = 0.f;

    // ------------------ pass 1 ------------------
    #pragma unroll 1
    for (int kt = 0; kt < 32; kt++) {
        if (kt < 31) {
            __nv_bfloat16* nb = KV + ((kt + 1) & 1) * 2 * 64 * AS;
            load_kv_async(Khg, Klg, nb, nb + 64 * AS, krow0 + (kt + 1) * 64, kcol, tid);
        }
        CP_COMMIT();
        CP_WAIT1();
        __syncthreads();

        const __nv_bfloat16* Kbh = KV + (kt & 1) * 2 * 64 * AS;
        const __nv_bfloat16* Kbl = Kbh + 64 * AS;

        float s[8][4];
        #pragma unroll
        for (int nt = 0; nt < 8; nt++)
            #pragma unroll
            for (int j = 0; j < 4; j++) s[nt][j] = 0.f;

        #pragma unroll
        for (int kk = 0; kk < 8; kk++) {
            uint32_t ah[4], al[4];
            int ar = w * 16 + (lane & 15), ac = kk * 16 + (lane >> 4) * 8;
            ldsm_x4(ah, smem_u32(&Qh[ar * AS + ac]));
            ldsm_x4(al, smem_u32(&Ql[ar * AS + ac]));
            #pragma unroll
            for (int p = 0; p < 4; p++) {
                int br = p * 16 + (lane & 15), bc = kk * 16 + (lane >> 4) * 8;
                uint32_t b4h[4], b4l[4];
                ldsm_x4(b4h, smem_u32(&Kbh[br * AS + bc]));
                ldsm_x4(b4l, smem_u32(&Kbl[br * AS + bc]));
                uint32_t be_h[2] = {b4h[0], b4h[2]}, bo_h[2] = {b4h[1], b4h[3]};
                uint32_t be_l[2] = {b4l[0], b4l[2]}, bo_l[2] = {b4l[1], b4l[3]};
                mma16816(s[2*p],   ah, be_h); mma16816(s[2*p],   ah, be_l); mma16816(s[2*p],   al, be_h);
                mma16816(s[2*p+1], ah, bo_h); mma16816(s[2*p+1], ah, bo_l); mma16816(s[2*p+1], al, bo_h);
            }
        }

        // stage raw S into AW; accumulate per-thread partial exp-sums
        const size_t gb = ((size_t)bh * T + (size_t)qt * 128) * T;
        const int r0 = w * 16 + (lane >> 2), c0 = (lane & 3) * 2;
        #pragma unroll
        for (int nt = 0; nt < 8; nt++) {
            const int col = kt * 64 + nt * 8 + c0;
            *reinterpret_cast<float2*>(&AW[gb + (size_t)r0 * T + col]) = make_float2(s[nt][0], s[nt][1]);
            *reinterpret_cast<float2*>(&AW[gb + (size_t)(r0 + 8) * T + col]) = make_float2(s[nt][2], s[nt][3]);
            l0 += __expf(s[nt][0]) + __expf(s[nt][1]);
            l1 += __expf(s[nt][2]) + __expf(s[nt][3]);
        }
        __syncthreads();
    }

    l0 += __shfl_xor_sync(0xffffffffu, l0, 1);
    l0 += __shfl_xor_sync(0xffffffffu, l0, 2);
    l1 += __shfl_xor_sync(0xffffffffu, l1, 1);
    l1 += __shfl_xor_sync(0xffffffffu, l1, 2);
    if ((lane & 3) == 0) {
        invL[w * 16 + (lane >> 2)] = 1.f / l0;
        invL[w * 16 + (lane >> 2) + 8] = 1.f / l1;
    }
    __syncthreads();

    // ------------------ pass 2 ------------------
    float o[16][4] = {};
    load_kv_async(Vhg, Vlg, KV, KV + 64 * AS, krow0, kcol, tid);
    CP_COMMIT();

    #pragma unroll 1
    for (int kt = 0; kt < 32; kt++) {
        if (kt < 31) {
            __nv_bfloat16* nb = KV + ((kt + 1) & 1) * 2 * 64 * AS;
            load_kv_async(Vhg, Vlg, nb, nb + 64 * AS, krow0 + (kt + 1) * 64, kcol, tid);
        }
        CP_COMMIT();

        // S -> normalized w (overwrite AW) + split into P smem (overlaps cp.async)
        const size_t sb = ((size_t)bh * T + (size_t)qt * 128) * T + (size_t)kt * 64;
        #pragma unroll
        for (int j = 0; j < 8; j++) {
            int idx = j * 256 + tid;
            int r = idx >> 4, c = (idx & 15) * 4;
            float4 sv = *reinterpret_cast<float4*>(&AW[sb + (size_t)r * T + c]);
            float il = invL[r];
            float w0 = __expf(sv.x) * il, w1 = __expf(sv.y) * il;
            float w2 = __expf(sv.z) * il, w3 = __expf(sv.w) * il;
            *reinterpret_cast<float4*>(&AW[sb + (size_t)r * T + c]) = make_float4(w0, w1, w2, w3);
            __nv_bfloat162 hh, ll;
            hh.x = __float2bfloat16(w0); hh.y = __float2bfloat16(w1);
            ll.x = __float2bfloat16(w0 - __bfloat162float(hh.x));
            ll.y = __float2bfloat16(w1 - __bfloat162float(hh.y));
            *reinterpret_cast<__nv_bfloat162*>(&Ph[r * PS + c]) = hh;
            *reinterpret_cast<__nv_bfloat162*>(&Pl[r * PS + c]) = ll;
            hh.x = __float2bfloat16(w2); hh.y = __float2bfloat16(w3);
            ll.x = __float2bfloat16(w2 - __bfloat162float(hh.x));
            ll.y = __float2bfloat16(w3 - __bfloat162float(hh.y));
            *reinterpret_cast<__nv_bfloat162*>(&Ph[r * PS + c + 2]) = hh;
            *reinterpret_cast<__nv_bfloat162*>(&Pl[r * PS + c + 2]) = ll;
        }
        CP_WAIT1();
        __syncthreads();

        const __nv_bfloat16* Vbh = KV + (kt & 1) * 2 * 64 * AS;
        const __nv_bfloat16* Vbl = Vbh + 64 * AS;

        #pragma unroll
        for (int kc = 0; kc < 4; kc++) {
            uint32_t ph4[4], pl4[4];
            int pr = w * 16 + (lane & 15), pc = kc * 16 + (lane >> 4) * 8;
            ldsm_x4(ph4, smem_u32(&Ph[pr * PS + pc]));
            ldsm_x4(pl4, smem_u32(&Pl[pr * PS + pc]));
            #pragma unroll
            for (int p = 0; p < 8; p++) {
                int vr = kc * 16 + (lane & 15), vc = p * 16 + (lane >> 4) * 8;
                uint32_t v4h[4], v4l[4];
                ldsm_x4t(v4h, smem_u32(&Vbh[vr * AS + vc]));
                ldsm_x4t(v4l, smem_u32(&Vbl[vr * AS + vc]));
                uint32_t be_h[2] = {v4h[0], v4h[1]}, bo_h[2] = {v4h[2], v4h[3]};
                uint32_t be_l[2] = {v4l[0], v4l[1]}, bo_l[2] = {v4l[2], v4l[3]};
                mma16816(o[2*p],   ph4, be_h); mma16816(o[2*p],   ph4, be_l); mma16816(o[2*p],   pl4, be_h);
                mma16816(o[2*p+1], ph4, bo_h); mma16816(o[2*p+1], ph4, bo_l); mma16816(o[2*p+1], pl4, bo_h);
            }
        }
        __syncthreads();
    }

    // write O to g_O [b, t, h*128 + c]
    #pragma unroll
    for (int nt = 0; nt < 16; nt++) {
        int r = w * 16 + (lane >> 2);
        int c = nt * 8 + (lane & 3) * 2;
        *reinterpret_cast<float2*>(&Op[(qrow0 + r) * DIM + h * 128 + c]) =
            make_float2(o[nt][0], o[nt][1]);
        *reinterpret_cast<float2*>(&Op[(qrow0 + r + 8) * DIM + h * 128 + c]) =
            make_float2(o[nt][2], o[nt][3]);
    }
}

// ---------------------------------------------------------------------------
// launch
// ---------------------------------------------------------------------------
extern "C" void kernel_launch(void* const* d_in, const int* in_sizes, int n_in,
                              void* d_out, int out_size)
{
    const float* q  = (const float*)d_in[0];
    const float* k  = (const float*)d_in[1];
    const float* v  = (const float*)d_in[2];
    const float* Wq = (const float*)d_in[3];
    const float* bq = (const float*)d_in[4];
    const float* Wk = (const float*)d_in[5];
    const float* bk = (const float*)d_in[6];
    const float* Wv = (const float*)d_in[7];
    const float* bv = (const float*)d_in[8];
    const float* Wo = (const float*)d_in[9];
    const float* bo = (const float*)d_in[10];

    float* out   = (float*)d_out;
    float* attnW = out + (size_t)BT * DIM;

    __nv_bfloat16 *gQh, *gQl, *gKh, *gKl, *gVh, *gVl;
    float* gO;
    cudaGetSymbolAddress((void**)&gQh, g_Qh);
    cudaGetSymbolAddress((void**)&gQl, g_Ql);
    cudaGetSymbolAddress((void**)&gKh, g_Kh);
    cudaGetSymbolAddress((void**)&gKl, g_Kl);
    cudaGetSymbolAddress((void**)&gVh, g_Vh);
    cudaGetSymbolAddress((void**)&gVl, g_Vl);
    cudaGetSymbolAddress((void**)&gO, g_O);

    cudaFuncSetAttribute(attn_kernel, cudaFuncAttributeMaxDynamicSharedMemorySize,
                         ATTN_SMEM_BYTES);

    const float scale = 0.08838834764831845f;  // 1/sqrt(128)

    // projections (split-bf16 epilogue; Q pre-scaled)
    gemm_bias_kernel<<<dim3(DIM / 128, BT / 128), 256>>>(
        q, Wq, bq, nullptr, gQh, gQl, scale, BT, DIM, DIM);
    gemm_bias_kernel<<<dim3(KVDIM / 128, BT / 128), 256>>>(
        k, Wk, bk, nullptr, gKh, gKl, 1.f, BT, KVDIM, DIM);
    gemm_bias_kernel<<<dim3(KVDIM / 128, BT / 128), 256>>>(
        v, Wv, bv, nullptr, gVh, gVl, 1.f, BT, KVDIM, DIM);

    // attention
    attn_kernel<<<dim3(T / 128, 32), 256, ATTN_SMEM_BYTES>>>(
        gQh, gQl, gKh, gKl, gVh, gVl, attnW, gO);

    // output projection (fp32 epilogue)
    gemm_bias_kernel<<<dim3(DIM / 128, BT / 128), 256>>>(
        gO, Wo, bo, out, nullptr, nullptr, 1.f, BT, DIM, DIM);
}

// round 3
// speedup vs baseline: 1.1680x; 1.0066x over previous
#include <cuda_runtime.h>
#include <cuda_bf16.h>
#include <cstdint>
#include <cmath>

// ---------------------------------------------------------------------------
// GroupedQueryAttention: B=2, T=2048, DIM=2048, H=16, KH=4, DK=DV=128
// d_out = [ out (2,2048,2048) fp32 | attn_weight (2,16,2048,2048) fp32 ]
//
// Round 2: pre-split bf16 hi/lo Q/K/V, S staged in the AW output buffer
// (no recompute), 256-thread attention CTAs, cp.async double buffering,
// ldmatrix.x4 everywhere. Split-bf16 3-term MMA for precision.
// ---------------------------------------------------------------------------

#define BT 4096
#define DIM 2048
#define KVDIM 512
#define T 2048

__device__ __nv_bfloat16 g_Qh[BT * DIM];
__device__ __nv_bfloat16 g_Ql[BT * DIM];
__device__ __nv_bfloat16 g_Kh[BT * KVDIM];
__device__ __nv_bfloat16 g_Kl[BT * KVDIM];
__device__ __nv_bfloat16 g_Vh[BT * KVDIM];
__device__ __nv_bfloat16 g_Vl[BT * KVDIM];
__device__ float g_O[BT * DIM];

// ---------------------------------------------------------------------------
// helpers
// ---------------------------------------------------------------------------
__device__ __forceinline__ uint32_t smem_u32(const void* p) {
    return (uint32_t)__cvta_generic_to_shared(p);
}
__device__ __forceinline__ void ldsm_x4(uint32_t* r, uint32_t addr) {
    asm volatile("ldmatrix.sync.aligned.m8n8.x4.shared.b16 {%0,%1,%2,%3}, [%4];"
                 : "=r"(r[0]), "=r"(r[1]), "=r"(r[2]), "=r"(r[3]) : "r"(addr));
}
__device__ __forceinline__ void ldsm_x4t(uint32_t* r, uint32_t addr) {
    asm volatile("ldmatrix.sync.aligned.m8n8.x4.trans.shared.b16 {%0,%1,%2,%3}, [%4];"
                 : "=r"(r[0]), "=r"(r[1]), "=r"(r[2]), "=r"(r[3]) : "r"(addr));
}
__device__ __forceinline__ void mma16816(float* c, const uint32_t* a, const uint32_t* b) {
    asm volatile(
        "mma.sync.aligned.m16n8k16.row.col.f32.bf16.bf16.f32 "
        "{%0,%1,%2,%3}, {%4,%5,%6,%7}, {%8,%9}, {%0,%1,%2,%3};\n"
        : "+f"(c[0]), "+f"(c[1]), "+f"(c[2]), "+f"(c[3])
        : "r"(a[0]), "r"(a[1]), "r"(a[2]), "r"(a[3]), "r"(b[0]), "r"(b[1]));
}
__device__ __forceinline__ void cp16(uint32_t saddr, const void* g) {
    asm volatile("cp.async.cg.shared.global [%0], [%1], 16;" :: "r"(saddr), "l"(g));
}
#define CP_COMMIT() asm volatile("cp.async.commit_group;")
#define CP_WAIT1()  asm volatile("cp.async.wait_group 1;")

__device__ __forceinline__ void split_store(float x, __nv_bfloat16* ph, __nv_bfloat16* pl) {
    __nv_bfloat16 h = __float2bfloat16(x);
    *ph = h;
    *pl = __float2bfloat16(x - __bfloat162float(h));
}

// ---------------------------------------------------------------------------
// GEMM: C[M,N] = (A[M,K] @ W[K,N] + bias) * scale
// epilogue: fp32 (Cf) or split-bf16 (Ch/Cl). 256 threads, BM=128 BN=128 BK=32.
// ---------------------------------------------------------------------------
#define GA_STRIDE 40
#define GB_STRIDE 136

__global__ __launch_bounds__(256) void gemm_bias_kernel(
    const float* __restrict__ A, const float* __restrict__ W,
    const float* __restrict__ bias,
    float* __restrict__ Cf, __nv_bfloat16* __restrict__ Ch, __nv_bfloat16* __restrict__ Cl,
    float scale, int M, int N, int K)
{
    __shared__ __nv_bfloat16 Ah[128 * GA_STRIDE];
    __shared__ __nv_bfloat16 Al[128 * GA_STRIDE];
    __shared__ __nv_bfloat16 Bh[32 * GB_STRIDE];
    __shared__ __nv_bfloat16 Bl[32 * GB_STRIDE];

    const int tid = threadIdx.x;
    const int lane = tid & 31;
    const int wid = tid >> 5;
    const int wm = wid >> 2;
    const int wn = wid & 3;
    const int bm0 = blockIdx.y * 128;
    const int bn0 = blockIdx.x * 128;

    float acc[4][4][4] = {};

    for (int kt = 0; kt < K; kt += 32) {
        #pragma unroll
        for (int i = 0; i < 4; i++) {
            int row = (tid >> 3) + i * 32;
            int col = (tid & 7) * 4;
            const float4 v = *reinterpret_cast<const float4*>(
                &A[(size_t)(bm0 + row) * K + kt + col]);
            float xs[4] = {v.x, v.y, v.z, v.w};
            #pragma unroll
            for (int j = 0; j < 4; j++)
                split_store(xs[j], &Ah[row * GA_STRIDE + col + j], &Al[row * GA_STRIDE + col + j]);
        }
        #pragma unroll
        for (int i = 0; i < 4; i++) {
            int row = (tid >> 5) + i * 8;
            int col = (tid & 31) * 4;
            const float4 v = *reinterpret_cast<const float4*>(
                &W[(size_t)(kt + row) * N + bn0 + col]);
            float xs[4] = {v.x, v.y, v.z, v.w};
            #pragma unroll
            for (int j = 0; j < 4; j++)
                split_store(xs[j], &Bh[row * GB_STRIDE + col + j], &Bl[row * GB_STRIDE + col + j]);
        }
        __syncthreads();

        #pragma unroll
        for (int ks = 0; ks < 2; ks++) {
            uint32_t ah[4][4], al[4][4];
            #pragma unroll
            for (int mt = 0; mt < 4; mt++) {
                int r = wm * 64 + mt * 16 + (lane & 15);
                int c = ks * 16 + (lane >> 4) * 8;
                ldsm_x4(ah[mt], smem_u32(&Ah[r * GA_STRIDE + c]));
                ldsm_x4(al[mt], smem_u32(&Al[r * GA_STRIDE + c]));
            }
            uint32_t bh[4][2], bl[4][2];
            #pragma unroll
            for (int p = 0; p < 2; p++) {
                int r = ks * 16 + (lane & 15);
                int c = wn * 32 + p * 16 + (lane >> 4) * 8;
                uint32_t t4[4];
                ldsm_x4t(t4, smem_u32(&Bh[r * GB_STRIDE + c]));
                bh[2*p][0] = t4[0]; bh[2*p][1] = t4[1];
                bh[2*p+1][0] = t4[2]; bh[2*p+1][1] = t4[3];
                ldsm_x4t(t4, smem_u32(&Bl[r * GB_STRIDE + c]));
                bl[2*p][0] = t4[0]; bl[2*p][1] = t4[1];
                bl[2*p+1][0] = t4[2]; bl[2*p+1][1] = t4[3];
            }
            #pragma unroll
            for (int mt = 0; mt < 4; mt++)
                #pragma unroll
                for (int nt = 0; nt < 4; nt++) {
                    mma16816(acc[mt][nt], ah[mt], bh[nt]);
                    mma16816(acc[mt][nt], ah[mt], bl[nt]);
                    mma16816(acc[mt][nt], al[mt], bh[nt]);
                }
        }
        __syncthreads();
    }

    #pragma unroll
    for (int mt = 0; mt < 4; mt++)
        #pragma unroll
        for (int nt = 0; nt < 4; nt++) {
            int row = bm0 + wm * 64 + mt * 16 + (lane >> 2);
            int col = bn0 + wn * 32 + nt * 8 + (lane & 3) * 2;
            float b0 = bias[col], b1 = bias[col + 1];
            float v00 = (acc[mt][nt][0] + b0) * scale;
            float v01 = (acc[mt][nt][1] + b1) * scale;
            float v10 = (acc[mt][nt][2] + b0) * scale;
            float v11 = (acc[mt][nt][3] + b1) * scale;
            if (Cf) {
                *reinterpret_cast<float2*>(&Cf[(size_t)row * N + col]) = make_float2(v00, v01);
                *reinterpret_cast<float2*>(&Cf[(size_t)(row + 8) * N + col]) = make_float2(v10, v11);
            } else {
                __nv_bfloat162 hh, ll;
                hh.x = __float2bfloat16(v00); hh.y = __float2bfloat16(v01);
                ll.x = __float2bfloat16(v00 - __bfloat162float(hh.x));
                ll.y = __float2bfloat16(v01 - __bfloat162float(hh.y));
                *reinterpret_cast<__nv_bfloat162*>(&Ch[(size_t)row * N + col]) = hh;
                *reinterpret_cast<__nv_bfloat162*>(&Cl[(size_t)row * N + col]) = ll;
                hh.x = __float2bfloat16(v10); hh.y = __float2bfloat16(v11);
                ll.x = __float2bfloat16(v10 - __bfloat162float(hh.x));
                ll.y = __float2bfloat16(v11 - __bfloat162float(hh.y));
                *reinterpret_cast<__nv_bfloat162*>(&Ch[(size_t)(row + 8) * N + col]) = hh;
                *reinterpret_cast<__nv_bfloat162*>(&Cl[(size_t)(row + 8) * N + col]) = ll;
            }
        }
}

// ---------------------------------------------------------------------------
// Attention: grid (16 qtiles x 32 bh), 256 threads (8 warps x 16 q rows).
// pass1: S = Q K^T  -> staged raw into AW buffer; l = sum exp(S) per row.
// pass2: w = exp(S)/l -> AW (overwrite) + split to smem; O += P V.
// Double-buffered cp.async K/V tiles (64 keys).
// ---------------------------------------------------------------------------
#define AS 136
#define PS 72
#define ATTN_SMEM_BYTES ((2 * 128 * AS + 4 * 64 * AS + 2 * 128 * PS) * 2 + 128 * 4)

__device__ __forceinline__ void load_kv_async(
    const __nv_bfloat16* __restrict__ gh, const __nv_bfloat16* __restrict__ gl,
    __nv_bfloat16* sh, __nv_bfloat16* sl, size_t row0, int col0, int tid)
{
    #pragma unroll
    for (int i = 0; i < 4; i++) {
        int idx = i * 256 + tid;
        int r = idx >> 4, c = (idx & 15) * 8;
        cp16(smem_u32(&sh[r * AS + c]), &gh[(row0 + r) * KVDIM + col0 + c]);
        cp16(smem_u32(&sl[r * AS + c]), &gl[(row0 + r) * KVDIM + col0 + c]);
    }
}

__global__ __launch_bounds__(256) void attn_kernel(
    const __nv_bfloat16* __restrict__ Qhg, const __nv_bfloat16* __restrict__ Qlg,
    const __nv_bfloat16* __restrict__ Khg, const __nv_bfloat16* __restrict__ Klg,
    const __nv_bfloat16* __restrict__ Vhg, const __nv_bfloat16* __restrict__ Vlg,
    float* __restrict__ AW, float* __restrict__ Op)
{
    extern __shared__ __nv_bfloat16 smem[];
    __nv_bfloat16* Qh = smem;
    __nv_bfloat16* Ql = Qh + 128 * AS;
    __nv_bfloat16* KV = Ql + 128 * AS;        // 4 x (64*AS): buf0h, buf0l, buf1h, buf1l
    __nv_bfloat16* Ph = KV + 4 * 64 * AS;
    __nv_bfloat16* Pl = Ph + 128 * PS;
    float* invL = reinterpret_cast<float*>(Pl + 128 * PS);

    const int tid = threadIdx.x;
    const int lane = tid & 31;
    const int w = tid >> 5;
    const int qt = blockIdx.x;
    const int bh = blockIdx.y;
    const int b = bh >> 4, h = bh & 15, kv = h >> 2;

    const size_t qrow0 = (size_t)b * T + qt * 128;
    const size_t krow0 = (size_t)b * T;
    const int kcol = kv * 128;

    // prologue: K tile 0 async, Q plain
    load_kv_async(Khg, Klg, KV, KV + 64 * AS, krow0, kcol, tid);
    CP_COMMIT();
    #pragma unroll
    for (int i = 0; i < 8; i++) {
        int idx = i * 256 + tid;
        int r = idx >> 4, c = (idx & 15) * 8;
        *reinterpret_cast<uint4*>(&Qh[r * AS + c]) =
            *reinterpret_cast<const uint4*>(&Qhg[(qrow0 + r) * DIM + h * 128 + c]);
        *reinterpret_cast<uint4*>(&Ql[r * AS + c]) =
            *reinterpret_cast<const uint4*>(&Qlg[(qrow0 + r) * DIM + h * 128 + c]);
    }

    float l0 = 0.f, l1 = 0.f;

    // ------------------ pass 1 ------------------
    #pragma unroll 1
    for (int kt = 0; kt < 32; kt++) {
        if (kt < 31) {
            __nv_bfloat16* nb = KV + ((kt + 1) & 1) * 2 * 64 * AS;
            load_kv_async(Khg, Klg, nb, nb + 64 * AS, krow0 + (kt + 1) * 64, kcol, tid);
        }
        CP_COMMIT();
        CP_WAIT1();
        __syncthreads();

        const __nv_bfloat16* Kbh = KV + (kt & 1) * 2 * 64 * AS;
        const __nv_bfloat16* Kbl = Kbh + 64 * AS;

        float s[8][4];
        #pragma unroll
        for (int nt = 0; nt < 8; nt++)
            #pragma unroll
            for (int j = 0; j < 4; j++) s[nt][j] = 0.f;

        #pragma unroll
        for (int kk = 0; kk < 8; kk++) {
            uint32_t ah[4], al[4];
            int ar = w * 16 + (lane & 15), ac = kk * 16 + (lane >> 4) * 8;
            ldsm_x4(ah, smem_u32(&Qh[ar * AS + ac]));
            ldsm_x4(al, smem_u32(&Ql[ar * AS + ac]));
            #pragma unroll
            for (int p = 0; p < 4; p++) {
                int br = p * 16 + (lane & 15), bc = kk * 16 + (lane >> 4) * 8;
                uint32_t b4h[4], b4l[4];
                ldsm_x4(b4h, smem_u32(&Kbh[br * AS + bc]));
                ldsm_x4(b4l, smem_u32(&Kbl[br * AS + bc]));
                uint32_t be_h[2] = {b4h[0], b4h[2]}, bo_h[2] = {b4h[1], b4h[3]};
                uint32_t be_l[2] = {b4l[0], b4l[2]}, bo_l[2] = {b4l[1], b4l[3]};
                mma16816(s[2*p],   ah, be_h); mma16816(s[2*p],   ah, be_l); mma16816(s[2*p],   al, be_h);
                mma16816(s[2*p+1], ah, bo_h); mma16816(s[2*p+1], ah, bo_l); mma16816(s[2*p+1], al, bo_h);
            }
        }

        // stage raw S into AW; accumulate per-thread partial exp-sums
        const size_t gb = ((size_t)bh * T + (size_t)qt * 128) * T;
        const int r0 = w * 16 + (lane >> 2), c0 = (lane & 3) * 2;
        #pragma unroll
        for (int nt = 0; nt < 8; nt++) {
            const int col = kt * 64 + nt * 8 + c0;
            *reinterpret_cast<float2*>(&AW[gb + (size_t)r0 * T + col]) = make_float2(s[nt][0], s[nt][1]);
            *reinterpret_cast<float2*>(&AW[gb + (size_t)(r0 + 8) * T + col]) = make_float2(s[nt][2], s[nt][3]);
            l0 += __expf(s[nt][0]) + __expf(s[nt][1]);
            l1 += __expf(s[nt][2]) + __expf(s[nt][3]);
        }
        __syncthreads();
    }

    l0 += __shfl_xor_sync(0xffffffffu, l0, 1);
    l0 += __shfl_xor_sync(0xffffffffu, l0, 2);
    l1 += __shfl_xor_sync(0xffffffffu, l1, 1);
    l1 += __shfl_xor_sync(0xffffffffu, l1, 2);
    if ((lane & 3) == 0) {
        invL[w * 16 + (lane >> 2)] = 1.f / l0;
        invL[w * 16 + (lane >> 2) + 8] = 1.f / l1;
    }
    __syncthreads();

    // ------------------ pass 2 ------------------
    float o[16][4] = {};
    load_kv_async(Vhg, Vlg, KV, KV + 64 * AS, krow0, kcol, tid);
    CP_COMMIT();

    #pragma unroll 1
    for (int kt = 0; kt < 32; kt++) {
        if (kt < 31) {
            __nv_bfloat16* nb = KV + ((kt + 1) & 1) * 2 * 64 * AS;
            load_kv_async(Vhg, Vlg, nb, nb + 64 * AS, krow0 + (kt + 1) * 64, kcol, tid);
        }
        CP_COMMIT();

        // S -> normalized w (overwrite AW) + split into P smem (overlaps cp.async)
        const size_t sb = ((size_t)bh * T + (size_t)qt * 128) * T + (size_t)kt * 64;
        #pragma unroll
        for (int j = 0; j < 8; j++) {
            int idx = j * 256 + tid;
            int r = idx >> 4, c = (idx & 15) * 4;
            float4 sv = *reinterpret_cast<float4*>(&AW[sb + (size_t)r * T + c]);
            float il = invL[r];
            float w0 = __expf(sv.x) * il, w1 = __expf(sv.y) * il;
            float w2 = __expf(sv.z) * il, w3 = __expf(sv.w) * il;
            *reinterpret_cast<float4*>(&AW[sb + (size_t)r * T + c]) = make_float4(w0, w1, w2, w3);
            __nv_bfloat162 hh, ll;
            hh.x = __float2bfloat16(w0); hh.y = __float2bfloat16(w1);
            ll.x = __float2bfloat16(w0 - __bfloat162float(hh.x));
            ll.y = __float2bfloat16(w1 - __bfloat162float(hh.y));
            *reinterpret_cast<__nv_bfloat162*>(&Ph[r * PS + c]) = hh;
            *reinterpret_cast<__nv_bfloat162*>(&Pl[r * PS + c]) = ll;
            hh.x = __float2bfloat16(w2); hh.y = __float2bfloat16(w3);
            ll.x = __float2bfloat16(w2 - __bfloat162float(hh.x));
            ll.y = __float2bfloat16(w3 - __bfloat162float(hh.y));
            *reinterpret_cast<__nv_bfloat162*>(&Ph[r * PS + c + 2]) = hh;
            *reinterpret_cast<__nv_bfloat162*>(&Pl[r * PS + c + 2]) = ll;
        }
        CP_WAIT1();
        __syncthreads();

        const __nv_bfloat16* Vbh = KV + (kt & 1) * 2 * 64 * AS;
        const __nv_bfloat16* Vbl = Vbh + 64 * AS;

        #pragma unroll
        for (int kc = 0; kc < 4; kc++) {
            uint32_t ph4[4], pl4[4];
            int pr = w * 16 + (lane & 15), pc = kc * 16 + (lane >> 4) * 8;
            ldsm_x4(ph4, smem_u32(&Ph[pr * PS + pc]));
            ldsm_x4(pl4, smem_u32(&Pl[pr * PS + pc]));
            #pragma unroll
            for (int p = 0; p < 8; p++) {
                int vr = kc * 16 + (lane & 15), vc = p * 16 + (lane >> 4) * 8;
                uint32_t v4h[4], v4l[4];
                ldsm_x4t(v4h, smem_u32(&Vbh[vr * AS + vc]));
                ldsm_x4t(v4l, smem_u32(&Vbl[vr * AS + vc]));
                uint32_t be_h[2] = {v4h[0], v4h[1]}, bo_h[2] = {v4h[2], v4h[3]};
                uint32_t be_l[2] = {v4l[0], v4l[1]}, bo_l[2] = {v4l[2], v4l[3]};
                mma16816(o[2*p],   ph4, be_h); mma16816(o[2*p],   ph4, be_l); mma16816(o[2*p],   pl4, be_h);
                mma16816(o[2*p+1], ph4, bo_h); mma16816(o[2*p+1], ph4, bo_l); mma16816(o[2*p+1], pl4, bo_h);
            }
        }
        __syncthreads();
    }

    // write O to g_O [b, t, h*128 + c]
    #pragma unroll
    for (int nt = 0; nt < 16; nt++) {
        int r = w * 16 + (lane >> 2);
        int c = nt * 8 + (lane & 3) * 2;
        *reinterpret_cast<float2*>(&Op[(qrow0 + r) * DIM + h * 128 + c]) =
            make_float2(o[nt][0], o[nt][1]);
        *reinterpret_cast<float2*>(&Op[(qrow0 + r + 8) * DIM + h * 128 + c]) =
            make_float2(o[nt][2], o[nt][3]);
    }
}

// ---------------------------------------------------------------------------
// launch
// ---------------------------------------------------------------------------
extern "C" void kernel_launch(void* const* d_in, const int* in_sizes, int n_in,
                              void* d_out, int out_size)
{
    const float* q  = (const float*)d_in[0];
    const float* k  = (const float*)d_in[1];
    const float* v  = (const float*)d_in[2];
    const float* Wq = (const float*)d_in[3];
    const float* bq = (const float*)d_in[4];
    const float* Wk = (const float*)d_in[5];
    const float* bk = (const float*)d_in[6];
    const float* Wv = (const float*)d_in[7];
    const float* bv = (const float*)d_in[8];
    const float* Wo = (const float*)d_in[9];
    const float* bo = (const float*)d_in[10];

    float* out   = (float*)d_out;
    float* attnW = out + (size_t)BT * DIM;

    __nv_bfloat16 *gQh, *gQl, *gKh, *gKl, *gVh, *gVl;
    float* gO;
    cudaGetSymbolAddress((void**)&gQh, g_Qh);
    cudaGetSymbolAddress((void**)&gQl, g_Ql);
    cudaGetSymbolAddress((void**)&gKh, g_Kh);
    cudaGetSymbolAddress((void**)&gKl, g_Kl);
    cudaGetSymbolAddress((void**)&gVh, g_Vh);
    cudaGetSymbolAddress((void**)&gVl, g_Vl);
    cudaGetSymbolAddress((void**)&gO, g_O);

    cudaFuncSetAttribute(attn_kernel, cudaFuncAttributeMaxDynamicSharedMemorySize,
                         ATTN_SMEM_BYTES);

    const float scale = 0.08838834764831845f;  // 1/sqrt(128)

    // projections (split-bf16 epilogue; Q pre-scaled)
    gemm_bias_kernel<<<dim3(DIM / 128, BT / 128), 256>>>(
        q, Wq, bq, nullptr, gQh, gQl, scale, BT, DIM, DIM);
    gemm_bias_kernel<<<dim3(KVDIM / 128, BT / 128), 256>>>(
        k, Wk, bk, nullptr, gKh, gKl, 1.f, BT, KVDIM, DIM);
    gemm_bias_kernel<<<dim3(KVDIM / 128, BT / 128), 256>>>(
        v, Wv, bv, nullptr, gVh, gVl, 1.f, BT, KVDIM, DIM);

    // attention
    attn_kernel<<<dim3(T / 128, 32), 256, ATTN_SMEM_BYTES>>>(
        gQh, gQl, gKh, gKl, gVh, gVl, attnW, gO);

    // output projection (fp32 epilogue)
    gemm_bias_kernel<<<dim3(DIM / 128, BT / 128), 256>>>(
        gO, Wo, bo, out, nullptr, nullptr, 1.f, BT, DIM, DIM);
}

// round 5
// speedup vs baseline: 1.6289x; 1.3946x over previous
#include <cuda_runtime.h>
#include <cuda_bf16.h>
#include <cstdint>
#include <cmath>

// ---------------------------------------------------------------------------
// GroupedQueryAttention: B=2, T=2048, DIM=2048, H=16, KH=4, DK=DV=128
// d_out = [ out (2,2048,2048) fp32 | attn_weight (2,16,2048,2048) fp32 ]
//
// Round 4: no tcgen05 (ptxas target is compute_103, arch-specific instrs
// rejected). mma.sync path, restructured:
//  - all operands pre-split to bf16 hi/lo once (split kernels)
//  - GEMMs: cp.async double-buffered, pure bf16 loads, 3-term split MMA
//  - attention: single pass, raw exp(s) -> AW, O scaled by 1/l at end,
//    separate streaming normalize kernel for AW
// ---------------------------------------------------------------------------

#define BT 4096
#define DIM 2048
#define KVDIM 512
#define T 2048

// ---- device scratch (no allocation allowed) ----
__device__ __nv_bfloat16 g_qh[BT * DIM],  g_ql[BT * DIM];     // split of input q
__device__ __nv_bfloat16 g_kh[BT * DIM],  g_kl[BT * DIM];     // split of input k
__device__ __nv_bfloat16 g_vh[BT * DIM],  g_vl[BT * DIM];     // split of input v
__device__ __nv_bfloat16 g_Wqh[DIM * DIM], g_Wql[DIM * DIM];
__device__ __nv_bfloat16 g_Wkh[DIM * KVDIM], g_Wkl[DIM * KVDIM];
__device__ __nv_bfloat16 g_Wvh[DIM * KVDIM], g_Wvl[DIM * KVDIM];
__device__ __nv_bfloat16 g_Woh[DIM * DIM], g_Wol[DIM * DIM];
__device__ __nv_bfloat16 g_Qh[BT * DIM],  g_Ql[BT * DIM];     // q projection (scaled)
__device__ __nv_bfloat16 g_Kh[BT * KVDIM], g_Kl[BT * KVDIM];  // k projection
__device__ __nv_bfloat16 g_Vh[BT * KVDIM], g_Vl[BT * KVDIM];  // v projection
__device__ __nv_bfloat16 g_Oh[BT * DIM],  g_Ol[BT * DIM];     // attn output (pre-split)
__device__ float g_invL[32 * T];                               // 1/rowsum per (bh, q)

// ---------------------------------------------------------------------------
// helpers
// ---------------------------------------------------------------------------
__device__ __forceinline__ uint32_t smem_u32(const void* p) {
    return (uint32_t)__cvta_generic_to_shared(p);
}
__device__ __forceinline__ void ldsm_x4(uint32_t* r, uint32_t addr) {
    asm volatile("ldmatrix.sync.aligned.m8n8.x4.shared.b16 {%0,%1,%2,%3}, [%4];"
                 : "=r"(r[0]), "=r"(r[1]), "=r"(r[2]), "=r"(r[3]) : "r"(addr));
}
__device__ __forceinline__ void ldsm_x4t(uint32_t* r, uint32_t addr) {
    asm volatile("ldmatrix.sync.aligned.m8n8.x4.trans.shared.b16 {%0,%1,%2,%3}, [%4];"
                 : "=r"(r[0]), "=r"(r[1]), "=r"(r[2]), "=r"(r[3]) : "r"(addr));
}
__device__ __forceinline__ void mma16816(float* c, const uint32_t* a, const uint32_t* b) {
    asm volatile(
        "mma.sync.aligned.m16n8k16.row.col.f32.bf16.bf16.f32 "
        "{%0,%1,%2,%3}, {%4,%5,%6,%7}, {%8,%9}, {%0,%1,%2,%3};\n"
        : "+f"(c[0]), "+f"(c[1]), "+f"(c[2]), "+f"(c[3])
        : "r"(a[0]), "r"(a[1]), "r"(a[2]), "r"(a[3]), "r"(b[0]), "r"(b[1]));
}
__device__ __forceinline__ void cp16(uint32_t saddr, const void* g) {
    asm volatile("cp.async.cg.shared.global [%0], [%1], 16;" :: "r"(saddr), "l"(g));
}
#define CP_COMMIT() asm volatile("cp.async.commit_group;")
#define CP_WAIT1()  asm volatile("cp.async.wait_group 1;")

__device__ __forceinline__ __nv_bfloat162 pack_hi(float a, float b) {
    __nv_bfloat162 r; r.x = __float2bfloat16(a); r.y = __float2bfloat16(b); return r;
}
__device__ __forceinline__ __nv_bfloat162 pack_lo(float a, float b, __nv_bfloat162 h) {
    __nv_bfloat162 r;
    r.x = __float2bfloat16(a - __bfloat162float(h.x));
    r.y = __float2bfloat16(b - __bfloat162float(h.y));
    return r;
}

// ---------------------------------------------------------------------------
// split: fp32 -> bf16 hi/lo (elementwise)
// ---------------------------------------------------------------------------
__global__ void split_kernel(const float* __restrict__ src,
                             __nv_bfloat16* __restrict__ h,
                             __nv_bfloat16* __restrict__ l, int n4)
{
    int i = blockIdx.x * blockDim.x + threadIdx.x;
    if (i >= n4) return;
    float4 v = reinterpret_cast<const float4*>(src)[i];
    __nv_bfloat162 h0 = pack_hi(v.x, v.y), h1 = pack_hi(v.z, v.w);
    __nv_bfloat162 l0 = pack_lo(v.x, v.y, h0), l1 = pack_lo(v.z, v.w, h1);
    uint2 hv = make_uint2(*(uint32_t*)&h0, *(uint32_t*)&h1);
    uint2 lv = make_uint2(*(uint32_t*)&l0, *(uint32_t*)&l1);
    *reinterpret_cast<uint2*>(&h[(size_t)i * 4]) = hv;
    *reinterpret_cast<uint2*>(&l[(size_t)i * 4]) = lv;
}

// ---------------------------------------------------------------------------
// normalize: AW[row][*] *= invL[row]   (row = global (bh,q) row, T cols)
// ---------------------------------------------------------------------------
__global__ void normalize_kernel(float* __restrict__ AW, const float* __restrict__ invL)
{
    size_t i4 = (size_t)blockIdx.x * blockDim.x + threadIdx.x;  // one float4 each
    size_t e = i4 * 4;
    int row = (int)(e >> 11);           // /2048
    float il = __ldg(&invL[row]);
    float4 v = reinterpret_cast<float4*>(AW)[i4];
    v.x *= il; v.y *= il; v.z *= il; v.w *= il;
    reinterpret_cast<float4*>(AW)[i4] = v;
}

// ---------------------------------------------------------------------------
// GEMM: C[M,N] = (A[M,K] @ W[K,N] + bias) * scale ; A,W pre-split bf16 hi/lo.
// BM=128 BN=128 BK=32, 256 threads (8 warps 2x4), cp.async double buffered.
// 3-term split MMA (hh + hl + lh).
// smem (halves): per stage: Ah 128*40, Al 128*40, Bh 32*136, Bl 32*136
// ---------------------------------------------------------------------------
#define GAS 40
#define GBS 136
#define G_STG (128 * GAS * 2 + 32 * GBS * 2)     // halves per stage = 18944
#define G_SMEM_BYTES (2 * G_STG * 2 + 512)

__global__ __launch_bounds__(256) void gemm_bf16_kernel(
    const __nv_bfloat16* __restrict__ Ahg, const __nv_bfloat16* __restrict__ Alg,
    const __nv_bfloat16* __restrict__ Bhg, const __nv_bfloat16* __restrict__ Blg,
    const float* __restrict__ bias,
    float* __restrict__ Cf, __nv_bfloat16* __restrict__ Ch, __nv_bfloat16* __restrict__ Cl,
    float scale, int M, int N, int K)
{
    extern __shared__ __nv_bfloat16 sm[];
    float* biasS = (float*)(sm + 2 * G_STG);

    const int tid = threadIdx.x;
    const int lane = tid & 31;
    const int wid = tid >> 5;
    const int wm = wid >> 2;
    const int wn = wid & 3;
    const int bm0 = blockIdx.y * 128;
    const int bn0 = blockIdx.x * 128;

    if (tid < 128) biasS[tid] = bias[bn0 + tid];

    auto load_stage = [&](int s, int kt) {
        __nv_bfloat16* sAh = sm + s * G_STG;
        __nv_bfloat16* sAl = sAh + 128 * GAS;
        __nv_bfloat16* sBh = sAl + 128 * GAS;
        __nv_bfloat16* sBl = sBh + 32 * GBS;
        #pragma unroll
        for (int i = 0; i < 2; i++) {
            int idx = i * 256 + tid;
            int r = idx >> 2, cg = (idx & 3) * 8;
            cp16(smem_u32(&sAh[r * GAS + cg]), &Ahg[(size_t)(bm0 + r) * K + kt + cg]);
            cp16(smem_u32(&sAl[r * GAS + cg]), &Alg[(size_t)(bm0 + r) * K + kt + cg]);
        }
        #pragma unroll
        for (int i = 0; i < 2; i++) {
            int idx = i * 256 + tid;
            int r = idx >> 4, cg = (idx & 15) * 8;
            cp16(smem_u32(&sBh[r * GBS + cg]), &Bhg[(size_t)(kt + r) * N + bn0 + cg]);
            cp16(smem_u32(&sBl[r * GBS + cg]), &Blg[(size_t)(kt + r) * N + bn0 + cg]);
        }
    };

    float acc[4][4][4] = {};
    const int nk = K >> 5;

    load_stage(0, 0);
    CP_COMMIT();

    for (int it = 0; it < nk; it++) {
        if (it + 1 < nk) load_stage((it + 1) & 1, (it + 1) * 32);
        CP_COMMIT();
        CP_WAIT1();
        __syncthreads();

        const __nv_bfloat16* sAh = sm + (it & 1) * G_STG;
        const __nv_bfloat16* sAl = sAh + 128 * GAS;
        const __nv_bfloat16* sBh = sAl + 128 * GAS;
        const __nv_bfloat16* sBl = sBh + 32 * GBS;

        #pragma unroll
        for (int ks = 0; ks < 2; ks++) {
            uint32_t ah[4][4], al[4][4];
            #pragma unroll
            for (int mt = 0; mt < 4; mt++) {
                int r = wm * 64 + mt * 16 + (lane & 15);
                int c = ks * 16 + (lane >> 4) * 8;
                ldsm_x4(ah[mt], smem_u32(&sAh[r * GAS + c]));
                ldsm_x4(al[mt], smem_u32(&sAl[r * GAS + c]));
            }
            uint32_t bh[4][2], bl[4][2];
            #pragma unroll
            for (int p = 0; p < 2; p++) {
                int r = ks * 16 + (lane & 15);
                int c = wn * 32 + p * 16 + (lane >> 4) * 8;
                uint32_t t4[4];
                ldsm_x4t(t4, smem_u32(&sBh[r * GBS + c]));
                bh[2*p][0] = t4[0]; bh[2*p][1] = t4[1];
                bh[2*p+1][0] = t4[2]; bh[2*p+1][1] = t4[3];
                ldsm_x4t(t4, smem_u32(&sBl[r * GBS + c]));
                bl[2*p][0] = t4[0]; bl[2*p][1] = t4[1];
                bl[2*p+1][0] = t4[2]; bl[2*p+1][1] = t4[3];
            }
            #pragma unroll
            for (int mt = 0; mt < 4; mt++)
                #pragma unroll
                for (int nt = 0; nt < 4; nt++) {
                    mma16816(acc[mt][nt], ah[mt], bh[nt]);
                    mma16816(acc[mt][nt], ah[mt], bl[nt]);
                    mma16816(acc[mt][nt], al[mt], bh[nt]);
                }
        }
        __syncthreads();
    }

    #pragma unroll
    for (int mt = 0; mt < 4; mt++)
        #pragma unroll
        for (int nt = 0; nt < 4; nt++) {
            int row = bm0 + wm * 64 + mt * 16 + (lane >> 2);
            int colL = wn * 32 + nt * 8 + (lane & 3) * 2;
            int col = bn0 + colL;
            float b0 = biasS[colL], b1 = biasS[colL + 1];
            float v00 = (acc[mt][nt][0] + b0) * scale;
            float v01 = (acc[mt][nt][1] + b1) * scale;
            float v10 = (acc[mt][nt][2] + b0) * scale;
            float v11 = (acc[mt][nt][3] + b1) * scale;
            if (Cf) {
                *reinterpret_cast<float2*>(&Cf[(size_t)row * N + col]) = make_float2(v00, v01);
                *reinterpret_cast<float2*>(&Cf[(size_t)(row + 8) * N + col]) = make_float2(v10, v11);
            } else {
                __nv_bfloat162 h0 = pack_hi(v00, v01), l0 = pack_lo(v00, v01, h0);
                *reinterpret_cast<__nv_bfloat162*>(&Ch[(size_t)row * N + col]) = h0;
                *reinterpret_cast<__nv_bfloat162*>(&Cl[(size_t)row * N + col]) = l0;
                __nv_bfloat162 h1 = pack_hi(v10, v11), l1 = pack_lo(v10, v11, h1);
                *reinterpret_cast<__nv_bfloat162*>(&Ch[(size_t)(row + 8) * N + col]) = h1;
                *reinterpret_cast<__nv_bfloat162*>(&Cl[(size_t)(row + 8) * N + col]) = l1;
            }
        }
}

// ---------------------------------------------------------------------------
// Attention (single pass): grid (32 qtiles x 32 bh), 256 threads (8 warps 4x2).
// Per tile kt (64 keys): S = Q K^T (3-term mma), e = exp(s) -> AW (raw),
// l += e, P = split(e) -> smem, O += P V (3-term mma). End: O *= 1/l,
// write O split; 1/l -> g_invL.
// smem (halves): Qh 64*136, Ql 64*136, 2 KV stages x (Kh,Kl,Vh,Vl 64*136),
// Ph/Pl 64*72, then float lpart[2][64].
// ---------------------------------------------------------------------------
#define AAS 136
#define APS 72
#define A_Q   0
#define A_KV  (2 * 64 * AAS)                 // 17408
#define A_KVS (4 * 64 * AAS)                 // halves per stage = 34816
#define A_P   (A_KV + 2 * A_KVS)             // 87040
#define A_LP  (A_P + 2 * 64 * APS)           // 96256 halves
#define ATTN_SMEM_BYTES (A_LP * 2 + 512)

__global__ __launch_bounds__(256) void attn_kernel(
    const __nv_bfloat16* __restrict__ Qhg, const __nv_bfloat16* __restrict__ Qlg,
    const __nv_bfloat16* __restrict__ Khg, const __nv_bfloat16* __restrict__ Klg,
    const __nv_bfloat16* __restrict__ Vhg, const __nv_bfloat16* __restrict__ Vlg,
    float* __restrict__ AW, float* __restrict__ invLg,
    __nv_bfloat16* __restrict__ Ohg, __nv_bfloat16* __restrict__ Olg)
{
    extern __shared__ __nv_bfloat16 sm[];
    __nv_bfloat16* Qh = sm + A_Q;
    __nv_bfloat16* Ql = Qh + 64 * AAS;
    __nv_bfloat16* Ph = sm + A_P;
    __nv_bfloat16* Pl = Ph + 64 * APS;
    float* lp = (float*)(sm + A_LP);   // [2][64]

    const int tid = threadIdx.x;
    const int lane = tid & 31;
    const int wid = tid >> 5;
    const int wr = wid & 3;            // row group (16 rows)
    const int wc = wid >> 2;           // col half
    const int qt = blockIdx.x;         // 0..31
    const int bh = blockIdx.y;         // 0..31
    const int b = bh >> 4, h = bh & 15, kv = h >> 2;

    const size_t qrow0 = (size_t)b * T + qt * 64;
    const size_t krow0 = (size_t)b * T;
    const int kcol = kv * 128;

    auto load_kv = [&](int s, size_t row0) {
        __nv_bfloat16* base = sm + A_KV + s * A_KVS;
        #pragma unroll
        for (int i = 0; i < 4; i++) {
            int idx = i * 256 + tid;
            int r = idx >> 4, cg = (idx & 15) * 8;
            cp16(smem_u32(&base[r * AAS + cg]),              &Khg[(row0 + r) * KVDIM + kcol + cg]);
            cp16(smem_u32(&base[64*AAS + r * AAS + cg]),     &Klg[(row0 + r) * KVDIM + kcol + cg]);
            cp16(smem_u32(&base[2*64*AAS + r * AAS + cg]),   &Vhg[(row0 + r) * KVDIM + kcol + cg]);
            cp16(smem_u32(&base[3*64*AAS + r * AAS + cg]),   &Vlg[(row0 + r) * KVDIM + kcol + cg]);
        }
    };

    load_kv(0, krow0);
    CP_COMMIT();

    #pragma unroll
    for (int i = 0; i < 4; i++) {
        int idx = i * 256 + tid;
        int r = idx >> 4, cg = (idx & 15) * 8;
        *reinterpret_cast<uint4*>(&Qh[r * AAS + cg]) =
            *reinterpret_cast<const uint4*>(&Qhg[(qrow0 + r) * DIM + h * 128 + cg]);
        *reinterpret_cast<uint4*>(&Ql[r * AAS + cg]) =
            *reinterpret_cast<const uint4*>(&Qlg[(qrow0 + r) * DIM + h * 128 + cg]);
    }

    float l0 = 0.f, l1 = 0.f;
    float o[8][4] = {};

    const int r0 = wr * 16 + (lane >> 2);
    const int c0 = (lane & 3) * 2;

    #pragma unroll 1
    for (int kt = 0; kt < 32; kt++) {
        if (kt < 31) load_kv((kt + 1) & 1, krow0 + (kt + 1) * 64);
        CP_COMMIT();
        CP_WAIT1();
        __syncthreads();

        const __nv_bfloat16* Kbh = sm + A_KV + (kt & 1) * A_KVS;
        const __nv_bfloat16* Kbl = Kbh + 64 * AAS;
        const __nv_bfloat16* Vbh = Kbh + 2 * 64 * AAS;
        const __nv_bfloat16* Vbl = Kbh + 3 * 64 * AAS;

        // ---- S = Q K^T : warp -> rows wr*16..+15, cols wc*32..+31 ----
        float s[4][4];
        #pragma unroll
        for (int nt = 0; nt < 4; nt++)
            #pragma unroll
            for (int j = 0; j < 4; j++) s[nt][j] = 0.f;

        #pragma unroll
        for (int kk = 0; kk < 8; kk++) {
            uint32_t ah[4], al[4];
            int ar = wr * 16 + (lane & 15), ac = kk * 16 + (lane >> 4) * 8;
            ldsm_x4(ah, smem_u32(&Qh[ar * AAS + ac]));
            ldsm_x4(al, smem_u32(&Ql[ar * AAS + ac]));
            #pragma unroll
            for (int p = 0; p < 2; p++) {
                int br = wc * 32 + p * 16 + (lane & 15);
                int bc = kk * 16 + (lane >> 4) * 8;
                uint32_t b4h[4], b4l[4];
                ldsm_x4(b4h, smem_u32(&Kbh[br * AAS + bc]));
                ldsm_x4(b4l, smem_u32(&Kbl[br * AAS + bc]));
                uint32_t be_h[2] = {b4h[0], b4h[2]}, bo_h[2] = {b4h[1], b4h[3]};
                uint32_t be_l[2] = {b4l[0], b4l[2]}, bo_l[2] = {b4l[1], b4l[3]};
                mma16816(s[2*p],   ah, be_h); mma16816(s[2*p],   ah, be_l); mma16816(s[2*p],   al, be_h);
                mma16816(s[2*p+1], ah, bo_h); mma16816(s[2*p+1], ah, bo_l); mma16816(s[2*p+1], al, bo_h);
            }
        }

        // ---- e = exp(s): write raw to AW, accumulate l, split into P ----
        const size_t gb = ((size_t)bh * T + (size_t)qt * 64) * T;
        #pragma unroll
        for (int nt = 0; nt < 4; nt++) {
            float e00 = __expf(s[nt][0]), e01 = __expf(s[nt][1]);
            float e10 = __expf(s[nt][2]), e11 = __expf(s[nt][3]);
            int colL = wc * 32 + nt * 8 + c0;
            int col = kt * 64 + colL;
            *reinterpret_cast<float2*>(&AW[gb + (size_t)r0 * T + col]) = make_float2(e00, e01);
            *reinterpret_cast<float2*>(&AW[gb + (size_t)(r0 + 8) * T + col]) = make_float2(e10, e11);
            l0 += e00 + e01;
            l1 += e10 + e11;
            __nv_bfloat162 h0 = pack_hi(e00, e01), lo0 = pack_lo(e00, e01, h0);
            __nv_bfloat162 h1 = pack_hi(e10, e11), lo1 = pack_lo(e10, e11, h1);
            *reinterpret_cast<__nv_bfloat162*>(&Ph[r0 * APS + colL]) = h0;
            *reinterpret_cast<__nv_bfloat162*>(&Pl[r0 * APS + colL]) = lo0;
            *reinterpret_cast<__nv_bfloat162*>(&Ph[(r0 + 8) * APS + colL]) = h1;
            *reinterpret_cast<__nv_bfloat162*>(&Pl[(r0 + 8) * APS + colL]) = lo1;
        }
        __syncthreads();

        // ---- O += P V : warp -> rows wr*16..+15, cols wc*64..+63 ----
        #pragma unroll
        for (int kc = 0; kc < 4; kc++) {
            uint32_t ph4[4], pl4[4];
            int pr = wr * 16 + (lane & 15), pc = kc * 16 + (lane >> 4) * 8;
            ldsm_x4(ph4, smem_u32(&Ph[pr * APS + pc]));
            ldsm_x4(pl4, smem_u32(&Pl[pr * APS + pc]));
            #pragma unroll
            for (int p = 0; p < 4; p++) {
                int vr = kc * 16 + (lane & 15);
                int vc = wc * 64 + p * 16 + (lane >> 4) * 8;
                uint32_t v4h[4], v4l[4];
                ldsm_x4t(v4h, smem_u32(&Vbh[vr * AAS + vc]));
                ldsm_x4t(v4l, smem_u32(&Vbl[vr * AAS + vc]));
                uint32_t be_h[2] = {v4h[0], v4h[1]}, bo_h[2] = {v4h[2], v4h[3]};
                uint32_t be_l[2] = {v4l[0], v4l[1]}, bo_l[2] = {v4l[2], v4l[3]};
                mma16816(o[2*p],   ph4, be_h); mma16816(o[2*p],   ph4, be_l); mma16816(o[2*p],   pl4, be_h);
                mma16816(o[2*p+1], ph4, bo_h); mma16816(o[2*p+1], ph4, bo_l); mma16816(o[2*p+1], pl4, bo_h);
            }
        }
        __syncthreads();
    }

    // ---- row-sum reduction across quads + warp halves ----
    l0 += __shfl_xor_sync(0xffffffffu, l0, 1);
    l0 += __shfl_xor_sync(0xffffffffu, l0, 2);
    l1 += __shfl_xor_sync(0xffffffffu, l1, 1);
    l1 += __shfl_xor_sync(0xffffffffu, l1, 2);
    if ((lane & 3) == 0) {
        lp[wc * 64 + r0] = l0;
        lp[wc * 64 + r0 + 8] = l1;
    }
    __syncthreads();

    if (tid < 64) {
        float il = 1.f / (lp[tid] + lp[64 + tid]);
        invLg[(size_t)bh * T + qt * 64 + tid] = il;
    }

    const float ilA = 1.f / (lp[r0] + lp[64 + r0]);
    const float ilB = 1.f / (lp[r0 + 8] + lp[64 + r0 + 8]);

    // ---- write O (scaled, split) ----
    #pragma unroll
    for (int nt = 0; nt < 8; nt++) {
        int c = h * 128 + wc * 64 + nt * 8 + c0;
        float v00 = o[nt][0] * ilA, v01 = o[nt][1] * ilA;
        float v10 = o[nt][2] * ilB, v11 = o[nt][3] * ilB;
        __nv_bfloat162 h0 = pack_hi(v00, v01), l0v = pack_lo(v00, v01, h0);
        __nv_bfloat162 h1 = pack_hi(v10, v11), l1v = pack_lo(v10, v11, h1);
        *reinterpret_cast<__nv_bfloat162*>(&Ohg[(qrow0 + r0) * DIM + c]) = h0;
        *reinterpret_cast<__nv_bfloat162*>(&Olg[(qrow0 + r0) * DIM + c]) = l0v;
        *reinterpret_cast<__nv_bfloat162*>(&Ohg[(qrow0 + r0 + 8) * DIM + c]) = h1;
        *reinterpret_cast<__nv_bfloat162*>(&Olg[(qrow0 + r0 + 8) * DIM + c]) = l1v;
    }
}

// ---------------------------------------------------------------------------
// launch
// ---------------------------------------------------------------------------
extern "C" void kernel_launch(void* const* d_in, const int* in_sizes, int n_in,
                              void* d_out, int out_size)
{
    const float* q  = (const float*)d_in[0];
    const float* k  = (const float*)d_in[1];
    const float* v  = (const float*)d_in[2];
    const float* Wq = (const float*)d_in[3];
    const float* bq = (const float*)d_in[4];
    const float* Wk = (const float*)d_in[5];
    const float* bk = (const float*)d_in[6];
    const float* Wv = (const float*)d_in[7];
    const float* bv = (const float*)d_in[8];
    const float* Wo = (const float*)d_in[9];
    const float* bo = (const float*)d_in[10];

    float* out   = (float*)d_out;
    float* attnW = out + (size_t)BT * DIM;

    __nv_bfloat16 *qh, *ql, *kh, *kl, *vh, *vl;
    __nv_bfloat16 *Wqh, *Wql, *Wkh, *Wkl, *Wvh, *Wvl, *Woh, *Wol;
    __nv_bfloat16 *Qh, *Ql, *Kh, *Kl, *Vh, *Vl, *Oh, *Ol;
    float* invL;
    cudaGetSymbolAddress((void**)&qh, g_qh);   cudaGetSymbolAddress((void**)&ql, g_ql);
    cudaGetSymbolAddress((void**)&kh, g_kh);   cudaGetSymbolAddress((void**)&kl, g_kl);
    cudaGetSymbolAddress((void**)&vh, g_vh);   cudaGetSymbolAddress((void**)&vl, g_vl);
    cudaGetSymbolAddress((void**)&Wqh, g_Wqh); cudaGetSymbolAddress((void**)&Wql, g_Wql);
    cudaGetSymbolAddress((void**)&Wkh, g_Wkh); cudaGetSymbolAddress((void**)&Wkl, g_Wkl);
    cudaGetSymbolAddress((void**)&Wvh, g_Wvh); cudaGetSymbolAddress((void**)&Wvl, g_Wvl);
    cudaGetSymbolAddress((void**)&Woh, g_Woh); cudaGetSymbolAddress((void**)&Wol, g_Wol);
    cudaGetSymbolAddress((void**)&Qh, g_Qh);   cudaGetSymbolAddress((void**)&Ql, g_Ql);
    cudaGetSymbolAddress((void**)&Kh, g_Kh);   cudaGetSymbolAddress((void**)&Kl, g_Kl);
    cudaGetSymbolAddress((void**)&Vh, g_Vh);   cudaGetSymbolAddress((void**)&Vl, g_Vl);
    cudaGetSymbolAddress((void**)&Oh, g_Oh);   cudaGetSymbolAddress((void**)&Ol, g_Ol);
    cudaGetSymbolAddress((void**)&invL, g_invL);

    cudaFuncSetAttribute(gemm_bf16_kernel, cudaFuncAttributeMaxDynamicSharedMemorySize,
                         G_SMEM_BYTES);
    cudaFuncSetAttribute(attn_kernel, cudaFuncAttributeMaxDynamicSharedMemorySize,
                         ATTN_SMEM_BYTES);

    const float scale = 0.08838834764831845f;  // 1/sqrt(128)

    // splits (fp32 -> bf16 hi/lo)
    const int nBD = BT * DIM / 4, nDD = DIM * DIM / 4, nDK = DIM * KVDIM / 4;
    split_kernel<<<(nBD + 255) / 256, 256>>>(q, qh, ql, nBD);
    split_kernel<<<(nBD + 255) / 256, 256>>>(k, kh, kl, nBD);
    split_kernel<<<(nBD + 255) / 256, 256>>>(v, vh, vl, nBD);
    split_kernel<<<(nDD + 255) / 256, 256>>>(Wq, Wqh, Wql, nDD);
    split_kernel<<<(nDK + 255) / 256, 256>>>(Wk, Wkh, Wkl, nDK);
    split_kernel<<<(nDK + 255) / 256, 256>>>(Wv, Wvh, Wvl, nDK);
    split_kernel<<<(nDD + 255) / 256, 256>>>(Wo, Woh, Wol, nDD);

    // projections (split-bf16 epilogue; Q pre-scaled)
    gemm_bf16_kernel<<<dim3(DIM / 128, BT / 128), 256, G_SMEM_BYTES>>>(
        qh, ql, Wqh, Wql, bq, nullptr, Qh, Ql, scale, BT, DIM, DIM);
    gemm_bf16_kernel<<<dim3(KVDIM / 128, BT / 128), 256, G_SMEM_BYTES>>>(
        kh, kl, Wkh, Wkl, bk, nullptr, Kh, Kl, 1.f, BT, KVDIM, DIM);
    gemm_bf16_kernel<<<dim3(KVDIM / 128, BT / 128), 256, G_SMEM_BYTES>>>(
        vh, vl, Wvh, Wvl, bv, nullptr, Vh, Vl, 1.f, BT, KVDIM, DIM);

    // attention (raw exp -> AW, O pre-split & scaled)
    attn_kernel<<<dim3(T / 64, 32), 256, ATTN_SMEM_BYTES>>>(
        Qh, Ql, Kh, Kl, Vh, Vl, attnW, invL, Oh, Ol);

    // normalize attention weights: AW[row] *= invL[row]
    normalize_kernel<<<(int)(((size_t)32 * T * T / 4) / 256), 256>>>(attnW, invL);

    // output projection (fp32 epilogue)
    gemm_bf16_kernel<<<dim3(DIM / 128, BT / 128), 256, G_SMEM_BYTES>>>(
        Oh, Ol, Woh, Wol, bo, out, nullptr, nullptr, 1.f, BT, DIM, DIM);
}

// round 6
// speedup vs baseline: 1.6389x; 1.0062x over previous
#include <cuda_runtime.h>
#include <cuda_bf16.h>
#include <cstdint>
#include <cmath>

// ---------------------------------------------------------------------------
// GroupedQueryAttention: B=2, T=2048, DIM=2048, H=16, KH=4, DK=DV=128
// d_out = [ out (2,2048,2048) fp32 | attn_weight (2,16,2048,2048) fp32 ]
//
// Round 5: attention hot-loop stall removal (Q frags hoisted to regs, AW
// stores deferred past PV MMA, 2 syncs/tile), K+V projections merged into
// one launch, split kernels fused. Same split-bf16 3-term numerics.
// ---------------------------------------------------------------------------

#define BT 4096
#define DIM 2048
#define KVDIM 512
#define T 2048

// ---- device scratch (no allocation allowed) ----
__device__ __nv_bfloat16 g_qh[BT * DIM],  g_ql[BT * DIM];
__device__ __nv_bfloat16 g_kh[BT * DIM],  g_kl[BT * DIM];
__device__ __nv_bfloat16 g_vh[BT * DIM],  g_vl[BT * DIM];
__device__ __nv_bfloat16 g_Wqh[DIM * DIM], g_Wql[DIM * DIM];
__device__ __nv_bfloat16 g_Wkh[DIM * KVDIM], g_Wkl[DIM * KVDIM];
__device__ __nv_bfloat16 g_Wvh[DIM * KVDIM], g_Wvl[DIM * KVDIM];
__device__ __nv_bfloat16 g_Woh[DIM * DIM], g_Wol[DIM * DIM];
__device__ __nv_bfloat16 g_Qh[BT * DIM],  g_Ql[BT * DIM];
__device__ __nv_bfloat16 g_Kh[BT * KVDIM], g_Kl[BT * KVDIM];
__device__ __nv_bfloat16 g_Vh[BT * KVDIM], g_Vl[BT * KVDIM];
__device__ __nv_bfloat16 g_Oh[BT * DIM],  g_Ol[BT * DIM];
__device__ float g_invL[32 * T];

// ---------------------------------------------------------------------------
// helpers
// ---------------------------------------------------------------------------
__device__ __forceinline__ uint32_t smem_u32(const void* p) {
    return (uint32_t)__cvta_generic_to_shared(p);
}
__device__ __forceinline__ void ldsm_x4(uint32_t* r, uint32_t addr) {
    asm volatile("ldmatrix.sync.aligned.m8n8.x4.shared.b16 {%0,%1,%2,%3}, [%4];"
                 : "=r"(r[0]), "=r"(r[1]), "=r"(r[2]), "=r"(r[3]) : "r"(addr));
}
__device__ __forceinline__ void ldsm_x4t(uint32_t* r, uint32_t addr) {
    asm volatile("ldmatrix.sync.aligned.m8n8.x4.trans.shared.b16 {%0,%1,%2,%3}, [%4];"
                 : "=r"(r[0]), "=r"(r[1]), "=r"(r[2]), "=r"(r[3]) : "r"(addr));
}
__device__ __forceinline__ void mma16816(float* c, const uint32_t* a, const uint32_t* b) {
    asm volatile(
        "mma.sync.aligned.m16n8k16.row.col.f32.bf16.bf16.f32 "
        "{%0,%1,%2,%3}, {%4,%5,%6,%7}, {%8,%9}, {%0,%1,%2,%3};\n"
        : "+f"(c[0]), "+f"(c[1]), "+f"(c[2]), "+f"(c[3])
        : "r"(a[0]), "r"(a[1]), "r"(a[2]), "r"(a[3]), "r"(b[0]), "r"(b[1]));
}
__device__ __forceinline__ void cp16(uint32_t saddr, const void* g) {
    asm volatile("cp.async.cg.shared.global [%0], [%1], 16;" :: "r"(saddr), "l"(g));
}
#define CP_COMMIT() asm volatile("cp.async.commit_group;")
#define CP_WAIT1()  asm volatile("cp.async.wait_group 1;")
#define CP_WAIT0()  asm volatile("cp.async.wait_group 0;")

__device__ __forceinline__ __nv_bfloat162 pack_hi(float a, float b) {
    __nv_bfloat162 r; r.x = __float2bfloat16(a); r.y = __float2bfloat16(b); return r;
}
__device__ __forceinline__ __nv_bfloat162 pack_lo(float a, float b, __nv_bfloat162 h) {
    __nv_bfloat162 r;
    r.x = __float2bfloat16(a - __bfloat162float(h.x));
    r.y = __float2bfloat16(b - __bfloat162float(h.y));
    return r;
}

// ---------------------------------------------------------------------------
// split: fp32 -> bf16 hi/lo; blockIdx.y selects one of up to 3 tensors
// ---------------------------------------------------------------------------
__global__ void split3_kernel(
    const float* __restrict__ s0, __nv_bfloat16* __restrict__ h0, __nv_bfloat16* __restrict__ l0,
    const float* __restrict__ s1, __nv_bfloat16* __restrict__ h1, __nv_bfloat16* __restrict__ l1,
    const float* __restrict__ s2, __nv_bfloat16* __restrict__ h2, __nv_bfloat16* __restrict__ l2,
    int n4)
{
    int i = blockIdx.x * blockDim.x + threadIdx.x;
    if (i >= n4) return;
    const float* src; __nv_bfloat16 *h, *l;
    if (blockIdx.y == 0)      { src = s0; h = h0; l = l0; }
    else if (blockIdx.y == 1) { src = s1; h = h1; l = l1; }
    else                      { src = s2; h = h2; l = l2; }
    float4 v = reinterpret_cast<const float4*>(src)[i];
    __nv_bfloat162 ha = pack_hi(v.x, v.y), hb = pack_hi(v.z, v.w);
    __nv_bfloat162 la = pack_lo(v.x, v.y, ha), lb = pack_lo(v.z, v.w, hb);
    uint2 hv = make_uint2(*(uint32_t*)&ha, *(uint32_t*)&hb);
    uint2 lv = make_uint2(*(uint32_t*)&la, *(uint32_t*)&lb);
    *reinterpret_cast<uint2*>(&h[(size_t)i * 4]) = hv;
    *reinterpret_cast<uint2*>(&l[(size_t)i * 4]) = lv;
}

// ---------------------------------------------------------------------------
// normalize: AW[row][*] *= invL[row]
// ---------------------------------------------------------------------------
__global__ void normalize_kernel(float* __restrict__ AW, const float* __restrict__ invL)
{
    size_t i4 = (size_t)blockIdx.x * blockDim.x + threadIdx.x;
    int row = (int)((i4 * 4) >> 11);
    float il = __ldg(&invL[row]);
    float4 v = reinterpret_cast<float4*>(AW)[i4];
    v.x *= il; v.y *= il; v.z *= il; v.w *= il;
    reinterpret_cast<float4*>(AW)[i4] = v;
}

// ---------------------------------------------------------------------------
// GEMM body: C[M,N] = (A[M,K] @ W[K,N] + bias) * scale, pre-split operands.
// BM=128 BN=128 BK=32, 256 threads, cp.async double-buffered, 3-term MMA.
// ---------------------------------------------------------------------------
#define GAS 40
#define GBS 136
#define G_STG (128 * GAS * 2 + 32 * GBS * 2)
#define G_SMEM_BYTES (2 * G_STG * 2 + 512)

__device__ __forceinline__ void gemm_body(
    const __nv_bfloat16* __restrict__ Ahg, const __nv_bfloat16* __restrict__ Alg,
    const __nv_bfloat16* __restrict__ Bhg, const __nv_bfloat16* __restrict__ Blg,
    const float* __restrict__ bias,
    float* __restrict__ Cf, __nv_bfloat16* __restrict__ Ch, __nv_bfloat16* __restrict__ Cl,
    float scale, int N, int K, int bm0, int bn0, __nv_bfloat16* sm)
{
    float* biasS = (float*)(sm + 2 * G_STG);

    const int tid = threadIdx.x;
    const int lane = tid & 31;
    const int wid = tid >> 5;
    const int wm = wid >> 2;
    const int wn = wid & 3;

    if (tid < 128) biasS[tid] = bias[bn0 + tid];

    auto load_stage = [&](int s, int kt) {
        __nv_bfloat16* sAh = sm + s * G_STG;
        __nv_bfloat16* sAl = sAh + 128 * GAS;
        __nv_bfloat16* sBh = sAl + 128 * GAS;
        __nv_bfloat16* sBl = sBh + 32 * GBS;
        #pragma unroll
        for (int i = 0; i < 2; i++) {
            int idx = i * 256 + tid;
            int r = idx >> 2, cg = (idx & 3) * 8;
            cp16(smem_u32(&sAh[r * GAS + cg]), &Ahg[(size_t)(bm0 + r) * K + kt + cg]);
            cp16(smem_u32(&sAl[r * GAS + cg]), &Alg[(size_t)(bm0 + r) * K + kt + cg]);
        }
        #pragma unroll
        for (int i = 0; i < 2; i++) {
            int idx = i * 256 + tid;
            int r = idx >> 4, cg = (idx & 15) * 8;
            cp16(smem_u32(&sBh[r * GBS + cg]), &Bhg[(size_t)(kt + r) * N + bn0 + cg]);
            cp16(smem_u32(&sBl[r * GBS + cg]), &Blg[(size_t)(kt + r) * N + bn0 + cg]);
        }
    };

    float acc[4][4][4] = {};
    const int nk = K >> 5;

    load_stage(0, 0);
    CP_COMMIT();

    for (int it = 0; it < nk; it++) {
        if (it + 1 < nk) load_stage((it + 1) & 1, (it + 1) * 32);
        CP_COMMIT();
        CP_WAIT1();
        __syncthreads();

        const __nv_bfloat16* sAh = sm + (it & 1) * G_STG;
        const __nv_bfloat16* sAl = sAh + 128 * GAS;
        const __nv_bfloat16* sBh = sAl + 128 * GAS;
        const __nv_bfloat16* sBl = sBh + 32 * GBS;

        #pragma unroll
        for (int ks = 0; ks < 2; ks++) {
            uint32_t ah[4][4], al[4][4];
            #pragma unroll
            for (int mt = 0; mt < 4; mt++) {
                int r = wm * 64 + mt * 16 + (lane & 15);
                int c = ks * 16 + (lane >> 4) * 8;
                ldsm_x4(ah[mt], smem_u32(&sAh[r * GAS + c]));
                ldsm_x4(al[mt], smem_u32(&sAl[r * GAS + c]));
            }
            uint32_t bh[4][2], bl[4][2];
            #pragma unroll
            for (int p = 0; p < 2; p++) {
                int r = ks * 16 + (lane & 15);
                int c = wn * 32 + p * 16 + (lane >> 4) * 8;
                uint32_t t4[4];
                ldsm_x4t(t4, smem_u32(&sBh[r * GBS + c]));
                bh[2*p][0] = t4[0]; bh[2*p][1] = t4[1];
                bh[2*p+1][0] = t4[2]; bh[2*p+1][1] = t4[3];
                ldsm_x4t(t4, smem_u32(&sBl[r * GBS + c]));
                bl[2*p][0] = t4[0]; bl[2*p][1] = t4[1];
                bl[2*p+1][0] = t4[2]; bl[2*p+1][1] = t4[3];
            }
            #pragma unroll
            for (int mt = 0; mt < 4; mt++)
                #pragma unroll
                for (int nt = 0; nt < 4; nt++) {
                    mma16816(acc[mt][nt], ah[mt], bh[nt]);
                    mma16816(acc[mt][nt], ah[mt], bl[nt]);
                    mma16816(acc[mt][nt], al[mt], bh[nt]);
                }
        }
        __syncthreads();
    }

    #pragma unroll
    for (int mt = 0; mt < 4; mt++)
        #pragma unroll
        for (int nt = 0; nt < 4; nt++) {
            int row = bm0 + wm * 64 + mt * 16 + (lane >> 2);
            int colL = wn * 32 + nt * 8 + (lane & 3) * 2;
            int col = bn0 + colL;
            float b0 = biasS[colL], b1 = biasS[colL + 1];
            float v00 = (acc[mt][nt][0] + b0) * scale;
            float v01 = (acc[mt][nt][1] + b1) * scale;
            float v10 = (acc[mt][nt][2] + b0) * scale;
            float v11 = (acc[mt][nt][3] + b1) * scale;
            if (Cf) {
                *reinterpret_cast<float2*>(&Cf[(size_t)row * N + col]) = make_float2(v00, v01);
                *reinterpret_cast<float2*>(&Cf[(size_t)(row + 8) * N + col]) = make_float2(v10, v11);
            } else {
                __nv_bfloat162 h0 = pack_hi(v00, v01), l0 = pack_lo(v00, v01, h0);
                *reinterpret_cast<__nv_bfloat162*>(&Ch[(size_t)row * N + col]) = h0;
                *reinterpret_cast<__nv_bfloat162*>(&Cl[(size_t)row * N + col]) = l0;
                __nv_bfloat162 h1 = pack_hi(v10, v11), l1 = pack_lo(v10, v11, h1);
                *reinterpret_cast<__nv_bfloat162*>(&Ch[(size_t)(row + 8) * N + col]) = h1;
                *reinterpret_cast<__nv_bfloat162*>(&Cl[(size_t)(row + 8) * N + col]) = l1;
            }
        }
}

__global__ __launch_bounds__(256) void gemm_bf16_kernel(
    const __nv_bfloat16* __restrict__ Ahg, const __nv_bfloat16* __restrict__ Alg,
    const __nv_bfloat16* __restrict__ Bhg, const __nv_bfloat16* __restrict__ Blg,
    const float* __restrict__ bias,
    float* __restrict__ Cf, __nv_bfloat16* __restrict__ Ch, __nv_bfloat16* __restrict__ Cl,
    float scale, int N, int K)
{
    extern __shared__ __nv_bfloat16 sm[];
    gemm_body(Ahg, Alg, Bhg, Blg, bias, Cf, Ch, Cl, scale, N, K,
              blockIdx.y * 128, blockIdx.x * 128, sm);
}

// K-proj and V-proj fused into one launch: blockIdx.x<4 -> K, else V.
__global__ __launch_bounds__(256) void gemm_kv_kernel(
    const __nv_bfloat16* __restrict__ kAh, const __nv_bfloat16* __restrict__ kAl,
    const __nv_bfloat16* __restrict__ kBh, const __nv_bfloat16* __restrict__ kBl,
    const float* __restrict__ kbias,
    __nv_bfloat16* __restrict__ kCh, __nv_bfloat16* __restrict__ kCl,
    const __nv_bfloat16* __restrict__ vAh, const __nv_bfloat16* __restrict__ vAl,
    const __nv_bfloat16* __restrict__ vBh, const __nv_bfloat16* __restrict__ vBl,
    const float* __restrict__ vbias,
    __nv_bfloat16* __restrict__ vCh, __nv_bfloat16* __restrict__ vCl)
{
    extern __shared__ __nv_bfloat16 sm[];
    if (blockIdx.x < 4)
        gemm_body(kAh, kAl, kBh, kBl, kbias, nullptr, kCh, kCl, 1.f, KVDIM, DIM,
                  blockIdx.y * 128, blockIdx.x * 128, sm);
    else
        gemm_body(vAh, vAl, vBh, vBl, vbias, nullptr, vCh, vCl, 1.f, KVDIM, DIM,
                  blockIdx.y * 128, (blockIdx.x - 4) * 128, sm);
}

// ---------------------------------------------------------------------------
// Attention (single pass): grid (32 qtiles x 32 bh), 256 threads (8 warps 4x2).
// Q fragments hoisted to registers. 2 syncs/tile. AW stores deferred past PV.
// ---------------------------------------------------------------------------
#define AAS 136
#define APS 72
#define A_Q   0
#define A_KV  (2 * 64 * AAS)
#define A_KVS (4 * 64 * AAS)
#define A_P   (A_KV + 2 * A_KVS)
#define A_LP  (A_P + 2 * 64 * APS)
#define ATTN_SMEM_BYTES (A_LP * 2 + 512)

__global__ __launch_bounds__(256) void attn_kernel(
    const __nv_bfloat16* __restrict__ Qhg, const __nv_bfloat16* __restrict__ Qlg,
    const __nv_bfloat16* __restrict__ Khg, const __nv_bfloat16* __restrict__ Klg,
    const __nv_bfloat16* __restrict__ Vhg, const __nv_bfloat16* __restrict__ Vlg,
    float* __restrict__ AW, float* __restrict__ invLg,
    __nv_bfloat16* __restrict__ Ohg, __nv_bfloat16* __restrict__ Olg)
{
    extern __shared__ __nv_bfloat16 sm[];
    __nv_bfloat16* Qh = sm + A_Q;
    __nv_bfloat16* Ql = Qh + 64 * AAS;
    __nv_bfloat16* Ph = sm + A_P;
    __nv_bfloat16* Pl = Ph + 64 * APS;
    float* lp = (float*)(sm + A_LP);

    const int tid = threadIdx.x;
    const int lane = tid & 31;
    const int wid = tid >> 5;
    const int wr = wid & 3;
    const int wc = wid >> 2;
    const int qt = blockIdx.x;
    const int bh = blockIdx.y;
    const int b = bh >> 4, h = bh & 15, kv = h >> 2;

    const size_t qrow0 = (size_t)b * T + qt * 64;
    const size_t krow0 = (size_t)b * T;
    const int kcol = kv * 128;

    auto load_kv = [&](int s, size_t row0) {
        __nv_bfloat16* base = sm + A_KV + s * A_KVS;
        #pragma unroll
        for (int i = 0; i < 4; i++) {
            int idx = i * 256 + tid;
            int r = idx >> 4, cg = (idx & 15) * 8;
            cp16(smem_u32(&base[r * AAS + cg]),            &Khg[(row0 + r) * KVDIM + kcol + cg]);
            cp16(smem_u32(&base[64*AAS + r * AAS + cg]),   &Klg[(row0 + r) * KVDIM + kcol + cg]);
            cp16(smem_u32(&base[2*64*AAS + r * AAS + cg]), &Vhg[(row0 + r) * KVDIM + kcol + cg]);
            cp16(smem_u32(&base[3*64*AAS + r * AAS + cg]), &Vlg[(row0 + r) * KVDIM + kcol + cg]);
        }
    };

    // prologue: KV tile 0 async + Q to smem
    load_kv(0, krow0);
    CP_COMMIT();
    #pragma unroll
    for (int i = 0; i < 4; i++) {
        int idx = i * 256 + tid;
        int r = idx >> 4, cg = (idx & 15) * 8;
        *reinterpret_cast<uint4*>(&Qh[r * AAS + cg]) =
            *reinterpret_cast<const uint4*>(&Qhg[(qrow0 + r) * DIM + h * 128 + cg]);
        *reinterpret_cast<uint4*>(&Ql[r * AAS + cg]) =
            *reinterpret_cast<const uint4*>(&Qlg[(qrow0 + r) * DIM + h * 128 + cg]);
    }
    __syncthreads();

    // hoist Q fragments (rows wr*16..+15, all 128 cols, hi+lo)
    uint32_t aF[8][4], aFl[8][4];
    {
        int ar = wr * 16 + (lane & 15);
        #pragma unroll
        for (int kk = 0; kk < 8; kk++) {
            int ac = kk * 16 + (lane >> 4) * 8;
            ldsm_x4(aF[kk],  smem_u32(&Qh[ar * AAS + ac]));
            ldsm_x4(aFl[kk], smem_u32(&Ql[ar * AAS + ac]));
        }
    }

    float l0 = 0.f, l1 = 0.f;
    float o[8][4] = {};

    const int r0 = wr * 16 + (lane >> 2);
    const int c0 = (lane & 3) * 2;
    const size_t gb = ((size_t)bh * T + (size_t)qt * 64) * T;

    #pragma unroll 1
    for (int kt = 0; kt < 32; kt++) {
        CP_WAIT0();
        __syncthreads();
        if (kt < 31) {
            load_kv((kt + 1) & 1, krow0 + (kt + 1) * 64);
            CP_COMMIT();
        }

        const __nv_bfloat16* Kbh = sm + A_KV + (kt & 1) * A_KVS;
        const __nv_bfloat16* Kbl = Kbh + 64 * AAS;
        const __nv_bfloat16* Vbh = Kbh + 2 * 64 * AAS;
        const __nv_bfloat16* Vbl = Kbh + 3 * 64 * AAS;

        // ---- S = Q K^T ----
        float s[4][4];
        #pragma unroll
        for (int nt = 0; nt < 4; nt++)
            #pragma unroll
            for (int j = 0; j < 4; j++) s[nt][j] = 0.f;

        #pragma unroll
        for (int kk = 0; kk < 8; kk++) {
            #pragma unroll
            for (int p = 0; p < 2; p++) {
                int br = wc * 32 + p * 16 + (lane & 15);
                int bc = kk * 16 + (lane >> 4) * 8;
                uint32_t b4h[4], b4l[4];
                ldsm_x4(b4h, smem_u32(&Kbh[br * AAS + bc]));
                ldsm_x4(b4l, smem_u32(&Kbl[br * AAS + bc]));
                uint32_t be_h[2] = {b4h[0], b4h[2]}, bo_h[2] = {b4h[1], b4h[3]};
                uint32_t be_l[2] = {b4l[0], b4l[2]}, bo_l[2] = {b4l[1], b4l[3]};
                mma16816(s[2*p],   aF[kk], be_h); mma16816(s[2*p],   aF[kk], be_l);
                mma16816(s[2*p],   aFl[kk], be_h);
                mma16816(s[2*p+1], aF[kk], bo_h); mma16816(s[2*p+1], aF[kk], bo_l);
                mma16816(s[2*p+1], aFl[kk], bo_h);
            }
        }

        // ---- e = exp(s) in regs, split into P smem ----
        #pragma unroll
        for (int nt = 0; nt < 4; nt++) {
            s[nt][0] = __expf(s[nt][0]); s[nt][1] = __expf(s[nt][1]);
            s[nt][2] = __expf(s[nt][2]); s[nt][3] = __expf(s[nt][3]);
            l0 += s[nt][0] + s[nt][1];
            l1 += s[nt][2] + s[nt][3];
            int colL = wc * 32 + nt * 8 + c0;
            __nv_bfloat162 h0 = pack_hi(s[nt][0], s[nt][1]), lo0 = pack_lo(s[nt][0], s[nt][1], h0);
            __nv_bfloat162 h1 = pack_hi(s[nt][2], s[nt][3]), lo1 = pack_lo(s[nt][2], s[nt][3], h1);
            *reinterpret_cast<__nv_bfloat162*>(&Ph[r0 * APS + colL]) = h0;
            *reinterpret_cast<__nv_bfloat162*>(&Pl[r0 * APS + colL]) = lo0;
            *reinterpret_cast<__nv_bfloat162*>(&Ph[(r0 + 8) * APS + colL]) = h1;
            *reinterpret_cast<__nv_bfloat162*>(&Pl[(r0 + 8) * APS + colL]) = lo1;
        }
        __syncthreads();

        // ---- O += P V ----
        #pragma unroll
        for (int kc = 0; kc < 4; kc++) {
            uint32_t ph4[4], pl4[4];
            int pr = wr * 16 + (lane & 15), pc = kc * 16 + (lane >> 4) * 8;
            ldsm_x4(ph4, smem_u32(&Ph[pr * APS + pc]));
            ldsm_x4(pl4, smem_u32(&Pl[pr * APS + pc]));
            #pragma unroll
            for (int p = 0; p < 4; p++) {
                int vr = kc * 16 + (lane & 15);
                int vc = wc * 64 + p * 16 + (lane >> 4) * 8;
                uint32_t v4h[4], v4l[4];
                ldsm_x4t(v4h, smem_u32(&Vbh[vr * AAS + vc]));
                ldsm_x4t(v4l, smem_u32(&Vbl[vr * AAS + vc]));
                uint32_t be_h[2] = {v4h[0], v4h[1]}, bo_h[2] = {v4h[2], v4h[3]};
                uint32_t be_l[2] = {v4l[0], v4l[1]}, bo_l[2] = {v4l[2], v4l[3]};
                mma16816(o[2*p],   ph4, be_h); mma16816(o[2*p],   ph4, be_l); mma16816(o[2*p],   pl4, be_h);
                mma16816(o[2*p+1], ph4, bo_h); mma16816(o[2*p+1], ph4, bo_l); mma16816(o[2*p+1], pl4, bo_h);
            }
        }

        // ---- deferred AW stores (raw exp) — overlap tensor-pipe drain ----
        #pragma unroll
        for (int nt = 0; nt < 4; nt++) {
            int col = kt * 64 + wc * 32 + nt * 8 + c0;
            *reinterpret_cast<float2*>(&AW[gb + (size_t)r0 * T + col]) =
                make_float2(s[nt][0], s[nt][1]);
            *reinterpret_cast<float2*>(&AW[gb + (size_t)(r0 + 8) * T + col]) =
                make_float2(s[nt][2], s[nt][3]);
        }
    }

    // ---- row-sum reduction ----
    l0 += __shfl_xor_sync(0xffffffffu, l0, 1);
    l0 += __shfl_xor_sync(0xffffffffu, l0, 2);
    l1 += __shfl_xor_sync(0xffffffffu, l1, 1);
    l1 += __shfl_xor_sync(0xffffffffu, l1, 2);
    __syncthreads();
    if ((lane & 3) == 0) {
        lp[wc * 64 + r0] = l0;
        lp[wc * 64 + r0 + 8] = l1;
    }
    __syncthreads();

    if (tid < 64) {
        float il = 1.f / (lp[tid] + lp[64 + tid]);
        invLg[(size_t)bh * T + qt * 64 + tid] = il;
    }

    const float ilA = 1.f / (lp[r0] + lp[64 + r0]);
    const float ilB = 1.f / (lp[r0 + 8] + lp[64 + r0 + 8]);

    // ---- write O (scaled, split) ----
    #pragma unroll
    for (int nt = 0; nt < 8; nt++) {
        int c = h * 128 + wc * 64 + nt * 8 + c0;
        float v00 = o[nt][0] * ilA, v01 = o[nt][1] * ilA;
        float v10 = o[nt][2] * ilB, v11 = o[nt][3] * ilB;
        __nv_bfloat162 h0 = pack_hi(v00, v01), l0v = pack_lo(v00, v01, h0);
        __nv_bfloat162 h1 = pack_hi(v10, v11), l1v = pack_lo(v10, v11, h1);
        *reinterpret_cast<__nv_bfloat162*>(&Ohg[(qrow0 + r0) * DIM + c]) = h0;
        *reinterpret_cast<__nv_bfloat162*>(&Olg[(qrow0 + r0) * DIM + c]) = l0v;
        *reinterpret_cast<__nv_bfloat162*>(&Ohg[(qrow0 + r0 + 8) * DIM + c]) = h1;
        *reinterpret_cast<__nv_bfloat162*>(&Olg[(qrow0 + r0 + 8) * DIM + c]) = l1v;
    }
}

// ---------------------------------------------------------------------------
// launch
// ---------------------------------------------------------------------------
extern "C" void kernel_launch(void* const* d_in, const int* in_sizes, int n_in,
                              void* d_out, int out_size)
{
    const float* q  = (const float*)d_in[0];
    const float* k  = (const float*)d_in[1];
    const float* v  = (const float*)d_in[2];
    const float* Wq = (const float*)d_in[3];
    const float* bq = (const float*)d_in[4];
    const float* Wk = (const float*)d_in[5];
    const float* bk = (const float*)d_in[6];
    const float* Wv = (const float*)d_in[7];
    const float* bv = (const float*)d_in[8];
    const float* Wo = (const float*)d_in[9];
    const float* bo = (const float*)d_in[10];

    float* out   = (float*)d_out;
    float* attnW = out + (size_t)BT * DIM;

    __nv_bfloat16 *qh, *ql, *kh, *kl, *vh, *vl;
    __nv_bfloat16 *Wqh, *Wql, *Wkh, *Wkl, *Wvh, *Wvl, *Woh, *Wol;
    __nv_bfloat16 *Qh, *Ql, *Kh, *Kl, *Vh, *Vl, *Oh, *Ol;
    float* invL;
    cudaGetSymbolAddress((void**)&qh, g_qh);   cudaGetSymbolAddress((void**)&ql, g_ql);
    cudaGetSymbolAddress((void**)&kh, g_kh);   cudaGetSymbolAddress((void**)&kl, g_kl);
    cudaGetSymbolAddress((void**)&vh, g_vh);   cudaGetSymbolAddress((void**)&vl, g_vl);
    cudaGetSymbolAddress((void**)&Wqh, g_Wqh); cudaGetSymbolAddress((void**)&Wql, g_Wql);
    cudaGetSymbolAddress((void**)&Wkh, g_Wkh); cudaGetSymbolAddress((void**)&Wkl, g_Wkl);
    cudaGetSymbolAddress((void**)&Wvh, g_Wvh); cudaGetSymbolAddress((void**)&Wvl, g_Wvl);
    cudaGetSymbolAddress((void**)&Woh, g_Woh); cudaGetSymbolAddress((void**)&Wol, g_Wol);
    cudaGetSymbolAddress((void**)&Qh, g_Qh);   cudaGetSymbolAddress((void**)&Ql, g_Ql);
    cudaGetSymbolAddress((void**)&Kh, g_Kh);   cudaGetSymbolAddress((void**)&Kl, g_Kl);
    cudaGetSymbolAddress((void**)&Vh, g_Vh);   cudaGetSymbolAddress((void**)&Vl, g_Vl);
    cudaGetSymbolAddress((void**)&Oh, g_Oh);   cudaGetSymbolAddress((void**)&Ol, g_Ol);
    cudaGetSymbolAddress((void**)&invL, g_invL);

    cudaFuncSetAttribute(gemm_bf16_kernel, cudaFuncAttributeMaxDynamicSharedMemorySize,
                         G_SMEM_BYTES);
    cudaFuncSetAttribute(gemm_kv_kernel, cudaFuncAttributeMaxDynamicSharedMemorySize,
                         G_SMEM_BYTES);
    cudaFuncSetAttribute(attn_kernel, cudaFuncAttributeMaxDynamicSharedMemorySize,
                         ATTN_SMEM_BYTES);

    const float scale = 0.08838834764831845f;  // 1/sqrt(128)

    // splits (fp32 -> bf16 hi/lo): 3 fused launches
    const int nBD = BT * DIM / 4, nDD = DIM * DIM / 4, nDK = DIM * KVDIM / 4;
    split3_kernel<<<dim3((nBD + 255) / 256, 3), 256>>>(
        q, qh, ql, k, kh, kl, v, vh, vl, nBD);
    split3_kernel<<<dim3((nDD + 255) / 256, 2), 256>>>(
        Wq, Wqh, Wql, Wo, Woh, Wol, nullptr, nullptr, nullptr, nDD);
    split3_kernel<<<dim3((nDK + 255) / 256, 2), 256>>>(
        Wk, Wkh, Wkl, Wv, Wvh, Wvl, nullptr, nullptr, nullptr, nDK);

    // Q projection (pre-scaled) + fused K/V projections
    gemm_bf16_kernel<<<dim3(DIM / 128, BT / 128), 256, G_SMEM_BYTES>>>(
        qh, ql, Wqh, Wql, bq, nullptr, Qh, Ql, scale, DIM, DIM);
    gemm_kv_kernel<<<dim3(2 * KVDIM / 128, BT / 128), 256, G_SMEM_BYTES>>>(
        kh, kl, Wkh, Wkl, bk, Kh, Kl,
        vh, vl, Wvh, Wvl, bv, Vh, Vl);

    // attention (raw exp -> AW, O pre-split & scaled)
    attn_kernel<<<dim3(T / 64, 32), 256, ATTN_SMEM_BYTES>>>(
        Qh, Ql, Kh, Kl, Vh, Vl, attnW, invL, Oh, Ol);

    // normalize attention weights
    normalize_kernel<<<(int)(((size_t)32 * T * T / 4) / 256), 256>>>(attnW, invL);

    // output projection (fp32 epilogue)
    gemm_bf16_kernel<<<dim3(DIM / 128, BT / 128), 256, G_SMEM_BYTES>>>(
        Oh, Ol, Woh, Wol, bo, out, nullptr, nullptr, 1.f, DIM, DIM);
}

// round 7
// speedup vs baseline: 1.6776x; 1.0236x over previous
#include <cuda_runtime.h>
#include <cuda_bf16.h>
#include <cstdint>
#include <cmath>

// ---------------------------------------------------------------------------
// GroupedQueryAttention: B=2, T=2048, DIM=2048, H=16, KH=4, DK=DV=128
// d_out = [ out (2,2048,2048) fp32 | attn_weight (2,16,2048,2048) fp32 ]
//
// Round 6: attention smem cut to 115.2KB (32-key double-buffered tiles,
// Q back in smem, no reg hoist) => 2 CTAs/SM, launch_bounds(256,2).
// GEMM path unchanged from round 5. Split-bf16 3-term numerics everywhere.
// ---------------------------------------------------------------------------

#define BT 4096
#define DIM 2048
#define KVDIM 512
#define T 2048

// ---- device scratch (no allocation allowed) ----
__device__ __nv_bfloat16 g_qh[BT * DIM],  g_ql[BT * DIM];
__device__ __nv_bfloat16 g_kh[BT * DIM],  g_kl[BT * DIM];
__device__ __nv_bfloat16 g_vh[BT * DIM],  g_vl[BT * DIM];
__device__ __nv_bfloat16 g_Wqh[DIM * DIM], g_Wql[DIM * DIM];
__device__ __nv_bfloat16 g_Wkh[DIM * KVDIM], g_Wkl[DIM * KVDIM];
__device__ __nv_bfloat16 g_Wvh[DIM * KVDIM], g_Wvl[DIM * KVDIM];
__device__ __nv_bfloat16 g_Woh[DIM * DIM], g_Wol[DIM * DIM];
__device__ __nv_bfloat16 g_Qh[BT * DIM],  g_Ql[BT * DIM];
__device__ __nv_bfloat16 g_Kh[BT * KVDIM], g_Kl[BT * KVDIM];
__device__ __nv_bfloat16 g_Vh[BT * KVDIM], g_Vl[BT * KVDIM];
__device__ __nv_bfloat16 g_Oh[BT * DIM],  g_Ol[BT * DIM];
__device__ float g_invL[32 * T];

// ---------------------------------------------------------------------------
// helpers
// ---------------------------------------------------------------------------
__device__ __forceinline__ uint32_t smem_u32(const void* p) {
    return (uint32_t)__cvta_generic_to_shared(p);
}
__device__ __forceinline__ void ldsm_x4(uint32_t* r, uint32_t addr) {
    asm volatile("ldmatrix.sync.aligned.m8n8.x4.shared.b16 {%0,%1,%2,%3}, [%4];"
                 : "=r"(r[0]), "=r"(r[1]), "=r"(r[2]), "=r"(r[3]) : "r"(addr));
}
__device__ __forceinline__ void ldsm_x4t(uint32_t* r, uint32_t addr) {
    asm volatile("ldmatrix.sync.aligned.m8n8.x4.trans.shared.b16 {%0,%1,%2,%3}, [%4];"
                 : "=r"(r[0]), "=r"(r[1]), "=r"(r[2]), "=r"(r[3]) : "r"(addr));
}
__device__ __forceinline__ void mma16816(float* c, const uint32_t* a, const uint32_t* b) {
    asm volatile(
        "mma.sync.aligned.m16n8k16.row.col.f32.bf16.bf16.f32 "
        "{%0,%1,%2,%3}, {%4,%5,%6,%7}, {%8,%9}, {%0,%1,%2,%3};\n"
        : "+f"(c[0]), "+f"(c[1]), "+f"(c[2]), "+f"(c[3])
        : "r"(a[0]), "r"(a[1]), "r"(a[2]), "r"(a[3]), "r"(b[0]), "r"(b[1]));
}
__device__ __forceinline__ void cp16(uint32_t saddr, const void* g) {
    asm volatile("cp.async.cg.shared.global [%0], [%1], 16;" :: "r"(saddr), "l"(g));
}
#define CP_COMMIT() asm volatile("cp.async.commit_group;")
#define CP_WAIT1()  asm volatile("cp.async.wait_group 1;")
#define CP_WAIT0()  asm volatile("cp.async.wait_group 0;")

__device__ __forceinline__ __nv_bfloat162 pack_hi(float a, float b) {
    __nv_bfloat162 r; r.x = __float2bfloat16(a); r.y = __float2bfloat16(b); return r;
}
__device__ __forceinline__ __nv_bfloat162 pack_lo(float a, float b, __nv_bfloat162 h) {
    __nv_bfloat162 r;
    r.x = __float2bfloat16(a - __bfloat162float(h.x));
    r.y = __float2bfloat16(b - __bfloat162float(h.y));
    return r;
}

// ---------------------------------------------------------------------------
// split: fp32 -> bf16 hi/lo; blockIdx.y selects one of up to 3 tensors
// ---------------------------------------------------------------------------
__global__ void split3_kernel(
    const float* __restrict__ s0, __nv_bfloat16* __restrict__ h0, __nv_bfloat16* __restrict__ l0,
    const float* __restrict__ s1, __nv_bfloat16* __restrict__ h1, __nv_bfloat16* __restrict__ l1,
    const float* __restrict__ s2, __nv_bfloat16* __restrict__ h2, __nv_bfloat16* __restrict__ l2,
    int n4)
{
    int i = blockIdx.x * blockDim.x + threadIdx.x;
    if (i >= n4) return;
    const float* src; __nv_bfloat16 *h, *l;
    if (blockIdx.y == 0)      { src = s0; h = h0; l = l0; }
    else if (blockIdx.y == 1) { src = s1; h = h1; l = l1; }
    else                      { src = s2; h = h2; l = l2; }
    float4 v = reinterpret_cast<const float4*>(src)[i];
    __nv_bfloat162 ha = pack_hi(v.x, v.y), hb = pack_hi(v.z, v.w);
    __nv_bfloat162 la = pack_lo(v.x, v.y, ha), lb = pack_lo(v.z, v.w, hb);
    uint2 hv = make_uint2(*(uint32_t*)&ha, *(uint32_t*)&hb);
    uint2 lv = make_uint2(*(uint32_t*)&la, *(uint32_t*)&lb);
    *reinterpret_cast<uint2*>(&h[(size_t)i * 4]) = hv;
    *reinterpret_cast<uint2*>(&l[(size_t)i * 4]) = lv;
}

// ---------------------------------------------------------------------------
// normalize: AW[row][*] *= invL[row]
// ---------------------------------------------------------------------------
__global__ void normalize_kernel(float* __restrict__ AW, const float* __restrict__ invL)
{
    size_t i4 = (size_t)blockIdx.x * blockDim.x + threadIdx.x;
    int row = (int)((i4 * 4) >> 11);
    float il = __ldg(&invL[row]);
    float4 v = reinterpret_cast<float4*>(AW)[i4];
    v.x *= il; v.y *= il; v.z *= il; v.w *= il;
    reinterpret_cast<float4*>(AW)[i4] = v;
}

// ---------------------------------------------------------------------------
// GEMM body: C[M,N] = (A[M,K] @ W[K,N] + bias) * scale, pre-split operands.
// BM=128 BN=128 BK=32, 256 threads, cp.async double-buffered, 3-term MMA.
// ---------------------------------------------------------------------------
#define GAS 40
#define GBS 136
#define G_STG (128 * GAS * 2 + 32 * GBS * 2)
#define G_SMEM_BYTES (2 * G_STG * 2 + 512)

__device__ __forceinline__ void gemm_body(
    const __nv_bfloat16* __restrict__ Ahg, const __nv_bfloat16* __restrict__ Alg,
    const __nv_bfloat16* __restrict__ Bhg, const __nv_bfloat16* __restrict__ Blg,
    const float* __restrict__ bias,
    float* __restrict__ Cf, __nv_bfloat16* __restrict__ Ch, __nv_bfloat16* __restrict__ Cl,
    float scale, int N, int K, int bm0, int bn0, __nv_bfloat16* sm)
{
    float* biasS = (float*)(sm + 2 * G_STG);

    const int tid = threadIdx.x;
    const int lane = tid & 31;
    const int wid = tid >> 5;
    const int wm = wid >> 2;
    const int wn = wid & 3;

    if (tid < 128) biasS[tid] = bias[bn0 + tid];

    auto load_stage = [&](int s, int kt) {
        __nv_bfloat16* sAh = sm + s * G_STG;
        __nv_bfloat16* sAl = sAh + 128 * GAS;
        __nv_bfloat16* sBh = sAl + 128 * GAS;
        __nv_bfloat16* sBl = sBh + 32 * GBS;
        #pragma unroll
        for (int i = 0; i < 2; i++) {
            int idx = i * 256 + tid;
            int r = idx >> 2, cg = (idx & 3) * 8;
            cp16(smem_u32(&sAh[r * GAS + cg]), &Ahg[(size_t)(bm0 + r) * K + kt + cg]);
            cp16(smem_u32(&sAl[r * GAS + cg]), &Alg[(size_t)(bm0 + r) * K + kt + cg]);
        }
        #pragma unroll
        for (int i = 0; i < 2; i++) {
            int idx = i * 256 + tid;
            int r = idx >> 4, cg = (idx & 15) * 8;
            cp16(smem_u32(&sBh[r * GBS + cg]), &Bhg[(size_t)(kt + r) * N + bn0 + cg]);
            cp16(smem_u32(&sBl[r * GBS + cg]), &Blg[(size_t)(kt + r) * N + bn0 + cg]);
        }
    };

    float acc[4][4][4] = {};
    const int nk = K >> 5;

    load_stage(0, 0);
    CP_COMMIT();

    for (int it = 0; it < nk; it++) {
        if (it + 1 < nk) load_stage((it + 1) & 1, (it + 1) * 32);
        CP_COMMIT();
        CP_WAIT1();
        __syncthreads();

        const __nv_bfloat16* sAh = sm + (it & 1) * G_STG;
        const __nv_bfloat16* sAl = sAh + 128 * GAS;
        const __nv_bfloat16* sBh = sAl + 128 * GAS;
        const __nv_bfloat16* sBl = sBh + 32 * GBS;

        #pragma unroll
        for (int ks = 0; ks < 2; ks++) {
            uint32_t ah[4][4], al[4][4];
            #pragma unroll
            for (int mt = 0; mt < 4; mt++) {
                int r = wm * 64 + mt * 16 + (lane & 15);
                int c = ks * 16 + (lane >> 4) * 8;
                ldsm_x4(ah[mt], smem_u32(&sAh[r * GAS + c]));
                ldsm_x4(al[mt], smem_u32(&sAl[r * GAS + c]));
            }
            uint32_t bh[4][2], bl[4][2];
            #pragma unroll
            for (int p = 0; p < 2; p++) {
                int r = ks * 16 + (lane & 15);
                int c = wn * 32 + p * 16 + (lane >> 4) * 8;
                uint32_t t4[4];
                ldsm_x4t(t4, smem_u32(&sBh[r * GBS + c]));
                bh[2*p][0] = t4[0]; bh[2*p][1] = t4[1];
                bh[2*p+1][0] = t4[2]; bh[2*p+1][1] = t4[3];
                ldsm_x4t(t4, smem_u32(&sBl[r * GBS + c]));
                bl[2*p][0] = t4[0]; bl[2*p][1] = t4[1];
                bl[2*p+1][0] = t4[2]; bl[2*p+1][1] = t4[3];
            }
            #pragma unroll
            for (int mt = 0; mt < 4; mt++)
                #pragma unroll
                for (int nt = 0; nt < 4; nt++) {
                    mma16816(acc[mt][nt], ah[mt], bh[nt]);
                    mma16816(acc[mt][nt], ah[mt], bl[nt]);
                    mma16816(acc[mt][nt], al[mt], bh[nt]);
                }
        }
        __syncthreads();
    }

    #pragma unroll
    for (int mt = 0; mt < 4; mt++)
        #pragma unroll
        for (int nt = 0; nt < 4; nt++) {
            int row = bm0 + wm * 64 + mt * 16 + (lane >> 2);
            int colL = wn * 32 + nt * 8 + (lane & 3) * 2;
            int col = bn0 + colL;
            float b0 = biasS[colL], b1 = biasS[colL + 1];
            float v00 = (acc[mt][nt][0] + b0) * scale;
            float v01 = (acc[mt][nt][1] + b1) * scale;
            float v10 = (acc[mt][nt][2] + b0) * scale;
            float v11 = (acc[mt][nt][3] + b1) * scale;
            if (Cf) {
                *reinterpret_cast<float2*>(&Cf[(size_t)row * N + col]) = make_float2(v00, v01);
                *reinterpret_cast<float2*>(&Cf[(size_t)(row + 8) * N + col]) = make_float2(v10, v11);
            } else {
                __nv_bfloat162 h0 = pack_hi(v00, v01), l0 = pack_lo(v00, v01, h0);
                *reinterpret_cast<__nv_bfloat162*>(&Ch[(size_t)row * N + col]) = h0;
                *reinterpret_cast<__nv_bfloat162*>(&Cl[(size_t)row * N + col]) = l0;
                __nv_bfloat162 h1 = pack_hi(v10, v11), l1 = pack_lo(v10, v11, h1);
                *reinterpret_cast<__nv_bfloat162*>(&Ch[(size_t)(row + 8) * N + col]) = h1;
                *reinterpret_cast<__nv_bfloat162*>(&Cl[(size_t)(row + 8) * N + col]) = l1;
            }
        }
}

__global__ __launch_bounds__(256) void gemm_bf16_kernel(
    const __nv_bfloat16* __restrict__ Ahg, const __nv_bfloat16* __restrict__ Alg,
    const __nv_bfloat16* __restrict__ Bhg, const __nv_bfloat16* __restrict__ Blg,
    const float* __restrict__ bias,
    float* __restrict__ Cf, __nv_bfloat16* __restrict__ Ch, __nv_bfloat16* __restrict__ Cl,
    float scale, int N, int K)
{
    extern __shared__ __nv_bfloat16 sm[];
    gemm_body(Ahg, Alg, Bhg, Blg, bias, Cf, Ch, Cl, scale, N, K,
              blockIdx.y * 128, blockIdx.x * 128, sm);
}

// K-proj and V-proj fused into one launch: blockIdx.x<4 -> K, else V.
__global__ __launch_bounds__(256) void gemm_kv_kernel(
    const __nv_bfloat16* __restrict__ kAh, const __nv_bfloat16* __restrict__ kAl,
    const __nv_bfloat16* __restrict__ kBh, const __nv_bfloat16* __restrict__ kBl,
    const float* __restrict__ kbias,
    __nv_bfloat16* __restrict__ kCh, __nv_bfloat16* __restrict__ kCl,
    const __nv_bfloat16* __restrict__ vAh, const __nv_bfloat16* __restrict__ vAl,
    const __nv_bfloat16* __restrict__ vBh, const __nv_bfloat16* __restrict__ vBl,
    const float* __restrict__ vbias,
    __nv_bfloat16* __restrict__ vCh, __nv_bfloat16* __restrict__ vCl)
{
    extern __shared__ __nv_bfloat16 sm[];
    if (blockIdx.x < 4)
        gemm_body(kAh, kAl, kBh, kBl, kbias, nullptr, kCh, kCl, 1.f, KVDIM, DIM,
                  blockIdx.y * 128, blockIdx.x * 128, sm);
    else
        gemm_body(vAh, vAl, vBh, vBl, vbias, nullptr, vCh, vCl, 1.f, KVDIM, DIM,
                  blockIdx.y * 128, (blockIdx.x - 4) * 128, sm);
}

// ---------------------------------------------------------------------------
// Attention (single pass): grid (32 qtiles x 32 bh), 256 threads (8 warps 4x2).
// 32-key double-buffered KV tiles; total smem 115.2KB => 2 CTAs/SM.
// Warp (wr,wc): wr = 16 q-rows, wc = 16-key half for S / 64-V-col half for PV.
// ---------------------------------------------------------------------------
#define AAS 136
#define APS 40
#define AT_Q   0                         // Qh,Ql: 2 x 64*AAS halves
#define AT_KV  (2 * 64 * AAS)            // 17408
#define AT_KVS (4 * 32 * AAS)            // per stage (Kh,Kl,Vh,Vl) = 17408
#define AT_P   (AT_KV + 2 * AT_KVS)      // 52224
#define AT_LP  (AT_P + 2 * 64 * APS)     // 57344 halves
#define ATTN_SMEM_BYTES (AT_LP * 2 + 512)  // 115200 B

__global__ __launch_bounds__(256, 2) void attn_kernel(
    const __nv_bfloat16* __restrict__ Qhg, const __nv_bfloat16* __restrict__ Qlg,
    const __nv_bfloat16* __restrict__ Khg, const __nv_bfloat16* __restrict__ Klg,
    const __nv_bfloat16* __restrict__ Vhg, const __nv_bfloat16* __restrict__ Vlg,
    float* __restrict__ AW, float* __restrict__ invLg,
    __nv_bfloat16* __restrict__ Ohg, __nv_bfloat16* __restrict__ Olg)
{
    extern __shared__ __nv_bfloat16 sm[];
    __nv_bfloat16* Qh = sm + AT_Q;
    __nv_bfloat16* Ql = Qh + 64 * AAS;
    __nv_bfloat16* Ph = sm + AT_P;
    __nv_bfloat16* Pl = Ph + 64 * APS;
    float* lp = (float*)(sm + AT_LP);

    const int tid = threadIdx.x;
    const int lane = tid & 31;
    const int wid = tid >> 5;
    const int wr = wid & 3;
    const int wc = wid >> 2;
    const int qt = blockIdx.x;
    const int bh = blockIdx.y;
    const int b = bh >> 4, h = bh & 15, kv = h >> 2;

    const size_t qrow0 = (size_t)b * T + qt * 64;
    const size_t krow0 = (size_t)b * T;
    const int kcol = kv * 128;

    // 32 keys per stage: Kh,Kl,Vh,Vl each 32 x 128 (stride AAS)
    auto load_kv = [&](int s, size_t row0) {
        __nv_bfloat16* base = sm + AT_KV + s * AT_KVS;
        #pragma unroll
        for (int i = 0; i < 2; i++) {
            int idx = i * 256 + tid;
            int r = idx >> 4, cg = (idx & 15) * 8;
            cp16(smem_u32(&base[r * AAS + cg]),            &Khg[(row0 + r) * KVDIM + kcol + cg]);
            cp16(smem_u32(&base[32*AAS + r * AAS + cg]),   &Klg[(row0 + r) * KVDIM + kcol + cg]);
            cp16(smem_u32(&base[2*32*AAS + r * AAS + cg]), &Vhg[(row0 + r) * KVDIM + kcol + cg]);
            cp16(smem_u32(&base[3*32*AAS + r * AAS + cg]), &Vlg[(row0 + r) * KVDIM + kcol + cg]);
        }
    };

    // prologue: KV tile 0 async + Q to smem
    load_kv(0, krow0);
    CP_COMMIT();
    #pragma unroll
    for (int i = 0; i < 4; i++) {
        int idx = i * 256 + tid;
        int r = idx >> 4, cg = (idx & 15) * 8;
        *reinterpret_cast<uint4*>(&Qh[r * AAS + cg]) =
            *reinterpret_cast<const uint4*>(&Qhg[(qrow0 + r) * DIM + h * 128 + cg]);
        *reinterpret_cast<uint4*>(&Ql[r * AAS + cg]) =
            *reinterpret_cast<const uint4*>(&Qlg[(qrow0 + r) * DIM + h * 128 + cg]);
    }

    float l0 = 0.f, l1 = 0.f;
    float o[8][4] = {};

    const int r0 = wr * 16 + (lane >> 2);
    const int c0 = (lane & 3) * 2;
    const size_t gb = ((size_t)bh * T + (size_t)qt * 64) * T;

    #pragma unroll 1
    for (int kt = 0; kt < 64; kt++) {
        CP_WAIT0();
        __syncthreads();
        if (kt < 63) {
            load_kv((kt + 1) & 1, krow0 + (kt + 1) * 32);
            CP_COMMIT();
        }

        const __nv_bfloat16* Kbh = sm + AT_KV + (kt & 1) * AT_KVS;
        const __nv_bfloat16* Kbl = Kbh + 32 * AAS;
        const __nv_bfloat16* Vbh = Kbh + 2 * 32 * AAS;
        const __nv_bfloat16* Vbl = Kbh + 3 * 32 * AAS;

        // ---- S = Q K^T : warp -> 16 q-rows x 16 keys (wc selects key half) ----
        float s[2][4];
        #pragma unroll
        for (int nt = 0; nt < 2; nt++)
            #pragma unroll
            for (int j = 0; j < 4; j++) s[nt][j] = 0.f;

        #pragma unroll
        for (int kk = 0; kk < 8; kk++) {
            uint32_t ah[4], al[4];
            int ar = wr * 16 + (lane & 15), ac = kk * 16 + (lane >> 4) * 8;
            ldsm_x4(ah, smem_u32(&Qh[ar * AAS + ac]));
            ldsm_x4(al, smem_u32(&Ql[ar * AAS + ac]));
            int br = wc * 16 + (lane & 15), bc = kk * 16 + (lane >> 4) * 8;
            uint32_t b4h[4], b4l[4];
            ldsm_x4(b4h, smem_u32(&Kbh[br * AAS + bc]));
            ldsm_x4(b4l, smem_u32(&Kbl[br * AAS + bc]));
            uint32_t be_h[2] = {b4h[0], b4h[2]}, bo_h[2] = {b4h[1], b4h[3]};
            uint32_t be_l[2] = {b4l[0], b4l[2]}, bo_l[2] = {b4l[1], b4l[3]};
            mma16816(s[0], ah, be_h); mma16816(s[0], ah, be_l); mma16816(s[0], al, be_h);
            mma16816(s[1], ah, bo_h); mma16816(s[1], ah, bo_l); mma16816(s[1], al, bo_h);
        }

        // ---- e = exp(s) in regs, split into P smem ----
        #pragma unroll
        for (int nt = 0; nt < 2; nt++) {
            s[nt][0] = __expf(s[nt][0]); s[nt][1] = __expf(s[nt][1]);
            s[nt][2] = __expf(s[nt][2]); s[nt][3] = __expf(s[nt][3]);
            l0 += s[nt][0] + s[nt][1];
            l1 += s[nt][2] + s[nt][3];
            int colL = wc * 16 + nt * 8 + c0;
            __nv_bfloat162 h0 = pack_hi(s[nt][0], s[nt][1]), lo0 = pack_lo(s[nt][0], s[nt][1], h0);
            __nv_bfloat162 h1 = pack_hi(s[nt][2], s[nt][3]), lo1 = pack_lo(s[nt][2], s[nt][3], h1);
            *reinterpret_cast<__nv_bfloat162*>(&Ph[r0 * APS + colL]) = h0;
            *reinterpret_cast<__nv_bfloat162*>(&Pl[r0 * APS + colL]) = lo0;
            *reinterpret_cast<__nv_bfloat162*>(&Ph[(r0 + 8) * APS + colL]) = h1;
            *reinterpret_cast<__nv_bfloat162*>(&Pl[(r0 + 8) * APS + colL]) = lo1;
        }
        __syncthreads();

        // ---- O += P V : warp -> 16 q-rows x 64 V-cols (wc selects col half) ----
        #pragma unroll
        for (int kc = 0; kc < 2; kc++) {
            uint32_t ph4[4], pl4[4];
            int pr = wr * 16 + (lane & 15), pc = kc * 16 + (lane >> 4) * 8;
            ldsm_x4(ph4, smem_u32(&Ph[pr * APS + pc]));
            ldsm_x4(pl4, smem_u32(&Pl[pr * APS + pc]));
            #pragma unroll
            for (int p = 0; p < 4; p++) {
                int vr = kc * 16 + (lane & 15);
                int vc = wc * 64 + p * 16 + (lane >> 4) * 8;
                uint32_t v4h[4], v4l[4];
                ldsm_x4t(v4h, smem_u32(&Vbh[vr * AAS + vc]));
                ldsm_x4t(v4l, smem_u32(&Vbl[vr * AAS + vc]));
                uint32_t be_h[2] = {v4h[0], v4h[1]}, bo_h[2] = {v4h[2], v4h[3]};
                uint32_t be_l[2] = {v4l[0], v4l[1]}, bo_l[2] = {v4l[2], v4l[3]};
                mma16816(o[2*p],   ph4, be_h); mma16816(o[2*p],   ph4, be_l); mma16816(o[2*p],   pl4, be_h);
                mma16816(o[2*p+1], ph4, bo_h); mma16816(o[2*p+1], ph4, bo_l); mma16816(o[2*p+1], pl4, bo_h);
            }
        }

        // ---- deferred AW stores (raw exp) — drain while tensor pipe busy ----
        #pragma unroll
        for (int nt = 0; nt < 2; nt++) {
            int col = kt * 32 + wc * 16 + nt * 8 + c0;
            *reinterpret_cast<float2*>(&AW[gb + (size_t)r0 * T + col]) =
                make_float2(s[nt][0], s[nt][1]);
            *reinterpret_cast<float2*>(&AW[gb + (size_t)(r0 + 8) * T + col]) =
                make_float2(s[nt][2], s[nt][3]);
        }
    }

    // ---- row-sum reduction ----
    l0 += __shfl_xor_sync(0xffffffffu, l0, 1);
    l0 += __shfl_xor_sync(0xffffffffu, l0, 2);
    l1 += __shfl_xor_sync(0xffffffffu, l1, 1);
    l1 += __shfl_xor_sync(0xffffffffu, l1, 2);
    __syncthreads();
    if ((lane & 3) == 0) {
        lp[wc * 64 + r0] = l0;
        lp[wc * 64 + r0 + 8] = l1;
    }
    __syncthreads();

    if (tid < 64) {
        float il = 1.f / (lp[tid] + lp[64 + tid]);
        invLg[(size_t)bh * T + qt * 64 + tid] = il;
    }

    const float ilA = 1.f / (lp[r0] + lp[64 + r0]);
    const float ilB = 1.f / (lp[r0 + 8] + lp[64 + r0 + 8]);

    // ---- write O (scaled, split) ----
    #pragma unroll
    for (int nt = 0; nt < 8; nt++) {
        int c = h * 128 + wc * 64 + nt * 8 + c0;
        float v00 = o[nt][0] * ilA, v01 = o[nt][1] * ilA;
        float v10 = o[nt][2] * ilB, v11 = o[nt][3] * ilB;
        __nv_bfloat162 h0 = pack_hi(v00, v01), l0v = pack_lo(v00, v01, h0);
        __nv_bfloat162 h1 = pack_hi(v10, v11), l1v = pack_lo(v10, v11, h1);
        *reinterpret_cast<__nv_bfloat162*>(&Ohg[(qrow0 + r0) * DIM + c]) = h0;
        *reinterpret_cast<__nv_bfloat162*>(&Olg[(qrow0 + r0) * DIM + c]) = l0v;
        *reinterpret_cast<__nv_bfloat162*>(&Ohg[(qrow0 + r0 + 8) * DIM + c]) = h1;
        *reinterpret_cast<__nv_bfloat162*>(&Olg[(qrow0 + r0 + 8) * DIM + c]) = l1v;
    }
}

// ---------------------------------------------------------------------------
// launch
// ---------------------------------------------------------------------------
extern "C" void kernel_launch(void* const* d_in, const int* in_sizes, int n_in,
                              void* d_out, int out_size)
{
    const float* q  = (const float*)d_in[0];
    const float* k  = (const float*)d_in[1];
    const float* v  = (const float*)d_in[2];
    const float* Wq = (const float*)d_in[3];
    const float* bq = (const float*)d_in[4];
    const float* Wk = (const float*)d_in[5];
    const float* bk = (const float*)d_in[6];
    const float* Wv = (const float*)d_in[7];
    const float* bv = (const float*)d_in[8];
    const float* Wo = (const float*)d_in[9];
    const float* bo = (const float*)d_in[10];

    float* out   = (float*)d_out;
    float* attnW = out + (size_t)BT * DIM;

    __nv_bfloat16 *qh, *ql, *kh, *kl, *vh, *vl;
    __nv_bfloat16 *Wqh, *Wql, *Wkh, *Wkl, *Wvh, *Wvl, *Woh, *Wol;
    __nv_bfloat16 *Qh, *Ql, *Kh, *Kl, *Vh, *Vl, *Oh, *Ol;
    float* invL;
    cudaGetSymbolAddress((void**)&qh, g_qh);   cudaGetSymbolAddress((void**)&ql, g_ql);
    cudaGetSymbolAddress((void**)&kh, g_kh);   cudaGetSymbolAddress((void**)&kl, g_kl);
    cudaGetSymbolAddress((void**)&vh, g_vh);   cudaGetSymbolAddress((void**)&vl, g_vl);
    cudaGetSymbolAddress((void**)&Wqh, g_Wqh); cudaGetSymbolAddress((void**)&Wql, g_Wql);
    cudaGetSymbolAddress((void**)&Wkh, g_Wkh); cudaGetSymbolAddress((void**)&Wkl, g_Wkl);
    cudaGetSymbolAddress((void**)&Wvh, g_Wvh); cudaGetSymbolAddress((void**)&Wvl, g_Wvl);
    cudaGetSymbolAddress((void**)&Woh, g_Woh); cudaGetSymbolAddress((void**)&Wol, g_Wol);
    cudaGetSymbolAddress((void**)&Qh, g_Qh);   cudaGetSymbolAddress((void**)&Ql, g_Ql);
    cudaGetSymbolAddress((void**)&Kh, g_Kh);   cudaGetSymbolAddress((void**)&Kl, g_Kl);
    cudaGetSymbolAddress((void**)&Vh, g_Vh);   cudaGetSymbolAddress((void**)&Vl, g_Vl);
    cudaGetSymbolAddress((void**)&Oh, g_Oh);   cudaGetSymbolAddress((void**)&Ol, g_Ol);
    cudaGetSymbolAddress((void**)&invL, g_invL);

    cudaFuncSetAttribute(gemm_bf16_kernel, cudaFuncAttributeMaxDynamicSharedMemorySize,
                         G_SMEM_BYTES);
    cudaFuncSetAttribute(gemm_kv_kernel, cudaFuncAttributeMaxDynamicSharedMemorySize,
                         G_SMEM_BYTES);
    cudaFuncSetAttribute(attn_kernel, cudaFuncAttributeMaxDynamicSharedMemorySize,
                         ATTN_SMEM_BYTES);

    const float scale = 0.08838834764831845f;  // 1/sqrt(128)

    // splits (fp32 -> bf16 hi/lo): 3 fused launches
    const int nBD = BT * DIM / 4, nDD = DIM * DIM / 4, nDK = DIM * KVDIM / 4;
    split3_kernel<<<dim3((nBD + 255) / 256, 3), 256>>>(
        q, qh, ql, k, kh, kl, v, vh, vl, nBD);
    split3_kernel<<<dim3((nDD + 255) / 256, 2), 256>>>(
        Wq, Wqh, Wql, Wo, Woh, Wol, nullptr, nullptr, nullptr, nDD);
    split3_kernel<<<dim3((nDK + 255) / 256, 2), 256>>>(
        Wk, Wkh, Wkl, Wv, Wvh, Wvl, nullptr, nullptr, nullptr, nDK);

    // Q projection (pre-scaled) + fused K/V projections
    gemm_bf16_kernel<<<dim3(DIM / 128, BT / 128), 256, G_SMEM_BYTES>>>(
        qh, ql, Wqh, Wql, bq, nullptr, Qh, Ql, scale, DIM, DIM);
    gemm_kv_kernel<<<dim3(2 * KVDIM / 128, BT / 128), 256, G_SMEM_BYTES>>>(
        kh, kl, Wkh, Wkl, bk, Kh, Kl,
        vh, vl, Wvh, Wvl, bv, Vh, Vl);

    // attention (raw exp -> AW, O pre-split & scaled)
    attn_kernel<<<dim3(T / 64, 32), 256, ATTN_SMEM_BYTES>>>(
        Qh, Ql, Kh, Kl, Vh, Vl, attnW, invL, Oh, Ol);

    // normalize attention weights
    normalize_kernel<<<(int)(((size_t)32 * T * T / 4) / 256), 256>>>(attnW, invL);

    // output projection (fp32 epilogue)
    gemm_bf16_kernel<<<dim3(DIM / 128, BT / 128), 256, G_SMEM_BYTES>>>(
        Oh, Ol, Woh, Wol, bo, out, nullptr, nullptr, 1.f, DIM, DIM);
}

// round 8
// speedup vs baseline: 1.7598x; 1.0490x over previous
#include <cuda_runtime.h>
#include <cuda_bf16.h>
#include <cstdint>
#include <cmath>

// ---------------------------------------------------------------------------
// GroupedQueryAttention: B=2, T=2048, DIM=2048, H=16, KH=4, DK=DV=128
// d_out = [ out (2,2048,2048) fp32 | attn_weight (2,16,2048,2048) fp32 ]
//
// Round 7: kernel fusion for pipe overlap —
//   * Q/K/V projections in ONE launch (one wave tail)
//   * Wo projection + AW normalize in ONE launch (normalize soaks idle HBM
//     under the tensor-bound gemm)
//   * GEMM mainloop: single __syncthreads per BK iteration
// Attention unchanged from round 6. Split-bf16 3-term numerics everywhere.
// ---------------------------------------------------------------------------

#define BT 4096
#define DIM 2048
#define KVDIM 512
#define T 2048

// ---- device scratch (no allocation allowed) ----
__device__ __nv_bfloat16 g_qh[BT * DIM],  g_ql[BT * DIM];
__device__ __nv_bfloat16 g_kh[BT * DIM],  g_kl[BT * DIM];
__device__ __nv_bfloat16 g_vh[BT * DIM],  g_vl[BT * DIM];
__device__ __nv_bfloat16 g_Wqh[DIM * DIM], g_Wql[DIM * DIM];
__device__ __nv_bfloat16 g_Wkh[DIM * KVDIM], g_Wkl[DIM * KVDIM];
__device__ __nv_bfloat16 g_Wvh[DIM * KVDIM], g_Wvl[DIM * KVDIM];
__device__ __nv_bfloat16 g_Woh[DIM * DIM], g_Wol[DIM * DIM];
__device__ __nv_bfloat16 g_Qh[BT * DIM],  g_Ql[BT * DIM];
__device__ __nv_bfloat16 g_Kh[BT * KVDIM], g_Kl[BT * KVDIM];
__device__ __nv_bfloat16 g_Vh[BT * KVDIM], g_Vl[BT * KVDIM];
__device__ __nv_bfloat16 g_Oh[BT * DIM],  g_Ol[BT * DIM];
__device__ float g_invL[32 * T];

// ---------------------------------------------------------------------------
// helpers
// ---------------------------------------------------------------------------
__device__ __forceinline__ uint32_t smem_u32(const void* p) {
    return (uint32_t)__cvta_generic_to_shared(p);
}
__device__ __forceinline__ void ldsm_x4(uint32_t* r, uint32_t addr) {
    asm volatile("ldmatrix.sync.aligned.m8n8.x4.shared.b16 {%0,%1,%2,%3}, [%4];"
                 : "=r"(r[0]), "=r"(r[1]), "=r"(r[2]), "=r"(r[3]) : "r"(addr));
}
__device__ __forceinline__ void ldsm_x4t(uint32_t* r, uint32_t addr) {
    asm volatile("ldmatrix.sync.aligned.m8n8.x4.trans.shared.b16 {%0,%1,%2,%3}, [%4];"
                 : "=r"(r[0]), "=r"(r[1]), "=r"(r[2]), "=r"(r[3]) : "r"(addr));
}
__device__ __forceinline__ void mma16816(float* c, const uint32_t* a, const uint32_t* b) {
    asm volatile(
        "mma.sync.aligned.m16n8k16.row.col.f32.bf16.bf16.f32 "
        "{%0,%1,%2,%3}, {%4,%5,%6,%7}, {%8,%9}, {%0,%1,%2,%3};\n"
        : "+f"(c[0]), "+f"(c[1]), "+f"(c[2]), "+f"(c[3])
        : "r"(a[0]), "r"(a[1]), "r"(a[2]), "r"(a[3]), "r"(b[0]), "r"(b[1]));
}
__device__ __forceinline__ void cp16(uint32_t saddr, const void* g) {
    asm volatile("cp.async.cg.shared.global [%0], [%1], 16;" :: "r"(saddr), "l"(g));
}
#define CP_COMMIT() asm volatile("cp.async.commit_group;")
#define CP_WAIT0()  asm volatile("cp.async.wait_group 0;")

__device__ __forceinline__ __nv_bfloat162 pack_hi(float a, float b) {
    __nv_bfloat162 r; r.x = __float2bfloat16(a); r.y = __float2bfloat16(b); return r;
}
__device__ __forceinline__ __nv_bfloat162 pack_lo(float a, float b, __nv_bfloat162 h) {
    __nv_bfloat162 r;
    r.x = __float2bfloat16(a - __bfloat162float(h.x));
    r.y = __float2bfloat16(b - __bfloat162float(h.y));
    return r;
}

// ---------------------------------------------------------------------------
// split: fp32 -> bf16 hi/lo; blockIdx.y selects one of up to 3 tensors
// ---------------------------------------------------------------------------
__global__ void split3_kernel(
    const float* __restrict__ s0, __nv_bfloat16* __restrict__ h0, __nv_bfloat16* __restrict__ l0,
    const float* __restrict__ s1, __nv_bfloat16* __restrict__ h1, __nv_bfloat16* __restrict__ l1,
    const float* __restrict__ s2, __nv_bfloat16* __restrict__ h2, __nv_bfloat16* __restrict__ l2,
    int n4)
{
    int i = blockIdx.x * blockDim.x + threadIdx.x;
    if (i >= n4) return;
    const float* src; __nv_bfloat16 *h, *l;
    if (blockIdx.y == 0)      { src = s0; h = h0; l = l0; }
    else if (blockIdx.y == 1) { src = s1; h = h1; l = l1; }
    else                      { src = s2; h = h2; l = l2; }
    float4 v = reinterpret_cast<const float4*>(src)[i];
    __nv_bfloat162 ha = pack_hi(v.x, v.y), hb = pack_hi(v.z, v.w);
    __nv_bfloat162 la = pack_lo(v.x, v.y, ha), lb = pack_lo(v.z, v.w, hb);
    uint2 hv = make_uint2(*(uint32_t*)&ha, *(uint32_t*)&hb);
    uint2 lv = make_uint2(*(uint32_t*)&la, *(uint32_t*)&lb);
    *reinterpret_cast<uint2*>(&h[(size_t)i * 4]) = hv;
    *reinterpret_cast<uint2*>(&l[(size_t)i * 4]) = lv;
}

// ---------------------------------------------------------------------------
// GEMM body: C[M,N] = (A[M,K] @ W[K,N] + bias) * scale, pre-split operands.
// BM=128 BN=128 BK=32, 256 threads, cp.async double-buffered,
// ONE __syncthreads per BK iteration. 3-term split MMA.
// ---------------------------------------------------------------------------
#define GAS 40
#define GBS 136
#define G_STG (128 * GAS * 2 + 32 * GBS * 2)
#define G_SMEM_BYTES (2 * G_STG * 2 + 512)

__device__ __forceinline__ void gemm_body(
    const __nv_bfloat16* __restrict__ Ahg, const __nv_bfloat16* __restrict__ Alg,
    const __nv_bfloat16* __restrict__ Bhg, const __nv_bfloat16* __restrict__ Blg,
    const float* __restrict__ bias,
    float* __restrict__ Cf, __nv_bfloat16* __restrict__ Ch, __nv_bfloat16* __restrict__ Cl,
    float scale, int N, int K, int bm0, int bn0, __nv_bfloat16* sm)
{
    float* biasS = (float*)(sm + 2 * G_STG);

    const int tid = threadIdx.x;
    const int lane = tid & 31;
    const int wid = tid >> 5;
    const int wm = wid >> 2;
    const int wn = wid & 3;

    if (tid < 128) biasS[tid] = bias[bn0 + tid];

    auto load_stage = [&](int s, int kt) {
        __nv_bfloat16* sAh = sm + s * G_STG;
        __nv_bfloat16* sAl = sAh + 128 * GAS;
        __nv_bfloat16* sBh = sAl + 128 * GAS;
        __nv_bfloat16* sBl = sBh + 32 * GBS;
        #pragma unroll
        for (int i = 0; i < 2; i++) {
            int idx = i * 256 + tid;
            int r = idx >> 2, cg = (idx & 3) * 8;
            cp16(smem_u32(&sAh[r * GAS + cg]), &Ahg[(size_t)(bm0 + r) * K + kt + cg]);
            cp16(smem_u32(&sAl[r * GAS + cg]), &Alg[(size_t)(bm0 + r) * K + kt + cg]);
        }
        #pragma unroll
        for (int i = 0; i < 2; i++) {
            int idx = i * 256 + tid;
            int r = idx >> 4, cg = (idx & 15) * 8;
            cp16(smem_u32(&sBh[r * GBS + cg]), &Bhg[(size_t)(kt + r) * N + bn0 + cg]);
            cp16(smem_u32(&sBl[r * GBS + cg]), &Blg[(size_t)(kt + r) * N + bn0 + cg]);
        }
    };

    float acc[4][4][4] = {};
    const int nk = K >> 5;

    load_stage(0, 0);
    CP_COMMIT();

    for (int it = 0; it < nk; it++) {
        CP_WAIT0();
        __syncthreads();
        if (it + 1 < nk) {
            load_stage((it + 1) & 1, (it + 1) * 32);
            CP_COMMIT();
        }

        const __nv_bfloat16* sAh = sm + (it & 1) * G_STG;
        const __nv_bfloat16* sAl = sAh + 128 * GAS;
        const __nv_bfloat16* sBh = sAl + 128 * GAS;
        const __nv_bfloat16* sBl = sBh + 32 * GBS;

        #pragma unroll
        for (int ks = 0; ks < 2; ks++) {
            uint32_t ah[4][4], al[4][4];
            #pragma unroll
            for (int mt = 0; mt < 4; mt++) {
                int r = wm * 64 + mt * 16 + (lane & 15);
                int c = ks * 16 + (lane >> 4) * 8;
                ldsm_x4(ah[mt], smem_u32(&sAh[r * GAS + c]));
                ldsm_x4(al[mt], smem_u32(&sAl[r * GAS + c]));
            }
            uint32_t bh[4][2], bl[4][2];
            #pragma unroll
            for (int p = 0; p < 2; p++) {
                int r = ks * 16 + (lane & 15);
                int c = wn * 32 + p * 16 + (lane >> 4) * 8;
                uint32_t t4[4];
                ldsm_x4t(t4, smem_u32(&sBh[r * GBS + c]));
                bh[2*p][0] = t4[0]; bh[2*p][1] = t4[1];
                bh[2*p+1][0] = t4[2]; bh[2*p+1][1] = t4[3];
                ldsm_x4t(t4, smem_u32(&sBl[r * GBS + c]));
                bl[2*p][0] = t4[0]; bl[2*p][1] = t4[1];
                bl[2*p+1][0] = t4[2]; bl[2*p+1][1] = t4[3];
            }
            #pragma unroll
            for (int mt = 0; mt < 4; mt++)
                #pragma unroll
                for (int nt = 0; nt < 4; nt++) {
                    mma16816(acc[mt][nt], ah[mt], bh[nt]);
                    mma16816(acc[mt][nt], ah[mt], bl[nt]);
                    mma16816(acc[mt][nt], al[mt], bh[nt]);
                }
        }
    }

    #pragma unroll
    for (int mt = 0; mt < 4; mt++)
        #pragma unroll
        for (int nt = 0; nt < 4; nt++) {
            int row = bm0 + wm * 64 + mt * 16 + (lane >> 2);
            int colL = wn * 32 + nt * 8 + (lane & 3) * 2;
            int col = bn0 + colL;
            float b0 = biasS[colL], b1 = biasS[colL + 1];
            float v00 = (acc[mt][nt][0] + b0) * scale;
            float v01 = (acc[mt][nt][1] + b1) * scale;
            float v10 = (acc[mt][nt][2] + b0) * scale;
            float v11 = (acc[mt][nt][3] + b1) * scale;
            if (Cf) {
                *reinterpret_cast<float2*>(&Cf[(size_t)row * N + col]) = make_float2(v00, v01);
                *reinterpret_cast<float2*>(&Cf[(size_t)(row + 8) * N + col]) = make_float2(v10, v11);
            } else {
                __nv_bfloat162 h0 = pack_hi(v00, v01), l0 = pack_lo(v00, v01, h0);
                *reinterpret_cast<__nv_bfloat162*>(&Ch[(size_t)row * N + col]) = h0;
                *reinterpret_cast<__nv_bfloat162*>(&Cl[(size_t)row * N + col]) = l0;
                __nv_bfloat162 h1 = pack_hi(v10, v11), l1 = pack_lo(v10, v11, h1);
                *reinterpret_cast<__nv_bfloat162*>(&Ch[(size_t)(row + 8) * N + col]) = h1;
                *reinterpret_cast<__nv_bfloat162*>(&Cl[(size_t)(row + 8) * N + col]) = l1;
            }
        }
}

// ---------------------------------------------------------------------------
// Fused Q/K/V projections: 768 CTAs in one launch.
//   id < 512        : Q tile  (16 n-tiles x 32 m-tiles), scaled by 1/sqrt(dk)
//   512 <= id < 640 : K tile  (4 x 32)
//   640 <= id < 768 : V tile  (4 x 32)
// ---------------------------------------------------------------------------
__global__ __launch_bounds__(256) void gemm_qkv_kernel(
    const __nv_bfloat16* __restrict__ qh, const __nv_bfloat16* __restrict__ ql,
    const __nv_bfloat16* __restrict__ Wqh, const __nv_bfloat16* __restrict__ Wql,
    const float* __restrict__ bq,
    __nv_bfloat16* __restrict__ Qh, __nv_bfloat16* __restrict__ Ql_,
    const __nv_bfloat16* __restrict__ kh, const __nv_bfloat16* __restrict__ kl,
    const __nv_bfloat16* __restrict__ Wkh, const __nv_bfloat16* __restrict__ Wkl,
    const float* __restrict__ bk,
    __nv_bfloat16* __restrict__ Kh, __nv_bfloat16* __restrict__ Kl,
    const __nv_bfloat16* __restrict__ vh, const __nv_bfloat16* __restrict__ vl,
    const __nv_bfloat16* __restrict__ Wvh, const __nv_bfloat16* __restrict__ Wvl,
    const float* __restrict__ bv,
    __nv_bfloat16* __restrict__ Vh, __nv_bfloat16* __restrict__ Vl,
    float qscale)
{
    extern __shared__ __nv_bfloat16 sm[];
    const int id = blockIdx.x;
    if (id < 512) {
        gemm_body(qh, ql, Wqh, Wql, bq, nullptr, Qh, Ql_, qscale, DIM, DIM,
                  (id >> 4) * 128, (id & 15) * 128, sm);
    } else if (id < 640) {
        int t = id - 512;
        gemm_body(kh, kl, Wkh, Wkl, bk, nullptr, Kh, Kl, 1.f, KVDIM, DIM,
                  (t >> 2) * 128, (t & 3) * 128, sm);
    } else {
        int t = id - 640;
        gemm_body(vh, vl, Wvh, Wvl, bv, nullptr, Vh, Vl, 1.f, KVDIM, DIM,
                  (t >> 2) * 128, (t & 3) * 128, sm);
    }
}

// ---------------------------------------------------------------------------
// Fused Wo projection + AW normalize: 512 gemm CTAs + 1024 normalize CTAs.
// Normalize CTAs soak idle DRAM bandwidth under the tensor-bound gemm.
// ---------------------------------------------------------------------------
#define NORM_CTAS 1024

__global__ __launch_bounds__(256) void gemm_wo_norm_kernel(
    const __nv_bfloat16* __restrict__ Oh, const __nv_bfloat16* __restrict__ Ol,
    const __nv_bfloat16* __restrict__ Woh, const __nv_bfloat16* __restrict__ Wol,
    const float* __restrict__ bo, float* __restrict__ out,
    float* __restrict__ AW, const float* __restrict__ invL)
{
    extern __shared__ __nv_bfloat16 sm[];
    const int id = blockIdx.x;
    if (id < 512) {
        gemm_body(Oh, Ol, Woh, Wol, bo, out, nullptr, nullptr, 1.f, DIM, DIM,
                  (id >> 4) * 128, (id & 15) * 128, sm);
    } else {
        const size_t nf4 = (size_t)32 * T * T / 4;          // 33,554,432 float4
        const size_t stride = (size_t)NORM_CTAS * 256;
        for (size_t i4 = (size_t)(id - 512) * 256 + threadIdx.x; i4 < nf4; i4 += stride) {
            int row = (int)((i4 * 4) >> 11);
            float il = __ldg(&invL[row]);
            float4 v = reinterpret_cast<float4*>(AW)[i4];
            v.x *= il; v.y *= il; v.z *= il; v.w *= il;
            reinterpret_cast<float4*>(AW)[i4] = v;
        }
    }
}

// ---------------------------------------------------------------------------
// Attention (single pass): grid (32 qtiles x 32 bh), 256 threads (8 warps 4x2).
// 32-key double-buffered KV tiles; total smem 115.2KB => 2 CTAs/SM.
// ---------------------------------------------------------------------------
#define AAS 136
#define APS 40
#define AT_Q   0
#define AT_KV  (2 * 64 * AAS)
#define AT_KVS (4 * 32 * AAS)
#define AT_P   (AT_KV + 2 * AT_KVS)
#define AT_LP  (AT_P + 2 * 64 * APS)
#define ATTN_SMEM_BYTES (AT_LP * 2 + 512)

__global__ __launch_bounds__(256, 2) void attn_kernel(
    const __nv_bfloat16* __restrict__ Qhg, const __nv_bfloat16* __restrict__ Qlg,
    const __nv_bfloat16* __restrict__ Khg, const __nv_bfloat16* __restrict__ Klg,
    const __nv_bfloat16* __restrict__ Vhg, const __nv_bfloat16* __restrict__ Vlg,
    float* __restrict__ AW, float* __restrict__ invLg,
    __nv_bfloat16* __restrict__ Ohg, __nv_bfloat16* __restrict__ Olg)
{
    extern __shared__ __nv_bfloat16 sm[];
    __nv_bfloat16* Qh = sm + AT_Q;
    __nv_bfloat16* Ql = Qh + 64 * AAS;
    __nv_bfloat16* Ph = sm + AT_P;
    __nv_bfloat16* Pl = Ph + 64 * APS;
    float* lp = (float*)(sm + AT_LP);

    const int tid = threadIdx.x;
    const int lane = tid & 31;
    const int wid = tid >> 5;
    const int wr = wid & 3;
    const int wc = wid >> 2;
    const int qt = blockIdx.x;
    const int bh = blockIdx.y;
    const int b = bh >> 4, h = bh & 15, kv = h >> 2;

    const size_t qrow0 = (size_t)b * T + qt * 64;
    const size_t krow0 = (size_t)b * T;
    const int kcol = kv * 128;

    auto load_kv = [&](int s, size_t row0) {
        __nv_bfloat16* base = sm + AT_KV + s * AT_KVS;
        #pragma unroll
        for (int i = 0; i < 2; i++) {
            int idx = i * 256 + tid;
            int r = idx >> 4, cg = (idx & 15) * 8;
            cp16(smem_u32(&base[r * AAS + cg]),            &Khg[(row0 + r) * KVDIM + kcol + cg]);
            cp16(smem_u32(&base[32*AAS + r * AAS + cg]),   &Klg[(row0 + r) * KVDIM + kcol + cg]);
            cp16(smem_u32(&base[2*32*AAS + r * AAS + cg]), &Vhg[(row0 + r) * KVDIM + kcol + cg]);
            cp16(smem_u32(&base[3*32*AAS + r * AAS + cg]), &Vlg[(row0 + r) * KVDIM + kcol + cg]);
        }
    };

    load_kv(0, krow0);
    CP_COMMIT();
    #pragma unroll
    for (int i = 0; i < 4; i++) {
        int idx = i * 256 + tid;
        int r = idx >> 4, cg = (idx & 15) * 8;
        *reinterpret_cast<uint4*>(&Qh[r * AAS + cg]) =
            *reinterpret_cast<const uint4*>(&Qhg[(qrow0 + r) * DIM + h * 128 + cg]);
        *reinterpret_cast<uint4*>(&Ql[r * AAS + cg]) =
            *reinterpret_cast<const uint4*>(&Qlg[(qrow0 + r) * DIM + h * 128 + cg]);
    }

    float l0 = 0.f, l1 = 0.f;
    float o[8][4] = {};

    const int r0 = wr * 16 + (lane >> 2);
    const int c0 = (lane & 3) * 2;
    const size_t gb = ((size_t)bh * T + (size_t)qt * 64) * T;

    #pragma unroll 1
    for (int kt = 0; kt < 64; kt++) {
        CP_WAIT0();
        __syncthreads();
        if (kt < 63) {
            load_kv((kt + 1) & 1, krow0 + (kt + 1) * 32);
            CP_COMMIT();
        }

        const __nv_bfloat16* Kbh = sm + AT_KV + (kt & 1) * AT_KVS;
        const __nv_bfloat16* Kbl = Kbh + 32 * AAS;
        const __nv_bfloat16* Vbh = Kbh + 2 * 32 * AAS;
        const __nv_bfloat16* Vbl = Kbh + 3 * 32 * AAS;

        float s[2][4];
        #pragma unroll
        for (int nt = 0; nt < 2; nt++)
            #pragma unroll
            for (int j = 0; j < 4; j++) s[nt][j] = 0.f;

        #pragma unroll
        for (int kk = 0; kk < 8; kk++) {
            uint32_t ah[4], al[4];
            int ar = wr * 16 + (lane & 15), ac = kk * 16 + (lane >> 4) * 8;
            ldsm_x4(ah, smem_u32(&Qh[ar * AAS + ac]));
            ldsm_x4(al, smem_u32(&Ql[ar * AAS + ac]));
            int br = wc * 16 + (lane & 15), bc = kk * 16 + (lane >> 4) * 8;
            uint32_t b4h[4], b4l[4];
            ldsm_x4(b4h, smem_u32(&Kbh[br * AAS + bc]));
            ldsm_x4(b4l, smem_u32(&Kbl[br * AAS + bc]));
            uint32_t be_h[2] = {b4h[0], b4h[2]}, bo_h[2] = {b4h[1], b4h[3]};
            uint32_t be_l[2] = {b4l[0], b4l[2]}, bo_l[2] = {b4l[1], b4l[3]};
            mma16816(s[0], ah, be_h); mma16816(s[0], ah, be_l); mma16816(s[0], al, be_h);
            mma16816(s[1], ah, bo_h); mma16816(s[1], ah, bo_l); mma16816(s[1], al, bo_h);
        }

        #pragma unroll
        for (int nt = 0; nt < 2; nt++) {
            s[nt][0] = __expf(s[nt][0]); s[nt][1] = __expf(s[nt][1]);
            s[nt][2] = __expf(s[nt][2]); s[nt][3] = __expf(s[nt][3]);
            l0 += s[nt][0] + s[nt][1];
            l1 += s[nt][2] + s[nt][3];
            int colL = wc * 16 + nt * 8 + c0;
            __nv_bfloat162 h0 = pack_hi(s[nt][0], s[nt][1]), lo0 = pack_lo(s[nt][0], s[nt][1], h0);
            __nv_bfloat162 h1 = pack_hi(s[nt][2], s[nt][3]), lo1 = pack_lo(s[nt][2], s[nt][3], h1);
            *reinterpret_cast<__nv_bfloat162*>(&Ph[r0 * APS + colL]) = h0;
            *reinterpret_cast<__nv_bfloat162*>(&Pl[r0 * APS + colL]) = lo0;
            *reinterpret_cast<__nv_bfloat162*>(&Ph[(r0 + 8) * APS + colL]) = h1;
            *reinterpret_cast<__nv_bfloat162*>(&Pl[(r0 + 8) * APS + colL]) = lo1;
        }
        __syncthreads();

        #pragma unroll
        for (int kc = 0; kc < 2; kc++) {
            uint32_t ph4[4], pl4[4];
            int pr = wr * 16 + (lane & 15), pc = kc * 16 + (lane >> 4) * 8;
            ldsm_x4(ph4, smem_u32(&Ph[pr * APS + pc]));
            ldsm_x4(pl4, smem_u32(&Pl[pr * APS + pc]));
            #pragma unroll
            for (int p = 0; p < 4; p++) {
                int vr = kc * 16 + (lane & 15);
                int vc = wc * 64 + p * 16 + (lane >> 4) * 8;
                uint32_t v4h[4], v4l[4];
                ldsm_x4t(v4h, smem_u32(&Vbh[vr * AAS + vc]));
                ldsm_x4t(v4l, smem_u32(&Vbl[vr * AAS + vc]));
                uint32_t be_h[2] = {v4h[0], v4h[1]}, bo_h[2] = {v4h[2], v4h[3]};
                uint32_t be_l[2] = {v4l[0], v4l[1]}, bo_l[2] = {v4l[2], v4l[3]};
                mma16816(o[2*p],   ph4, be_h); mma16816(o[2*p],   ph4, be_l); mma16816(o[2*p],   pl4, be_h);
                mma16816(o[2*p+1], ph4, bo_h); mma16816(o[2*p+1], ph4, bo_l); mma16816(o[2*p+1], pl4, bo_h);
            }
        }

        #pragma unroll
        for (int nt = 0; nt < 2; nt++) {
            int col = kt * 32 + wc * 16 + nt * 8 + c0;
            *reinterpret_cast<float2*>(&AW[gb + (size_t)r0 * T + col]) =
                make_float2(s[nt][0], s[nt][1]);
            *reinterpret_cast<float2*>(&AW[gb + (size_t)(r0 + 8) * T + col]) =
                make_float2(s[nt][2], s[nt][3]);
        }
    }

    l0 += __shfl_xor_sync(0xffffffffu, l0, 1);
    l0 += __shfl_xor_sync(0xffffffffu, l0, 2);
    l1 += __shfl_xor_sync(0xffffffffu, l1, 1);
    l1 += __shfl_xor_sync(0xffffffffu, l1, 2);
    __syncthreads();
    if ((lane & 3) == 0) {
        lp[wc * 64 + r0] = l0;
        lp[wc * 64 + r0 + 8] = l1;
    }
    __syncthreads();

    if (tid < 64) {
        float il = 1.f / (lp[tid] + lp[64 + tid]);
        invLg[(size_t)bh * T + qt * 64 + tid] = il;
    }

    const float ilA = 1.f / (lp[r0] + lp[64 + r0]);
    const float ilB = 1.f / (lp[r0 + 8] + lp[64 + r0 + 8]);

    #pragma unroll
    for (int nt = 0; nt < 8; nt++) {
        int c = h * 128 + wc * 64 + nt * 8 + c0;
        float v00 = o[nt][0] * ilA, v01 = o[nt][1] * ilA;
        float v10 = o[nt][2] * ilB, v11 = o[nt][3] * ilB;
        __nv_bfloat162 h0 = pack_hi(v00, v01), l0v = pack_lo(v00, v01, h0);
        __nv_bfloat162 h1 = pack_hi(v10, v11), l1v = pack_lo(v10, v11, h1);
        *reinterpret_cast<__nv_bfloat162*>(&Ohg[(qrow0 + r0) * DIM + c]) = h0;
        *reinterpret_cast<__nv_bfloat162*>(&Olg[(qrow0 + r0) * DIM + c]) = l0v;
        *reinterpret_cast<__nv_bfloat162*>(&Ohg[(qrow0 + r0 + 8) * DIM + c]) = h1;
        *reinterpret_cast<__nv_bfloat162*>(&Olg[(qrow0 + r0 + 8) * DIM + c]) = l1v;
    }
}

// ---------------------------------------------------------------------------
// launch
// ---------------------------------------------------------------------------
extern "C" void kernel_launch(void* const* d_in, const int* in_sizes, int n_in,
                              void* d_out, int out_size)
{
    const float* q  = (const float*)d_in[0];
    const float* k  = (const float*)d_in[1];
    const float* v  = (const float*)d_in[2];
    const float* Wq = (const float*)d_in[3];
    const float* bq = (const float*)d_in[4];
    const float* Wk = (const float*)d_in[5];
    const float* bk = (const float*)d_in[6];
    const float* Wv = (const float*)d_in[7];
    const float* bv = (const float*)d_in[8];
    const float* Wo = (const float*)d_in[9];
    const float* bo = (const float*)d_in[10];

    float* out   = (float*)d_out;
    float* attnW = out + (size_t)BT * DIM;

    __nv_bfloat16 *qh, *ql, *kh, *kl, *vh, *vl;
    __nv_bfloat16 *Wqh, *Wql, *Wkh, *Wkl, *Wvh, *Wvl, *Woh, *Wol;
    __nv_bfloat16 *Qh, *Ql, *Kh, *Kl, *Vh, *Vl, *Oh, *Ol;
    float* invL;
    cudaGetSymbolAddress((void**)&qh, g_qh);   cudaGetSymbolAddress((void**)&ql, g_ql);
    cudaGetSymbolAddress((void**)&kh, g_kh);   cudaGetSymbolAddress((void**)&kl, g_kl);
    cudaGetSymbolAddress((void**)&vh, g_vh);   cudaGetSymbolAddress((void**)&vl, g_vl);
    cudaGetSymbolAddress((void**)&Wqh, g_Wqh); cudaGetSymbolAddress((void**)&Wql, g_Wql);
    cudaGetSymbolAddress((void**)&Wkh, g_Wkh); cudaGetSymbolAddress((void**)&Wkl, g_Wkl);
    cudaGetSymbolAddress((void**)&Wvh, g_Wvh); cudaGetSymbolAddress((void**)&Wvl, g_Wvl);
    cudaGetSymbolAddress((void**)&Woh, g_Woh); cudaGetSymbolAddress((void**)&Wol, g_Wol);
    cudaGetSymbolAddress((void**)&Qh, g_Qh);   cudaGetSymbolAddress((void**)&Ql, g_Ql);
    cudaGetSymbolAddress((void**)&Kh, g_Kh);   cudaGetSymbolAddress((void**)&Kl, g_Kl);
    cudaGetSymbolAddress((void**)&Vh, g_Vh);   cudaGetSymbolAddress((void**)&Vl, g_Vl);
    cudaGetSymbolAddress((void**)&Oh, g_Oh);   cudaGetSymbolAddress((void**)&Ol, g_Ol);
    cudaGetSymbolAddress((void**)&invL, g_invL);

    cudaFuncSetAttribute(gemm_qkv_kernel, cudaFuncAttributeMaxDynamicSharedMemorySize,
                         G_SMEM_BYTES);
    cudaFuncSetAttribute(gemm_wo_norm_kernel, cudaFuncAttributeMaxDynamicSharedMemorySize,
                         G_SMEM_BYTES);
    cudaFuncSetAttribute(attn_kernel, cudaFuncAttributeMaxDynamicSharedMemorySize,
                         ATTN_SMEM_BYTES);

    const float scale = 0.08838834764831845f;  // 1/sqrt(128)

    // splits (fp32 -> bf16 hi/lo): 3 fused launches
    const int nBD = BT * DIM / 4, nDD = DIM * DIM / 4, nDK = DIM * KVDIM / 4;
    split3_kernel<<<dim3((nBD + 255) / 256, 3), 256>>>(
        q, qh, ql, k, kh, kl, v, vh, vl, nBD);
    split3_kernel<<<dim3((nDD + 255) / 256, 2), 256>>>(
        Wq, Wqh, Wql, Wo, Woh, Wol, nullptr, nullptr, nullptr, nDD);
    split3_kernel<<<dim3((nDK + 255) / 256, 2), 256>>>(
        Wk, Wkh, Wkl, Wv, Wvh, Wvl, nullptr, nullptr, nullptr, nDK);

    // fused Q/K/V projections (one launch, one wave tail)
    gemm_qkv_kernel<<<768, 256, G_SMEM_BYTES>>>(
        qh, ql, Wqh, Wql, bq, Qh, Ql,
        kh, kl, Wkh, Wkl, bk, Kh, Kl,
        vh, vl, Wvh, Wvl, bv, Vh, Vl,
        scale);

    // attention (raw exp -> AW, O pre-split & scaled)
    attn_kernel<<<dim3(T / 64, 32), 256, ATTN_SMEM_BYTES>>>(
        Qh, Ql, Kh, Kl, Vh, Vl, attnW, invL, Oh, Ol);

    // fused Wo projection + AW normalize (memory-bound CTAs soak idle HBM)
    gemm_wo_norm_kernel<<<512 + NORM_CTAS, 256, G_SMEM_BYTES>>>(
        Oh, Ol, Woh, Wol, bo, out, attnW, invL);
}

// round 9
// speedup vs baseline: 1.7631x; 1.0018x over previous
#include <cuda_runtime.h>
#include <cuda_bf16.h>
#include <cstdint>
#include <cmath>

// ---------------------------------------------------------------------------
// GroupedQueryAttention: B=2, T=2048, DIM=2048, H=16, KH=4, DK=DV=128
// d_out = [ out (2,2048,2048) fp32 | attn_weight (2,16,2048,2048) fp32 ]
//
// Round 7: kernel fusion for pipe overlap —
//   * Q/K/V projections in ONE launch (one wave tail)
//   * Wo projection + AW normalize in ONE launch (normalize soaks idle HBM
//     under the tensor-bound gemm)
//   * GEMM mainloop: single __syncthreads per BK iteration
// Attention unchanged from round 6. Split-bf16 3-term numerics everywhere.
// ---------------------------------------------------------------------------

#define BT 4096
#define DIM 2048
#define KVDIM 512
#define T 2048

// ---- device scratch (no allocation allowed) ----
__device__ __nv_bfloat16 g_qh[BT * DIM],  g_ql[BT * DIM];
__device__ __nv_bfloat16 g_kh[BT * DIM],  g_kl[BT * DIM];
__device__ __nv_bfloat16 g_vh[BT * DIM],  g_vl[BT * DIM];
__device__ __nv_bfloat16 g_Wqh[DIM * DIM], g_Wql[DIM * DIM];
__device__ __nv_bfloat16 g_Wkh[DIM * KVDIM], g_Wkl[DIM * KVDIM];
__device__ __nv_bfloat16 g_Wvh[DIM * KVDIM], g_Wvl[DIM * KVDIM];
__device__ __nv_bfloat16 g_Woh[DIM * DIM], g_Wol[DIM * DIM];
__device__ __nv_bfloat16 g_Qh[BT * DIM],  g_Ql[BT * DIM];
__device__ __nv_bfloat16 g_Kh[BT * KVDIM], g_Kl[BT * KVDIM];
__device__ __nv_bfloat16 g_Vh[BT * KVDIM], g_Vl[BT * KVDIM];
__device__ __nv_bfloat16 g_Oh[BT * DIM],  g_Ol[BT * DIM];
__device__ float g_invL[32 * T];

// ---------------------------------------------------------------------------
// helpers
// ---------------------------------------------------------------------------
__device__ __forceinline__ uint32_t smem_u32(const void* p) {
    return (uint32_t)__cvta_generic_to_shared(p);
}
__device__ __forceinline__ void ldsm_x4(uint32_t* r, uint32_t addr) {
    asm volatile("ldmatrix.sync.aligned.m8n8.x4.shared.b16 {%0,%1,%2,%3}, [%4];"
                 : "=r"(r[0]), "=r"(r[1]), "=r"(r[2]), "=r"(r[3]) : "r"(addr));
}
__device__ __forceinline__ void ldsm_x4t(uint32_t* r, uint32_t addr) {
    asm volatile("ldmatrix.sync.aligned.m8n8.x4.trans.shared.b16 {%0,%1,%2,%3}, [%4];"
                 : "=r"(r[0]), "=r"(r[1]), "=r"(r[2]), "=r"(r[3]) : "r"(addr));
}
__device__ __forceinline__ void mma16816(float* c, const uint32_t* a, const uint32_t* b) {
    asm volatile(
        "mma.sync.aligned.m16n8k16.row.col.f32.bf16.bf16.f32 "
        "{%0,%1,%2,%3}, {%4,%5,%6,%7}, {%8,%9}, {%0,%1,%2,%3};\n"
        : "+f"(c[0]), "+f"(c[1]), "+f"(c[2]), "+f"(c[3])
        : "r"(a[0]), "r"(a[1]), "r"(a[2]), "r"(a[3]), "r"(b[0]), "r"(b[1]));
}
__device__ __forceinline__ void cp16(uint32_t saddr, const void* g) {
    asm volatile("cp.async.cg.shared.global [%0], [%1], 16;" :: "r"(saddr), "l"(g));
}
#define CP_COMMIT() asm volatile("cp.async.commit_group;")
#define CP_WAIT0()  asm volatile("cp.async.wait_group 0;")

__device__ __forceinline__ __nv_bfloat162 pack_hi(float a, float b) {
    __nv_bfloat162 r; r.x = __float2bfloat16(a); r.y = __float2bfloat16(b); return r;
}
__device__ __forceinline__ __nv_bfloat162 pack_lo(float a, float b, __nv_bfloat162 h) {
    __nv_bfloat162 r;
    r.x = __float2bfloat16(a - __bfloat162float(h.x));
    r.y = __float2bfloat16(b - __bfloat162float(h.y));
    return r;
}

// ---------------------------------------------------------------------------
// split: fp32 -> bf16 hi/lo; blockIdx.y selects one of up to 3 tensors
// ---------------------------------------------------------------------------
__global__ void split3_kernel(
    const float* __restrict__ s0, __nv_bfloat16* __restrict__ h0, __nv_bfloat16* __restrict__ l0,
    const float* __restrict__ s1, __nv_bfloat16* __restrict__ h1, __nv_bfloat16* __restrict__ l1,
    const float* __restrict__ s2, __nv_bfloat16* __restrict__ h2, __nv_bfloat16* __restrict__ l2,
    int n4)
{
    int i = blockIdx.x * blockDim.x + threadIdx.x;
    if (i >= n4) return;
    const float* src; __nv_bfloat16 *h, *l;
    if (blockIdx.y == 0)      { src = s0; h = h0; l = l0; }
    else if (blockIdx.y == 1) { src = s1; h = h1; l = l1; }
    else                      { src = s2; h = h2; l = l2; }
    float4 v = reinterpret_cast<const float4*>(src)[i];
    __nv_bfloat162 ha = pack_hi(v.x, v.y), hb = pack_hi(v.z, v.w);
    __nv_bfloat162 la = pack_lo(v.x, v.y, ha), lb = pack_lo(v.z, v.w, hb);
    uint2 hv = make_uint2(*(uint32_t*)&ha, *(uint32_t*)&hb);
    uint2 lv = make_uint2(*(uint32_t*)&la, *(uint32_t*)&lb);
    *reinterpret_cast<uint2*>(&h[(size_t)i * 4]) = hv;
    *reinterpret_cast<uint2*>(&l[(size_t)i * 4]) = lv;
}

// ---------------------------------------------------------------------------
// GEMM body: C[M,N] = (A[M,K] @ W[K,N] + bias) * scale, pre-split operands.
// BM=128 BN=128 BK=32, 256 threads, cp.async double-buffered,
// ONE __syncthreads per BK iteration. 3-term split MMA.
// ---------------------------------------------------------------------------
#define GAS 40
#define GBS 136
#define G_STG (128 * GAS * 2 + 32 * GBS * 2)
#define G_SMEM_BYTES (2 * G_STG * 2 + 512)

__device__ __forceinline__ void gemm_body(
    const __nv_bfloat16* __restrict__ Ahg, const __nv_bfloat16* __restrict__ Alg,
    const __nv_bfloat16* __restrict__ Bhg, const __nv_bfloat16* __restrict__ Blg,
    const float* __restrict__ bias,
    float* __restrict__ Cf, __nv_bfloat16* __restrict__ Ch, __nv_bfloat16* __restrict__ Cl,
    float scale, int N, int K, int bm0, int bn0, __nv_bfloat16* sm)
{
    float* biasS = (float*)(sm + 2 * G_STG);

    const int tid = threadIdx.x;
    const int lane = tid & 31;
    const int wid = tid >> 5;
    const int wm = wid >> 2;
    const int wn = wid & 3;

    if (tid < 128) biasS[tid] = bias[bn0 + tid];

    auto load_stage = [&](int s, int kt) {
        __nv_bfloat16* sAh = sm + s * G_STG;
        __nv_bfloat16* sAl = sAh + 128 * GAS;
        __nv_bfloat16* sBh = sAl + 128 * GAS;
        __nv_bfloat16* sBl = sBh + 32 * GBS;
        #pragma unroll
        for (int i = 0; i < 2; i++) {
            int idx = i * 256 + tid;
            int r = idx >> 2, cg = (idx & 3) * 8;
            cp16(smem_u32(&sAh[r * GAS + cg]), &Ahg[(size_t)(bm0 + r) * K + kt + cg]);
            cp16(smem_u32(&sAl[r * GAS + cg]), &Alg[(size_t)(bm0 + r) * K + kt + cg]);
        }
        #pragma unroll
        for (int i = 0; i < 2; i++) {
            int idx = i * 256 + tid;
            int r = idx >> 4, cg = (idx & 15) * 8;
            cp16(smem_u32(&sBh[r * GBS + cg]), &Bhg[(size_t)(kt + r) * N + bn0 + cg]);
            cp16(smem_u32(&sBl[r * GBS + cg]), &Blg[(size_t)(kt + r) * N + bn0 + cg]);
        }
    };

    float acc[4][4][4] = {};
    const int nk = K >> 5;

    load_stage(0, 0);
    CP_COMMIT();

    for (int it = 0; it < nk; it++) {
        CP_WAIT0();
        __syncthreads();
        if (it + 1 < nk) {
            load_stage((it + 1) & 1, (it + 1) * 32);
            CP_COMMIT();
        }

        const __nv_bfloat16* sAh = sm + (it & 1) * G_STG;
        const __nv_bfloat16* sAl = sAh + 128 * GAS;
        const __nv_bfloat16* sBh = sAl + 128 * GAS;
        const __nv_bfloat16* sBl = sBh + 32 * GBS;

        #pragma unroll
        for (int ks = 0; ks < 2; ks++) {
            uint32_t ah[4][4], al[4][4];
            #pragma unroll
            for (int mt = 0; mt < 4; mt++) {
                int r = wm * 64 + mt * 16 + (lane & 15);
                int c = ks * 16 + (lane >> 4) * 8;
                ldsm_x4(ah[mt], smem_u32(&sAh[r * GAS + c]));
                ldsm_x4(al[mt], smem_u32(&sAl[r * GAS + c]));
            }
            uint32_t bh[4][2], bl[4][2];
            #pragma unroll
            for (int p = 0; p < 2; p++) {
                int r = ks * 16 + (lane & 15);
                int c = wn * 32 + p * 16 + (lane >> 4) * 8;
                uint32_t t4[4];
                ldsm_x4t(t4, smem_u32(&sBh[r * GBS + c]));
                bh[2*p][0] = t4[0]; bh[2*p][1] = t4[1];
                bh[2*p+1][0] = t4[2]; bh[2*p+1][1] = t4[3];
                ldsm_x4t(t4, smem_u32(&sBl[r * GBS + c]));
                bl[2*p][0] = t4[0]; bl[2*p][1] = t4[1];
                bl[2*p+1][0] = t4[2]; bl[2*p+1][1] = t4[3];
            }
            #pragma unroll
            for (int mt = 0; mt < 4; mt++)
                #pragma unroll
                for (int nt = 0; nt < 4; nt++) {
                    mma16816(acc[mt][nt], ah[mt], bh[nt]);
                    mma16816(acc[mt][nt], ah[mt], bl[nt]);
                    mma16816(acc[mt][nt], al[mt], bh[nt]);
                }
        }
    }

    #pragma unroll
    for (int mt = 0; mt < 4; mt++)
        #pragma unroll
        for (int nt = 0; nt < 4; nt++) {
            int row = bm0 + wm * 64 + mt * 16 + (lane >> 2);
            int colL = wn * 32 + nt * 8 + (lane & 3) * 2;
            int col = bn0 + colL;
            float b0 = biasS[colL], b1 = biasS[colL + 1];
            float v00 = (acc[mt][nt][0] + b0) * scale;
            float v01 = (acc[mt][nt][1] + b1) * scale;
            float v10 = (acc[mt][nt][2] + b0) * scale;
            float v11 = (acc[mt][nt][3] + b1) * scale;
            if (Cf) {
                *reinterpret_cast<float2*>(&Cf[(size_t)row * N + col]) = make_float2(v00, v01);
                *reinterpret_cast<float2*>(&Cf[(size_t)(row + 8) * N + col]) = make_float2(v10, v11);
            } else {
                __nv_bfloat162 h0 = pack_hi(v00, v01), l0 = pack_lo(v00, v01, h0);
                *reinterpret_cast<__nv_bfloat162*>(&Ch[(size_t)row * N + col]) = h0;
                *reinterpret_cast<__nv_bfloat162*>(&Cl[(size_t)row * N + col]) = l0;
                __nv_bfloat162 h1 = pack_hi(v10, v11), l1 = pack_lo(v10, v11, h1);
                *reinterpret_cast<__nv_bfloat162*>(&Ch[(size_t)(row + 8) * N + col]) = h1;
                *reinterpret_cast<__nv_bfloat162*>(&Cl[(size_t)(row + 8) * N + col]) = l1;
            }
        }
}

// ---------------------------------------------------------------------------
// Fused Q/K/V projections: 768 CTAs in one launch.
//   id < 512        : Q tile  (16 n-tiles x 32 m-tiles), scaled by 1/sqrt(dk)
//   512 <= id < 640 : K tile  (4 x 32)
//   640 <= id < 768 : V tile  (4 x 32)
// ---------------------------------------------------------------------------
__global__ __launch_bounds__(256) void gemm_qkv_kernel(
    const __nv_bfloat16* __restrict__ qh, const __nv_bfloat16* __restrict__ ql,
    const __nv_bfloat16* __restrict__ Wqh, const __nv_bfloat16* __restrict__ Wql,
    const float* __restrict__ bq,
    __nv_bfloat16* __restrict__ Qh, __nv_bfloat16* __restrict__ Ql_,
    const __nv_bfloat16* __restrict__ kh, const __nv_bfloat16* __restrict__ kl,
    const __nv_bfloat16* __restrict__ Wkh, const __nv_bfloat16* __restrict__ Wkl,
    const float* __restrict__ bk,
    __nv_bfloat16* __restrict__ Kh, __nv_bfloat16* __restrict__ Kl,
    const __nv_bfloat16* __restrict__ vh, const __nv_bfloat16* __restrict__ vl,
    const __nv_bfloat16* __restrict__ Wvh, const __nv_bfloat16* __restrict__ Wvl,
    const float* __restrict__ bv,
    __nv_bfloat16* __restrict__ Vh, __nv_bfloat16* __restrict__ Vl,
    float qscale)
{
    extern __shared__ __nv_bfloat16 sm[];
    const int id = blockIdx.x;
    if (id < 512) {
        gemm_body(qh, ql, Wqh, Wql, bq, nullptr, Qh, Ql_, qscale, DIM, DIM,
                  (id >> 4) * 128, (id & 15) * 128, sm);
    } else if (id < 640) {
        int t = id - 512;
        gemm_body(kh, kl, Wkh, Wkl, bk, nullptr, Kh, Kl, 1.f, KVDIM, DIM,
                  (t >> 2) * 128, (t & 3) * 128, sm);
    } else {
        int t = id - 640;
        gemm_body(vh, vl, Wvh, Wvl, bv, nullptr, Vh, Vl, 1.f, KVDIM, DIM,
                  (t >> 2) * 128, (t & 3) * 128, sm);
    }
}

// ---------------------------------------------------------------------------
// Fused Wo projection + AW normalize: 512 gemm CTAs + 1024 normalize CTAs.
// Normalize CTAs soak idle DRAM bandwidth under the tensor-bound gemm.
// ---------------------------------------------------------------------------
#define NORM_CTAS 1024

__global__ __launch_bounds__(256) void gemm_wo_norm_kernel(
    const __nv_bfloat16* __restrict__ Oh, const __nv_bfloat16* __restrict__ Ol,
    const __nv_bfloat16* __restrict__ Woh, const __nv_bfloat16* __restrict__ Wol,
    const float* __restrict__ bo, float* __restrict__ out,
    float* __restrict__ AW, const float* __restrict__ invL)
{
    extern __shared__ __nv_bfloat16 sm[];
    const int id = blockIdx.x;
    if (id < 512) {
        gemm_body(Oh, Ol, Woh, Wol, bo, out, nullptr, nullptr, 1.f, DIM, DIM,
                  (id >> 4) * 128, (id & 15) * 128, sm);
    } else {
        const size_t nf4 = (size_t)32 * T * T / 4;          // 33,554,432 float4
        const size_t stride = (size_t)NORM_CTAS * 256;
        for (size_t i4 = (size_t)(id - 512) * 256 + threadIdx.x; i4 < nf4; i4 += stride) {
            int row = (int)((i4 * 4) >> 11);
            float il = __ldg(&invL[row]);
            float4 v = reinterpret_cast<float4*>(AW)[i4];
            v.x *= il; v.y *= il; v.z *= il; v.w *= il;
            reinterpret_cast<float4*>(AW)[i4] = v;
        }
    }
}

// ---------------------------------------------------------------------------
// Attention (single pass): grid (32 qtiles x 32 bh), 256 threads (8 warps 4x2).
// 32-key double-buffered KV tiles; total smem 115.2KB => 2 CTAs/SM.
// ---------------------------------------------------------------------------
#define AAS 136
#define APS 40
#define AT_Q   0
#define AT_KV  (2 * 64 * AAS)
#define AT_KVS (4 * 32 * AAS)
#define AT_P   (AT_KV + 2 * AT_KVS)
#define AT_LP  (AT_P + 2 * 64 * APS)
#define ATTN_SMEM_BYTES (AT_LP * 2 + 512)

__global__ __launch_bounds__(256, 2) void attn_kernel(
    const __nv_bfloat16* __restrict__ Qhg, const __nv_bfloat16* __restrict__ Qlg,
    const __nv_bfloat16* __restrict__ Khg, const __nv_bfloat16* __restrict__ Klg,
    const __nv_bfloat16* __restrict__ Vhg, const __nv_bfloat16* __restrict__ Vlg,
    float* __restrict__ AW, float* __restrict__ invLg,
    __nv_bfloat16* __restrict__ Ohg, __nv_bfloat16* __restrict__ Olg)
{
    extern __shared__ __nv_bfloat16 sm[];
    __nv_bfloat16* Qh = sm + AT_Q;
    __nv_bfloat16* Ql = Qh + 64 * AAS;
    __nv_bfloat16* Ph = sm + AT_P;
    __nv_bfloat16* Pl = Ph + 64 * APS;
    float* lp = (float*)(sm + AT_LP);

    const int tid = threadIdx.x;
    const int lane = tid & 31;
    const int wid = tid >> 5;
    const int wr = wid & 3;
    const int wc = wid >> 2;
    const int qt = blockIdx.x;
    const int bh = blockIdx.y;
    const int b = bh >> 4, h = bh & 15, kv = h >> 2;

    const size_t qrow0 = (size_t)b * T + qt * 64;
    const size_t krow0 = (size_t)b * T;
    const int kcol = kv * 128;

    auto load_kv = [&](int s, size_t row0) {
        __nv_bfloat16* base = sm + AT_KV + s * AT_KVS;
        #pragma unroll
        for (int i = 0; i < 2; i++) {
            int idx = i * 256 + tid;
            int r = idx >> 4, cg = (idx & 15) * 8;
            cp16(smem_u32(&base[r * AAS + cg]),            &Khg[(row0 + r) * KVDIM + kcol + cg]);
            cp16(smem_u32(&base[32*AAS + r * AAS + cg]),   &Klg[(row0 + r) * KVDIM + kcol + cg]);
            cp16(smem_u32(&base[2*32*AAS + r * AAS + cg]), &Vhg[(row0 + r) * KVDIM + kcol + cg]);
            cp16(smem_u32(&base[3*32*AAS + r * AAS + cg]), &Vlg[(row0 + r) * KVDIM + kcol + cg]);
        }
    };

    load_kv(0, krow0);
    CP_COMMIT();
    #pragma unroll
    for (int i = 0; i < 4; i++) {
        int idx = i * 256 + tid;
        int r = idx >> 4, cg = (idx & 15) * 8;
        *reinterpret_cast<uint4*>(&Qh[r * AAS + cg]) =
            *reinterpret_cast<const uint4*>(&Qhg[(qrow0 + r) * DIM + h * 128 + cg]);
        *reinterpret_cast<uint4*>(&Ql[r * AAS + cg]) =
            *reinterpret_cast<const uint4*>(&Qlg[(qrow0 + r) * DIM + h * 128 + cg]);
    }

    float l0 = 0.f, l1 = 0.f;
    float o[8][4] = {};

    const int r0 = wr * 16 + (lane >> 2);
    const int c0 = (lane & 3) * 2;
    const size_t gb = ((size_t)bh * T + (size_t)qt * 64) * T;

    #pragma unroll 1
    for (int kt = 0; kt < 64; kt++) {
        CP_WAIT0();
        __syncthreads();
        if (kt < 63) {
            load_kv((kt + 1) & 1, krow0 + (kt + 1) * 32);
            CP_COMMIT();
        }

        const __nv_bfloat16* Kbh = sm + AT_KV + (kt & 1) * AT_KVS;
        const __nv_bfloat16* Kbl = Kbh + 32 * AAS;
        const __nv_bfloat16* Vbh = Kbh + 2 * 32 * AAS;
        const __nv_bfloat16* Vbl = Kbh + 3 * 32 * AAS;

        float s[2][4];
        #pragma unroll
        for (int nt = 0; nt < 2; nt++)
            #pragma unroll
            for (int j = 0; j < 4; j++) s[nt][j] = 0.f;

        #pragma unroll
        for (int kk = 0; kk < 8; kk++) {
            uint32_t ah[4], al[4];
            int ar = wr * 16 + (lane & 15), ac = kk * 16 + (lane >> 4) * 8;
            ldsm_x4(ah, smem_u32(&Qh[ar * AAS + ac]));
            ldsm_x4(al, smem_u32(&Ql[ar * AAS + ac]));
            int br = wc * 16 + (lane & 15), bc = kk * 16 + (lane >> 4) * 8;
            uint32_t b4h[4], b4l[4];
            ldsm_x4(b4h, smem_u32(&Kbh[br * AAS + bc]));
            ldsm_x4(b4l, smem_u32(&Kbl[br * AAS + bc]));
            uint32_t be_h[2] = {b4h[0], b4h[2]}, bo_h[2] = {b4h[1], b4h[3]};
            uint32_t be_l[2] = {b4l[0], b4l[2]}, bo_l[2] = {b4l[1], b4l[3]};
            mma16816(s[0], ah, be_h); mma16816(s[0], ah, be_l); mma16816(s[0], al, be_h);
            mma16816(s[1], ah, bo_h); mma16816(s[1], ah, bo_l); mma16816(s[1], al, bo_h);
        }

        #pragma unroll
        for (int nt = 0; nt < 2; nt++) {
            s[nt][0] = __expf(s[nt][0]); s[nt][1] = __expf(s[nt][1]);
            s[nt][2] = __expf(s[nt][2]); s[nt][3] = __expf(s[nt][3]);
            l0 += s[nt][0] + s[nt][1];
            l1 += s[nt][2] + s[nt][3];
            int colL = wc * 16 + nt * 8 + c0;
            __nv_bfloat162 h0 = pack_hi(s[nt][0], s[nt][1]), lo0 = pack_lo(s[nt][0], s[nt][1], h0);
            __nv_bfloat162 h1 = pack_hi(s[nt][2], s[nt][3]), lo1 = pack_lo(s[nt][2], s[nt][3], h1);
            *reinterpret_cast<__nv_bfloat162*>(&Ph[r0 * APS + colL]) = h0;
            *reinterpret_cast<__nv_bfloat162*>(&Pl[r0 * APS + colL]) = lo0;
            *reinterpret_cast<__nv_bfloat162*>(&Ph[(r0 + 8) * APS + colL]) = h1;
            *reinterpret_cast<__nv_bfloat162*>(&Pl[(r0 + 8) * APS + colL]) = lo1;
        }
        __syncthreads();

        #pragma unroll
        for (int kc = 0; kc < 2; kc++) {
            uint32_t ph4[4], pl4[4];
            int pr = wr * 16 + (lane & 15), pc = kc * 16 + (lane >> 4) * 8;
            ldsm_x4(ph4, smem_u32(&Ph[pr * APS + pc]));
            ldsm_x4(pl4, smem_u32(&Pl[pr * APS + pc]));
            #pragma unroll
            for (int p = 0; p < 4; p++) {
                int vr = kc * 16 + (lane & 15);
                int vc = wc * 64 + p * 16 + (lane >> 4) * 8;
                uint32_t v4h[4], v4l[4];
                ldsm_x4t(v4h, smem_u32(&Vbh[vr * AAS + vc]));
                ldsm_x4t(v4l, smem_u32(&Vbl[vr * AAS + vc]));
                uint32_t be_h[2] = {v4h[0], v4h[1]}, bo_h[2] = {v4h[2], v4h[3]};
                uint32_t be_l[2] = {v4l[0], v4l[1]}, bo_l[2] = {v4l[2], v4l[3]};
                mma16816(o[2*p],   ph4, be_h); mma16816(o[2*p],   ph4, be_l); mma16816(o[2*p],   pl4, be_h);
                mma16816(o[2*p+1], ph4, bo_h); mma16816(o[2*p+1], ph4, bo_l); mma16816(o[2*p+1], pl4, bo_h);
            }
        }

        #pragma unroll
        for (int nt = 0; nt < 2; nt++) {
            int col = kt * 32 + wc * 16 + nt * 8 + c0;
            *reinterpret_cast<float2*>(&AW[gb + (size_t)r0 * T + col]) =
                make_float2(s[nt][0], s[nt][1]);
            *reinterpret_cast<float2*>(&AW[gb + (size_t)(r0 + 8) * T + col]) =
                make_float2(s[nt][2], s[nt][3]);
        }
    }

    l0 += __shfl_xor_sync(0xffffffffu, l0, 1);
    l0 += __shfl_xor_sync(0xffffffffu, l0, 2);
    l1 += __shfl_xor_sync(0xffffffffu, l1, 1);
    l1 += __shfl_xor_sync(0xffffffffu, l1, 2);
    __syncthreads();
    if ((lane & 3) == 0) {
        lp[wc * 64 + r0] = l0;
        lp[wc * 64 + r0 + 8] = l1;
    }
    __syncthreads();

    if (tid < 64) {
        float il = 1.f / (lp[tid] + lp[64 + tid]);
        invLg[(size_t)bh * T + qt * 64 + tid] = il;
    }

    const float ilA = 1.f / (lp[r0] + lp[64 + r0]);
    const float ilB = 1.f / (lp[r0 + 8] + lp[64 + r0 + 8]);

    #pragma unroll
    for (int nt = 0; nt < 8; nt++) {
        int c = h * 128 + wc * 64 + nt * 8 + c0;
        float v00 = o[nt][0] * ilA, v01 = o[nt][1] * ilA;
        float v10 = o[nt][2] * ilB, v11 = o[nt][3] * ilB;
        __nv_bfloat162 h0 = pack_hi(v00, v01), l0v = pack_lo(v00, v01, h0);
        __nv_bfloat162 h1 = pack_hi(v10, v11), l1v = pack_lo(v10, v11, h1);
        *reinterpret_cast<__nv_bfloat162*>(&Ohg[(qrow0 + r0) * DIM + c]) = h0;
        *reinterpret_cast<__nv_bfloat162*>(&Olg[(qrow0 + r0) * DIM + c]) = l0v;
        *reinterpret_cast<__nv_bfloat162*>(&Ohg[(qrow0 + r0 + 8) * DIM + c]) = h1;
        *reinterpret_cast<__nv_bfloat162*>(&Olg[(qrow0 + r0 + 8) * DIM + c]) = l1v;
    }
}

// ---------------------------------------------------------------------------
// launch
// ---------------------------------------------------------------------------
extern "C" void kernel_launch(void* const* d_in, const int* in_sizes, int n_in,
                              void* d_out, int out_size)
{
    const float* q  = (const float*)d_in[0];
    const float* k  = (const float*)d_in[1];
    const float* v  = (const float*)d_in[2];
    const float* Wq = (const float*)d_in[3];
    const float* bq = (const float*)d_in[4];
    const float* Wk = (const float*)d_in[5];
    const float* bk = (const float*)d_in[6];
    const float* Wv = (const float*)d_in[7];
    const float* bv = (const float*)d_in[8];
    const float* Wo = (const float*)d_in[9];
    const float* bo = (const float*)d_in[10];

    float* out   = (float*)d_out;
    float* attnW = out + (size_t)BT * DIM;

    __nv_bfloat16 *qh, *ql, *kh, *kl, *vh, *vl;
    __nv_bfloat16 *Wqh, *Wql, *Wkh, *Wkl, *Wvh, *Wvl, *Woh, *Wol;
    __nv_bfloat16 *Qh, *Ql, *Kh, *Kl, *Vh, *Vl, *Oh, *Ol;
    float* invL;
    cudaGetSymbolAddress((void**)&qh, g_qh);   cudaGetSymbolAddress((void**)&ql, g_ql);
    cudaGetSymbolAddress((void**)&kh, g_kh);   cudaGetSymbolAddress((void**)&kl, g_kl);
    cudaGetSymbolAddress((void**)&vh, g_vh);   cudaGetSymbolAddress((void**)&vl, g_vl);
    cudaGetSymbolAddress((void**)&Wqh, g_Wqh); cudaGetSymbolAddress((void**)&Wql, g_Wql);
    cudaGetSymbolAddress((void**)&Wkh, g_Wkh); cudaGetSymbolAddress((void**)&Wkl, g_Wkl);
    cudaGetSymbolAddress((void**)&Wvh, g_Wvh); cudaGetSymbolAddress((void**)&Wvl, g_Wvl);
    cudaGetSymbolAddress((void**)&Woh, g_Woh); cudaGetSymbolAddress((void**)&Wol, g_Wol);
    cudaGetSymbolAddress((void**)&Qh, g_Qh);   cudaGetSymbolAddress((void**)&Ql, g_Ql);
    cudaGetSymbolAddress((void**)&Kh, g_Kh);   cudaGetSymbolAddress((void**)&Kl, g_Kl);
    cudaGetSymbolAddress((void**)&Vh, g_Vh);   cudaGetSymbolAddress((void**)&Vl, g_Vl);
    cudaGetSymbolAddress((void**)&Oh, g_Oh);   cudaGetSymbolAddress((void**)&Ol, g_Ol);
    cudaGetSymbolAddress((void**)&invL, g_invL);

    cudaFuncSetAttribute(gemm_qkv_kernel, cudaFuncAttributeMaxDynamicSharedMemorySize,
                         G_SMEM_BYTES);
    cudaFuncSetAttribute(gemm_wo_norm_kernel, cudaFuncAttributeMaxDynamicSharedMemorySize,
                         G_SMEM_BYTES);
    cudaFuncSetAttribute(attn_kernel, cudaFuncAttributeMaxDynamicSharedMemorySize,
                         ATTN_SMEM_BYTES);

    const float scale = 0.08838834764831845f;  // 1/sqrt(128)

    // splits (fp32 -> bf16 hi/lo): 3 fused launches
    const int nBD = BT * DIM / 4, nDD = DIM * DIM / 4, nDK = DIM * KVDIM / 4;
    split3_kernel<<<dim3((nBD + 255) / 256, 3), 256>>>(
        q, qh, ql, k, kh, kl, v, vh, vl, nBD);
    split3_kernel<<<dim3((nDD + 255) / 256, 2), 256>>>(
        Wq, Wqh, Wql, Wo, Woh, Wol, nullptr, nullptr, nullptr, nDD);
    split3_kernel<<<dim3((nDK + 255) / 256, 2), 256>>>(
        Wk, Wkh, Wkl, Wv, Wvh, Wvl, nullptr, nullptr, nullptr, nDK);

    // fused Q/K/V projections (one launch, one wave tail)
    gemm_qkv_kernel<<<768, 256, G_SMEM_BYTES>>>(
        qh, ql, Wqh, Wql, bq, Qh, Ql,
        kh, kl, Wkh, Wkl, bk, Kh, Kl,
        vh, vl, Wvh, Wvl, bv, Vh, Vl,
        scale);

    // attention (raw exp -> AW, O pre-split & scaled)
    attn_kernel<<<dim3(T / 64, 32), 256, ATTN_SMEM_BYTES>>>(
        Qh, Ql, Kh, Kl, Vh, Vl, attnW, invL, Oh, Ol);

    // fused Wo projection + AW normalize (memory-bound CTAs soak idle HBM)
    gemm_wo_norm_kernel<<<512 + NORM_CTAS, 256, G_SMEM_BYTES>>>(
        Oh, Ol, Woh, Wol, bo, out, attnW, invL);
}